// round 9
// baseline (speedup 1.0000x reference)
#include <cuda_runtime.h>
#include <cuda_bf16.h>
#include <cstdint>
#include <stdint.h>
#include <math.h>

// Problem constants (fixed by the reference)
#define BB 4
#define TT 2048
#define DD 1024
#define HH 16
#define DK 64
#define MROWS (BB * TT)          // 8192
#define KSPLIT (3 * DD)          // 3072 = split-K' for compensated bf16 GEMM

// Scratch (allocation-free rule: __device__ globals)
__device__ float         g_v[(size_t)BB * HH * TT * DK];    // V fp32 [bh][t][d]
__device__ __nv_bfloat16 g_xp[(size_t)MROWS * KSPLIT];      // x  split  (hi|lo|hi)
__device__ __nv_bfloat16 g_wqkvp[(size_t)(3 * DD) * KSPLIT];// Wqkv split (hi|hi|lo)
__device__ __nv_bfloat16 g_yp[(size_t)MROWS * KSPLIT];      // y  split  (hi|lo|hi)
__device__ __nv_bfloat16 g_wprojp[(size_t)DD * KSPLIT];     // Wproj split (hi|hi|lo)
// attention operand tensors, per (b,h):
__device__ __nv_bfloat16 g_qh[(size_t)BB * HH * TT * DK];   // Q hi  [bh][t][d]
__device__ __nv_bfloat16 g_ql[(size_t)BB * HH * TT * DK];   // Q lo
__device__ __nv_bfloat16 g_kh[(size_t)BB * HH * TT * DK];   // K hi
__device__ __nv_bfloat16 g_kl[(size_t)BB * HH * TT * DK];   // K lo
__device__ __nv_bfloat16 g_vht[(size_t)BB * HH * DK * TT];  // V^T hi [bh][d][t]
__device__ __nv_bfloat16 g_vlt[(size_t)BB * HH * DK * TT];  // V^T lo

// ---------------------------------------------------------------------------
// helpers (all baseline PTX — compiles on compute_103)
// ---------------------------------------------------------------------------
__device__ __forceinline__ uint32_t smem_u32(const void* p) {
    uint32_t a;
    asm("{ .reg .u64 t; cvta.to.shared.u64 t, %1; cvt.u32.u64 %0, t; }"
        : "=r"(a) : "l"(p));
    return a;
}
__device__ __forceinline__ void cp16(uint32_t saddr, const void* gaddr) {
    asm volatile("cp.async.cg.shared.global [%0], [%1], 16;"
                 :: "r"(saddr), "l"(gaddr) : "memory");
}
__device__ __forceinline__ void cp_commit() {
    asm volatile("cp.async.commit_group;" ::: "memory");
}
template <int N>
__device__ __forceinline__ void cp_wait() {
    asm volatile("cp.async.wait_group %0;" :: "n"(N) : "memory");
}
__device__ __forceinline__ void ldsm_x4(uint32_t* r, uint32_t addr) {
    asm volatile("ldmatrix.sync.aligned.m8n8.x4.shared.b16 {%0,%1,%2,%3}, [%4];"
                 : "=r"(r[0]), "=r"(r[1]), "=r"(r[2]), "=r"(r[3]) : "r"(addr));
}
__device__ __forceinline__ void mma_bf16(float* c, const uint32_t* a,
                                         const uint32_t* b) {
    asm volatile(
        "mma.sync.aligned.m16n8k16.row.col.f32.bf16.bf16.f32 "
        "{%0,%1,%2,%3}, {%4,%5,%6,%7}, {%8,%9}, {%0,%1,%2,%3};"
        : "+f"(c[0]), "+f"(c[1]), "+f"(c[2]), "+f"(c[3])
        : "r"(a[0]), "r"(a[1]), "r"(a[2]), "r"(a[3]), "r"(b[0]), "r"(b[1]));
}
__device__ __forceinline__ uint32_t sw128(uint32_t bo) {
    return bo ^ ((bo >> 3) & 0x70);
}
__device__ __forceinline__ uint32_t pack2(float a, float b) {
    __nv_bfloat162 t = __floats2bfloat162_rn(a, b);
    return *(uint32_t*)&t;
}

#define GEMM_SMEM 98304   // 3 x (16KB A + 16KB B)

// ---------------------------------------------------------------------------
// Tensor-core GEMM via mma.sync: C = A @ B^T + bias.
// mode 0: plain fp32 C[M,N].
// mode 1 (qkv): columns <1024 -> g_qh/g_ql split, <2048 -> g_kh/g_kl,
//               else V fp32 -> g_v [bh][t][d].  (C unused)
// 128x128 CTA tile, 256 threads, warp tile 64x32, K-chunks of 64,
// 3-stage cp.async pipeline.
// ---------------------------------------------------------------------------
__global__ __launch_bounds__(256)
void gemm_bf16_mma(const __nv_bfloat16* __restrict__ A,
                   const __nv_bfloat16* __restrict__ B,
                   const float* __restrict__ bias, float* __restrict__ C,
                   int M, int N, int K, int mode)
{
    extern __shared__ char smc[];
    const uint32_t sb = smem_u32(smc);
    const int tid  = threadIdx.x;
    const int wid  = tid >> 5;
    const int lane = tid & 31;
    const int nb   = blockIdx.x * 128;
    const int mb   = blockIdx.y * 128;
    const int mw   = (wid >> 2) * 64;
    const int nw   = (wid & 3) * 32;

    const uint32_t sA = sb;             // 3 x 16KB
    const uint32_t sB = sb + 49152;     // 3 x 16KB

    float acc[4][4][4];
#pragma unroll
    for (int mt = 0; mt < 4; mt++)
#pragma unroll
        for (int nt = 0; nt < 4; nt++)
#pragma unroll
            for (int q = 0; q < 4; q++) acc[mt][nt][q] = 0.f;

    const int lrow = tid >> 3;
    const int lci  = tid & 7;
    const uint32_t lsw = sw128((uint32_t)(lrow * 128 + lci * 16));

    const int nch = K >> 6;

    // prologue: issue chunks 0 and 1
#pragma unroll
    for (int c = 0; c < 2; c++) {
        const __nv_bfloat16* Ap = A + (size_t)mb * K + (c << 6);
        const __nv_bfloat16* Bp = B + (size_t)nb * K + (c << 6);
        const uint32_t sbuf = c * 16384;
#pragma unroll
        for (int i = 0; i < 4; i++) {
            const uint32_t so = sbuf + lsw + i * 4096;
            cp16(sA + so, Ap + (size_t)(lrow + i * 32) * K + lci * 8);
            cp16(sB + so, Bp + (size_t)(lrow + i * 32) * K + lci * 8);
        }
        cp_commit();
    }

    int s = 0;      // buffer of chunk c
    int sn = 2;     // buffer of chunk c+2
    for (int c = 0; c < nch; c++) {
        if (c + 2 < nch) {
            const int k0 = (c + 2) << 6;
            const __nv_bfloat16* Ap = A + (size_t)mb * K + k0;
            const __nv_bfloat16* Bp = B + (size_t)nb * K + k0;
            const uint32_t sbuf = sn * 16384;
#pragma unroll
            for (int i = 0; i < 4; i++) {
                const uint32_t so = sbuf + lsw + i * 4096;
                cp16(sA + so, Ap + (size_t)(lrow + i * 32) * K + lci * 8);
                cp16(sB + so, Bp + (size_t)(lrow + i * 32) * K + lci * 8);
            }
            cp_commit();
            cp_wait<2>();
        } else if (c + 1 < nch) {
            cp_wait<1>();
        } else {
            cp_wait<0>();
        }
        __syncthreads();

        const uint32_t baseA = sA + s * 16384;
        const uint32_t baseB = sB + s * 16384;
#pragma unroll
        for (int ks = 0; ks < 4; ks++) {
            uint32_t af[4][4];
#pragma unroll
            for (int mt = 0; mt < 4; mt++) {
                const int row = mw + mt * 16 + (lane & 15);
                const uint32_t bo =
                    (uint32_t)(row * 128 + ks * 32 + ((lane >> 4) & 1) * 16);
                ldsm_x4(af[mt], baseA + sw128(bo));
            }
            uint32_t bf[4][2];
#pragma unroll
            for (int nt2 = 0; nt2 < 2; nt2++) {
                const int row = nw + nt2 * 16 + ((lane >> 4) << 3) + (lane & 7);
                const uint32_t bo =
                    (uint32_t)(row * 128 + ks * 32 + ((lane >> 3) & 1) * 16);
                uint32_t t[4];
                ldsm_x4(t, baseB + sw128(bo));
                bf[nt2 * 2 + 0][0] = t[0]; bf[nt2 * 2 + 0][1] = t[1];
                bf[nt2 * 2 + 1][0] = t[2]; bf[nt2 * 2 + 1][1] = t[3];
            }
#pragma unroll
            for (int mt = 0; mt < 4; mt++)
#pragma unroll
                for (int nt = 0; nt < 4; nt++)
                    mma_bf16(acc[mt][nt], af[mt], bf[nt]);
        }
        __syncthreads();
        s  = (s  == 2) ? 0 : s + 1;
        sn = (sn == 2) ? 0 : sn + 1;
    }

    const int r0 = mb + mw + (lane >> 2);
    const int c0 = nb + nw + (lane & 3) * 2;

    if (mode == 0) {
#pragma unroll
        for (int mt = 0; mt < 4; mt++) {
#pragma unroll
            for (int nt = 0; nt < 4; nt++) {
                const int col = c0 + nt * 8;
                const float bx = bias[col], by = bias[col + 1];
                float2 v0 = make_float2(acc[mt][nt][0] + bx, acc[mt][nt][1] + by);
                float2 v1 = make_float2(acc[mt][nt][2] + bx, acc[mt][nt][3] + by);
                *(float2*)(C + (size_t)(r0 + mt * 16) * N + col)     = v0;
                *(float2*)(C + (size_t)(r0 + mt * 16 + 8) * N + col) = v1;
            }
        }
    } else {
        // qkv epilogue: scatter into attention operand layouts
#pragma unroll
        for (int nt = 0; nt < 4; nt++) {
            const int col = c0 + nt * 8;
            const int src = col >> 10;          // 0=q, 1=k, 2=v (warp-uniform)
            const int cc  = col & 1023;
            const int h   = cc >> 6;
            const int d   = cc & 63;
            const float bx = bias[col], by = bias[col + 1];
#pragma unroll
            for (int mt = 0; mt < 4; mt++) {
#pragma unroll
                for (int half = 0; half < 2; half++) {
                    const int r = r0 + mt * 16 + half * 8;
                    const float vx = acc[mt][nt][half * 2 + 0] + bx;
                    const float vy = acc[mt][nt][half * 2 + 1] + by;
                    const int bsel = r >> 11;
                    const int t    = r & 2047;
                    const size_t o =
                        ((size_t)(bsel * HH + h) * TT + t) * DK + d;
                    if (src == 2) {
                        *(float2*)(g_v + o) = make_float2(vx, vy);
                    } else {
                        const float hx = __bfloat162float(__float2bfloat16(vx));
                        const float hy = __bfloat162float(__float2bfloat16(vy));
                        if (src == 0) {
                            *(uint32_t*)(g_qh + o) = pack2(hx, hy);
                            *(uint32_t*)(g_ql + o) = pack2(vx - hx, vy - hy);
                        } else {
                            *(uint32_t*)(g_kh + o) = pack2(hx, hy);
                            *(uint32_t*)(g_kl + o) = pack2(vx - hx, vy - hy);
                        }
                    }
                }
            }
        }
    }
}

// ---------------------------------------------------------------------------
// Split fp32 -> compensated bf16 triple along K (x and the two weights).
// type 0 (A operand): (hi | lo | hi)   type 1 (B operand): (hi | hi | lo)
// ---------------------------------------------------------------------------
__global__ __launch_bounds__(256)
void split_hilo(const float* __restrict__ in, __nv_bfloat16* __restrict__ out,
                int total, int type)
{
    int idx = blockIdx.x * 256 + threadIdx.x;
    if (idx >= total) return;
    const int r = idx >> 10;
    const int k = idx & 1023;
    const float x = in[idx];
    const __nv_bfloat16 h = __float2bfloat16(x);
    const __nv_bfloat16 l = __float2bfloat16(x - __bfloat162float(h));
    const size_t o = (size_t)r * KSPLIT + k;
    if (type == 0) { out[o] = h; out[o + 1024] = l; out[o + 2048] = h; }
    else           { out[o] = h; out[o + 1024] = h; out[o + 2048] = l; }
}

// ---------------------------------------------------------------------------
// V transpose + split: g_v [bh][t][64] fp32 -> V^T hi/lo [bh][d][t].
// Block = (ttile 128, h, b).
// ---------------------------------------------------------------------------
__global__ __launch_bounds__(256)
void v_split(const float* __restrict__ v,
             __nv_bfloat16* __restrict__ vht, __nv_bfloat16* __restrict__ vlt)
{
    __shared__ float tile[128][65];
    const int tid = threadIdx.x;
    const int t0  = blockIdx.x * 128;
    const int h   = blockIdx.y;
    const int b   = blockIdx.z;
    const int bh  = b * HH + h;

#pragma unroll
    for (int i = 0; i < 8; i++) {
        const int s   = tid + i * 256;     // 2048 float4 slots
        const int row = s >> 4;
        const int c4  = (s & 15) * 4;
        float4 vv = *(const float4*)(v + ((size_t)bh * TT + t0 + row) * DK + c4);
        tile[row][c4 + 0] = vv.x; tile[row][c4 + 1] = vv.y;
        tile[row][c4 + 2] = vv.z; tile[row][c4 + 3] = vv.w;
    }
    __syncthreads();

    const int wid  = tid >> 5;
    const int lane = tid & 31;
#pragma unroll
    for (int r = 0; r < 8; r++) {
        const int d = wid * 8 + r;
        uint32_t* oh = (uint32_t*)(vht + ((size_t)bh * DK + d) * TT + t0);
        uint32_t* ol = (uint32_t*)(vlt + ((size_t)bh * DK + d) * TT + t0);
#pragma unroll
        for (int it = 0; it < 2; it++) {
            const int tt = (lane + it * 32) * 2;
            const float v0 = tile[tt][d], v1 = tile[tt + 1][d];
            const float h0 = __bfloat162float(__float2bfloat16(v0));
            const float h1 = __bfloat162float(__float2bfloat16(v1));
            oh[lane + it * 32] = pack2(h0, h1);
            ol[lane + it * 32] = pack2(v0 - h0, v1 - h1);
        }
    }
}

// ---------------------------------------------------------------------------
// Flash attention on tensor cores (compensated bf16).
// Block: 128 queries x one (b,h). 256 threads = 8 warps; warp w owns query
// rows [w*16, w*16+16). Key tiles of 64. Epilogue writes the proj-GEMM
// A-operand layout (hi | lo | hi) directly.
// ---------------------------------------------------------------------------
#define SQHI 0
#define SQLO 16384
#define SKHI 32768
#define SKLO 40960
#define SVHI 49152
#define SVLO 57344
#define SPHI 65536
#define SPLO 81920
#define SPAD 98304
#define ATT2_SMEM (98304 + 256)

__global__ __launch_bounds__(256)
void attn_mma(const __nv_bfloat16* __restrict__ qh,
              const __nv_bfloat16* __restrict__ ql,
              const __nv_bfloat16* __restrict__ kh,
              const __nv_bfloat16* __restrict__ kl,
              const __nv_bfloat16* __restrict__ vht,
              const __nv_bfloat16* __restrict__ vlt,
              const int* __restrict__ mask,
              __nv_bfloat16* __restrict__ yp)
{
    extern __shared__ char smc[];
    const uint32_t sb = smem_u32(smc);
    int* padm = (int*)(smc + SPAD);

    const int tid  = threadIdx.x;
    const int wid  = tid >> 5;
    const int lane = tid & 31;
    const int bx   = gridDim.x - 1 - blockIdx.x;   // heavy blocks first
    const int b    = blockIdx.z;
    const int hh   = blockIdx.y;
    const int bh   = b * HH + hh;
    const int qb   = bx * 128;

    // ---- load Q (hi & lo) ----
    {
        const __nv_bfloat16* qhp = qh + ((size_t)bh * TT + qb) * DK;
        const __nv_bfloat16* qlp = ql + ((size_t)bh * TT + qb) * DK;
#pragma unroll
        for (int i = 0; i < 4; i++) {
            const int s   = tid + i * 256;
            const int row = s >> 3;
            const int ci  = s & 7;
            const uint32_t sw = sw128((uint32_t)(row * 128 + ci * 16));
            cp16(sb + SQHI + sw, qhp + (size_t)row * DK + ci * 8);
            cp16(sb + SQLO + sw, qlp + (size_t)row * DK + ci * 8);
        }
        cp_commit();
    }

    float acc[8][4];
#pragma unroll
    for (int nt = 0; nt < 8; nt++)
#pragma unroll
        for (int q = 0; q < 4; q++) acc[nt][q] = 0.f;
    float m0 = -INFINITY, m1 = -INFINITY, l0 = 0.f, l1 = 0.f;

    const int r0g = qb + wid * 16 + (lane >> 2);
    const int r1g = r0g + 8;

    const int ntiles = 2 * bx + 2;
    for (int kt = 0; kt < ntiles; kt++) {
        const int j0 = kt * 64;
        __syncthreads();

        {
            const __nv_bfloat16* khp = kh + ((size_t)bh * TT + j0) * DK;
            const __nv_bfloat16* klp = kl + ((size_t)bh * TT + j0) * DK;
            const __nv_bfloat16* vhp = vht + (size_t)bh * DK * TT + j0;
            const __nv_bfloat16* vlp = vlt + (size_t)bh * DK * TT + j0;
#pragma unroll
            for (int i = 0; i < 2; i++) {
                const int s   = tid + i * 256;
                const int row = s >> 3;
                const int ci  = s & 7;
                const uint32_t sw = sw128((uint32_t)(row * 128 + ci * 16));
                cp16(sb + SKHI + sw, khp + (size_t)row * DK + ci * 8);
                cp16(sb + SKLO + sw, klp + (size_t)row * DK + ci * 8);
                cp16(sb + SVHI + sw, vhp + (size_t)row * TT + ci * 8);
                cp16(sb + SVLO + sw, vlp + (size_t)row * TT + ci * 8);
            }
            if (tid < 64) padm[tid] = mask[b * TT + j0 + tid];
            cp_commit();
            cp_wait<0>();
            __syncthreads();
        }

        // ---- S = Qhi*Khi + Qlo*Khi + Qhi*Klo ----
        float s4[8][4];
#pragma unroll
        for (int nt = 0; nt < 8; nt++)
#pragma unroll
            for (int q = 0; q < 4; q++) s4[nt][q] = 0.f;

#pragma unroll
        for (int seg = 0; seg < 3; seg++) {
            const uint32_t Ab = sb + (seg == 1 ? SQLO : SQHI);
            const uint32_t Bb = sb + (seg == 2 ? SKLO : SKHI);
#pragma unroll
            for (int ks = 0; ks < 4; ks++) {
                uint32_t af[4];
                {
                    const int row = wid * 16 + (lane & 15);
                    const uint32_t bo =
                        (uint32_t)(row * 128 + ks * 32 + ((lane >> 4) & 1) * 16);
                    ldsm_x4(af, Ab + sw128(bo));
                }
#pragma unroll
                for (int nt2 = 0; nt2 < 4; nt2++) {
                    const int row = nt2 * 16 + ((lane >> 4) << 3) + (lane & 7);
                    const uint32_t bo =
                        (uint32_t)(row * 128 + ks * 32 + ((lane >> 3) & 1) * 16);
                    uint32_t t[4];
                    ldsm_x4(t, Bb + sw128(bo));
                    mma_bf16(s4[nt2 * 2 + 0], af, t);
                    mma_bf16(s4[nt2 * 2 + 1], af, t + 2);
                }
            }
        }

        // ---- mask + scale ----
#pragma unroll
        for (int nt = 0; nt < 8; nt++) {
            const int c0 = nt * 8 + (lane & 3) * 2;
            const bool p0 = padm[c0] != 0, p1 = padm[c0 + 1] != 0;
            const int jg0 = j0 + c0, jg1 = jg0 + 1;
            s4[nt][0] = (p0 && jg0 <= r0g) ? s4[nt][0] * 0.125f : -INFINITY;
            s4[nt][1] = (p1 && jg1 <= r0g) ? s4[nt][1] * 0.125f : -INFINITY;
            s4[nt][2] = (p0 && jg0 <= r1g) ? s4[nt][2] * 0.125f : -INFINITY;
            s4[nt][3] = (p1 && jg1 <= r1g) ? s4[nt][3] * 0.125f : -INFINITY;
        }

        // ---- online softmax ----
        float mx0 = -INFINITY, mx1 = -INFINITY;
#pragma unroll
        for (int nt = 0; nt < 8; nt++) {
            mx0 = fmaxf(mx0, fmaxf(s4[nt][0], s4[nt][1]));
            mx1 = fmaxf(mx1, fmaxf(s4[nt][2], s4[nt][3]));
        }
        mx0 = fmaxf(mx0, __shfl_xor_sync(0xffffffffu, mx0, 1));
        mx0 = fmaxf(mx0, __shfl_xor_sync(0xffffffffu, mx0, 2));
        mx1 = fmaxf(mx1, __shfl_xor_sync(0xffffffffu, mx1, 1));
        mx1 = fmaxf(mx1, __shfl_xor_sync(0xffffffffu, mx1, 2));

        float a0 = 1.f, a1 = 1.f;
        if (mx0 > -INFINITY) {
            const float mn = fmaxf(m0, mx0);
            a0 = __expf(m0 - mn);
            m0 = mn;
        }
        if (mx1 > -INFINITY) {
            const float mn = fmaxf(m1, mx1);
            a1 = __expf(m1 - mn);
            m1 = mn;
        }
        const float mm0 = (m0 == -INFINITY) ? 0.f : m0;
        const float mm1 = (m1 == -INFINITY) ? 0.f : m1;

        // ---- p = exp(s-m) -> hi/lo smem P tiles ----
        const int pr0 = wid * 16 + (lane >> 2);
        const uint32_t pcolb = (uint32_t)((lane & 3) * 4);
        float sum0 = 0.f, sum1 = 0.f;
#pragma unroll
        for (int nt = 0; nt < 8; nt++) {
            const float p00 = __expf(s4[nt][0] - mm0);
            const float p01 = __expf(s4[nt][1] - mm0);
            const float p10 = __expf(s4[nt][2] - mm1);
            const float p11 = __expf(s4[nt][3] - mm1);
            sum0 += p00 + p01;
            sum1 += p10 + p11;
            const float h00 = __bfloat162float(__float2bfloat16(p00));
            const float h01 = __bfloat162float(__float2bfloat16(p01));
            const float h10 = __bfloat162float(__float2bfloat16(p10));
            const float h11 = __bfloat162float(__float2bfloat16(p11));
            const uint32_t bo0 = (uint32_t)(pr0 * 128 + nt * 16) + pcolb;
            const uint32_t bo1 = bo0 + 8 * 128;
            *(uint32_t*)(smc + SPHI + sw128(bo0)) = pack2(h00, h01);
            *(uint32_t*)(smc + SPHI + sw128(bo1)) = pack2(h10, h11);
            *(uint32_t*)(smc + SPLO + sw128(bo0)) = pack2(p00 - h00, p01 - h01);
            *(uint32_t*)(smc + SPLO + sw128(bo1)) = pack2(p10 - h10, p11 - h11);
        }
        sum0 += __shfl_xor_sync(0xffffffffu, sum0, 1);
        sum0 += __shfl_xor_sync(0xffffffffu, sum0, 2);
        sum1 += __shfl_xor_sync(0xffffffffu, sum1, 1);
        sum1 += __shfl_xor_sync(0xffffffffu, sum1, 2);
        l0 = l0 * a0 + sum0;
        l1 = l1 * a1 + sum1;

#pragma unroll
        for (int nt = 0; nt < 8; nt++) {
            acc[nt][0] *= a0; acc[nt][1] *= a0;
            acc[nt][2] *= a1; acc[nt][3] *= a1;
        }
        __syncwarp();

        // ---- O += Phi*Vhi + Plo*Vhi + Phi*Vlo ----
#pragma unroll
        for (int seg = 0; seg < 3; seg++) {
            const uint32_t Ab = sb + (seg == 1 ? SPLO : SPHI);
            const uint32_t Bb = sb + (seg == 2 ? SVLO : SVHI);
#pragma unroll
            for (int ks = 0; ks < 4; ks++) {
                uint32_t af[4];
                {
                    const int row = wid * 16 + (lane & 15);
                    const uint32_t bo =
                        (uint32_t)(row * 128 + ks * 32 + ((lane >> 4) & 1) * 16);
                    ldsm_x4(af, Ab + sw128(bo));
                }
#pragma unroll
                for (int nt2 = 0; nt2 < 4; nt2++) {
                    const int row = nt2 * 16 + ((lane >> 4) << 3) + (lane & 7);
                    const uint32_t bo =
                        (uint32_t)(row * 128 + ks * 32 + ((lane >> 3) & 1) * 16);
                    uint32_t t[4];
                    ldsm_x4(t, Bb + sw128(bo));
                    mma_bf16(acc[nt2 * 2 + 0], af, t);
                    mma_bf16(acc[nt2 * 2 + 1], af, t + 2);
                }
            }
        }
    }

    // ---- epilogue: write proj A-operand layout (hi | lo | hi) directly ----
    const float inv0 = (l0 > 0.f) ? (1.f / l0) : 0.f;
    const float inv1 = (l1 > 0.f) ? (1.f / l1) : 0.f;
#pragma unroll
    for (int nt = 0; nt < 8; nt++) {
        const int col = hh * DK + nt * 8 + (lane & 3) * 2;
        {
            const float vx = acc[nt][0] * inv0, vy = acc[nt][1] * inv0;
            const float hx = __bfloat162float(__float2bfloat16(vx));
            const float hy = __bfloat162float(__float2bfloat16(vy));
            const size_t o = ((size_t)b * TT + r0g) * KSPLIT + col;
            const uint32_t hp = pack2(hx, hy);
            *(uint32_t*)(yp + o)        = hp;
            *(uint32_t*)(yp + o + 1024) = pack2(vx - hx, vy - hy);
            *(uint32_t*)(yp + o + 2048) = hp;
        }
        {
            const float vx = acc[nt][2] * inv1, vy = acc[nt][3] * inv1;
            const float hx = __bfloat162float(__float2bfloat16(vx));
            const float hy = __bfloat162float(__float2bfloat16(vy));
            const size_t o = ((size_t)b * TT + r1g) * KSPLIT + col;
            const uint32_t hp = pack2(hx, hy);
            *(uint32_t*)(yp + o)        = hp;
            *(uint32_t*)(yp + o + 1024) = pack2(vx - hx, vy - hy);
            *(uint32_t*)(yp + o + 2048) = hp;
        }
    }
}

// ---------------------------------------------------------------------------
extern "C" void kernel_launch(void* const* d_in, const int* in_sizes, int n_in,
                              void* d_out, int out_size)
{
    const float* x     = (const float*)d_in[0];
    const float* Wqkv  = (const float*)d_in[1];
    const float* bqkv  = (const float*)d_in[2];
    const float* Wproj = (const float*)d_in[3];
    const float* bproj = (const float*)d_in[4];
    const int*   mask  = (const int*)d_in[5];
    float* out = (float*)d_out;

    float *vp;
    __nv_bfloat16 *xpp, *wqp, *ypp, *wpp;
    __nv_bfloat16 *qhp, *qlp, *khp, *klp, *vhp, *vlp;
    cudaGetSymbolAddress((void**)&vp,   g_v);
    cudaGetSymbolAddress((void**)&xpp,  g_xp);
    cudaGetSymbolAddress((void**)&wqp,  g_wqkvp);
    cudaGetSymbolAddress((void**)&ypp,  g_yp);
    cudaGetSymbolAddress((void**)&wpp,  g_wprojp);
    cudaGetSymbolAddress((void**)&qhp,  g_qh);
    cudaGetSymbolAddress((void**)&qlp,  g_ql);
    cudaGetSymbolAddress((void**)&khp,  g_kh);
    cudaGetSymbolAddress((void**)&klp,  g_kl);
    cudaGetSymbolAddress((void**)&vhp,  g_vht);
    cudaGetSymbolAddress((void**)&vlp,  g_vlt);

    cudaFuncSetAttribute(gemm_bf16_mma,
                         cudaFuncAttributeMaxDynamicSharedMemorySize, GEMM_SMEM);
    cudaFuncSetAttribute(attn_mma,
                         cudaFuncAttributeMaxDynamicSharedMemorySize, ATT2_SMEM);

    // input splits
    split_hilo<<<(MROWS * DD) / 256, 256>>>(x, xpp, MROWS * DD, 0);
    split_hilo<<<(3 * DD * DD) / 256, 256>>>(Wqkv, wqp, 3 * DD * DD, 1);
    split_hilo<<<(DD * DD) / 256, 256>>>(Wproj, wpp, DD * DD, 1);

    // qkv GEMM with fused q/k split + compact V (mode 1)
    gemm_bf16_mma<<<dim3(3 * DD / 128, MROWS / 128), 256, GEMM_SMEM>>>(
        xpp, wqp, bqkv, nullptr, MROWS, 3 * DD, KSPLIT, 1);

    // V transpose + split
    v_split<<<dim3(TT / 128, HH, BB), 256>>>(vp, vhp, vlp);

    // attention -> g_yp (proj A-operand layout, fused)
    attn_mma<<<dim3(TT / 128, HH, BB), 256, ATT2_SMEM>>>(
        qhp, qlp, khp, klp, vhp, vlp, mask, ypp);

    // out = y @ Wproj^T + bproj (mode 0)
    gemm_bf16_mma<<<dim3(DD / 128, MROWS / 128), 256, GEMM_SMEM>>>(
        ypp, wpp, bproj, out, MROWS, DD, KSPLIT, 0);
}

// round 10
// speedup vs baseline: 1.1045x; 1.1045x over previous
#include <cuda_runtime.h>
#include <cuda_bf16.h>
#include <cstdint>
#include <stdint.h>
#include <math.h>

// Problem constants (fixed by the reference)
#define BB 4
#define TT 2048
#define DD 1024
#define HH 16
#define DK 64
#define MROWS (BB * TT)          // 8192
#define KSPLIT (3 * DD)          // 3072 = split-K' for compensated bf16 GEMM

// Scratch (allocation-free rule: __device__ globals)
__device__ float         g_v[(size_t)BB * HH * TT * DK];    // V fp32 [bh][t][d]
__device__ __nv_bfloat16 g_xp[(size_t)MROWS * KSPLIT];      // x  split  (hi|lo|hi)
__device__ __nv_bfloat16 g_wqkvp[(size_t)(3 * DD) * KSPLIT];// Wqkv split (hi|hi|lo)
__device__ __nv_bfloat16 g_yp[(size_t)MROWS * KSPLIT];      // y  split  (hi|lo|hi)
__device__ __nv_bfloat16 g_wprojp[(size_t)DD * KSPLIT];     // Wproj split (hi|hi|lo)
// attention operand tensors, per (b,h):
__device__ __nv_bfloat16 g_qh[(size_t)BB * HH * TT * DK];   // Q hi  [bh][t][d]
__device__ __nv_bfloat16 g_ql[(size_t)BB * HH * TT * DK];   // Q lo
__device__ __nv_bfloat16 g_kh[(size_t)BB * HH * TT * DK];   // K hi
__device__ __nv_bfloat16 g_kl[(size_t)BB * HH * TT * DK];   // K lo
__device__ __nv_bfloat16 g_vht[(size_t)BB * HH * DK * TT];  // V^T hi [bh][d][t]
__device__ __nv_bfloat16 g_vlt[(size_t)BB * HH * DK * TT];  // V^T lo

// ---------------------------------------------------------------------------
// helpers (all baseline PTX — compiles on compute_103)
// ---------------------------------------------------------------------------
__device__ __forceinline__ uint32_t smem_u32(const void* p) {
    uint32_t a;
    asm("{ .reg .u64 t; cvta.to.shared.u64 t, %1; cvt.u32.u64 %0, t; }"
        : "=r"(a) : "l"(p));
    return a;
}
__device__ __forceinline__ void cp16(uint32_t saddr, const void* gaddr) {
    asm volatile("cp.async.cg.shared.global [%0], [%1], 16;"
                 :: "r"(saddr), "l"(gaddr) : "memory");
}
__device__ __forceinline__ void cp_commit() {
    asm volatile("cp.async.commit_group;" ::: "memory");
}
template <int N>
__device__ __forceinline__ void cp_wait() {
    asm volatile("cp.async.wait_group %0;" :: "n"(N) : "memory");
}
__device__ __forceinline__ void ldsm_x4(uint32_t* r, uint32_t addr) {
    asm volatile("ldmatrix.sync.aligned.m8n8.x4.shared.b16 {%0,%1,%2,%3}, [%4];"
                 : "=r"(r[0]), "=r"(r[1]), "=r"(r[2]), "=r"(r[3]) : "r"(addr));
}
__device__ __forceinline__ void mma_bf16(float* c, const uint32_t* a,
                                         const uint32_t* b) {
    asm volatile(
        "mma.sync.aligned.m16n8k16.row.col.f32.bf16.bf16.f32 "
        "{%0,%1,%2,%3}, {%4,%5,%6,%7}, {%8,%9}, {%0,%1,%2,%3};"
        : "+f"(c[0]), "+f"(c[1]), "+f"(c[2]), "+f"(c[3])
        : "r"(a[0]), "r"(a[1]), "r"(a[2]), "r"(a[3]), "r"(b[0]), "r"(b[1]));
}
__device__ __forceinline__ uint32_t sw128(uint32_t bo) {
    return bo ^ ((bo >> 3) & 0x70);
}
__device__ __forceinline__ uint32_t pack2(float a, float b) {
    __nv_bfloat162 t = __floats2bfloat162_rn(a, b);
    return *(uint32_t*)&t;
}

#define GEMM_SMEM 65536   // 2 x (16KB A + 16KB B)

// ---------------------------------------------------------------------------
// Tensor-core GEMM via mma.sync: C = A @ B^T + bias.
// MODE 0: plain fp32 C[M,N].
// MODE 1 (qkv): columns <1024 -> g_qh/g_ql split, <2048 -> g_kh/g_kl,
//               else V fp32 -> g_v [bh][t][d].  (C unused)
// 128x128 CTA tile, 256 threads, warp tile 64x32, K-chunks of 64,
// 2-stage cp.async double buffer. min 2 CTAs/SM (forces <=128 regs).
// ---------------------------------------------------------------------------
template <int MODE>
__global__ __launch_bounds__(256, 2)
void gemm_bf16_mma(const __nv_bfloat16* __restrict__ A,
                   const __nv_bfloat16* __restrict__ B,
                   const float* __restrict__ bias, float* __restrict__ C,
                   int M, int N, int K)
{
    extern __shared__ char smc[];
    const uint32_t sb = smem_u32(smc);
    const int tid  = threadIdx.x;
    const int wid  = tid >> 5;
    const int lane = tid & 31;
    const int nb   = blockIdx.x * 128;
    const int mb   = blockIdx.y * 128;
    const int mw   = (wid >> 2) * 64;
    const int nw   = (wid & 3) * 32;

    const uint32_t sA = sb;
    const uint32_t sB = sb + 32768;

    float acc[4][4][4];
#pragma unroll
    for (int mt = 0; mt < 4; mt++)
#pragma unroll
        for (int nt = 0; nt < 4; nt++)
#pragma unroll
            for (int q = 0; q < 4; q++) acc[mt][nt][q] = 0.f;

    const int lrow = tid >> 3;
    const int lci  = tid & 7;
    const uint32_t lsw = sw128((uint32_t)(lrow * 128 + lci * 16));

    const int nch = K >> 6;
    {
        const __nv_bfloat16* Ap = A + (size_t)mb * K;
        const __nv_bfloat16* Bp = B + (size_t)nb * K;
#pragma unroll
        for (int i = 0; i < 4; i++) {
            const uint32_t so = lsw + i * 4096;
            cp16(sA + so, Ap + (size_t)(lrow + i * 32) * K + lci * 8);
            cp16(sB + so, Bp + (size_t)(lrow + i * 32) * K + lci * 8);
        }
        cp_commit();
    }

    for (int c = 0; c < nch; c++) {
        const int s = c & 1;
        if (c + 1 < nch) {
            const int k0 = (c + 1) << 6;
            const __nv_bfloat16* Ap = A + (size_t)mb * K + k0;
            const __nv_bfloat16* Bp = B + (size_t)nb * K + k0;
            const uint32_t sbuf = (s ^ 1) * 16384;
#pragma unroll
            for (int i = 0; i < 4; i++) {
                const uint32_t so = sbuf + lsw + i * 4096;
                cp16(sA + so, Ap + (size_t)(lrow + i * 32) * K + lci * 8);
                cp16(sB + so, Bp + (size_t)(lrow + i * 32) * K + lci * 8);
            }
            cp_commit();
            cp_wait<1>();
        } else {
            cp_wait<0>();
        }
        __syncthreads();

        const uint32_t baseA = sA + s * 16384;
        const uint32_t baseB = sB + s * 16384;
#pragma unroll
        for (int ks = 0; ks < 4; ks++) {
            uint32_t af[4][4];
#pragma unroll
            for (int mt = 0; mt < 4; mt++) {
                const int row = mw + mt * 16 + (lane & 15);
                const uint32_t bo =
                    (uint32_t)(row * 128 + ks * 32 + ((lane >> 4) & 1) * 16);
                ldsm_x4(af[mt], baseA + sw128(bo));
            }
            uint32_t bf[4][2];
#pragma unroll
            for (int nt2 = 0; nt2 < 2; nt2++) {
                const int row = nw + nt2 * 16 + ((lane >> 4) << 3) + (lane & 7);
                const uint32_t bo =
                    (uint32_t)(row * 128 + ks * 32 + ((lane >> 3) & 1) * 16);
                uint32_t t[4];
                ldsm_x4(t, baseB + sw128(bo));
                bf[nt2 * 2 + 0][0] = t[0]; bf[nt2 * 2 + 0][1] = t[1];
                bf[nt2 * 2 + 1][0] = t[2]; bf[nt2 * 2 + 1][1] = t[3];
            }
#pragma unroll
            for (int mt = 0; mt < 4; mt++)
#pragma unroll
                for (int nt = 0; nt < 4; nt++)
                    mma_bf16(acc[mt][nt], af[mt], bf[nt]);
        }
        __syncthreads();
    }

    const int r0 = mb + mw + (lane >> 2);
    const int c0 = nb + nw + (lane & 3) * 2;

    if (MODE == 0) {
#pragma unroll
        for (int mt = 0; mt < 4; mt++) {
#pragma unroll
            for (int nt = 0; nt < 4; nt++) {
                const int col = c0 + nt * 8;
                const float bx = bias[col], by = bias[col + 1];
                float2 v0 = make_float2(acc[mt][nt][0] + bx, acc[mt][nt][1] + by);
                float2 v1 = make_float2(acc[mt][nt][2] + bx, acc[mt][nt][3] + by);
                *(float2*)(C + (size_t)(r0 + mt * 16) * N + col)     = v0;
                *(float2*)(C + (size_t)(r0 + mt * 16 + 8) * N + col) = v1;
            }
        }
    } else {
        // qkv epilogue: scatter into attention operand layouts
#pragma unroll
        for (int nt = 0; nt < 4; nt++) {
            const int col = c0 + nt * 8;
            const int src = col >> 10;          // 0=q, 1=k, 2=v (warp-uniform)
            const int cc  = col & 1023;
            const int h   = cc >> 6;
            const int d   = cc & 63;
            const float bx = bias[col], by = bias[col + 1];
#pragma unroll
            for (int mt = 0; mt < 4; mt++) {
#pragma unroll
                for (int half = 0; half < 2; half++) {
                    const int r = r0 + mt * 16 + half * 8;
                    const float vx = acc[mt][nt][half * 2 + 0] + bx;
                    const float vy = acc[mt][nt][half * 2 + 1] + by;
                    const int bsel = r >> 11;
                    const int t    = r & 2047;
                    const size_t o =
                        ((size_t)(bsel * HH + h) * TT + t) * DK + d;
                    if (src == 2) {
                        *(float2*)(g_v + o) = make_float2(vx, vy);
                    } else {
                        const float hx = __bfloat162float(__float2bfloat16(vx));
                        const float hy = __bfloat162float(__float2bfloat16(vy));
                        if (src == 0) {
                            *(uint32_t*)(g_qh + o) = pack2(hx, hy);
                            *(uint32_t*)(g_ql + o) = pack2(vx - hx, vy - hy);
                        } else {
                            *(uint32_t*)(g_kh + o) = pack2(hx, hy);
                            *(uint32_t*)(g_kl + o) = pack2(vx - hx, vy - hy);
                        }
                    }
                }
            }
        }
    }
}

// ---------------------------------------------------------------------------
// Split fp32 -> compensated bf16 triple along K (x and the two weights).
// type 0 (A operand): (hi | lo | hi)   type 1 (B operand): (hi | hi | lo)
// ---------------------------------------------------------------------------
__global__ __launch_bounds__(256)
void split_hilo(const float* __restrict__ in, __nv_bfloat16* __restrict__ out,
                int total, int type)
{
    int idx = blockIdx.x * 256 + threadIdx.x;
    if (idx >= total) return;
    const int r = idx >> 10;
    const int k = idx & 1023;
    const float x = in[idx];
    const __nv_bfloat16 h = __float2bfloat16(x);
    const __nv_bfloat16 l = __float2bfloat16(x - __bfloat162float(h));
    const size_t o = (size_t)r * KSPLIT + k;
    if (type == 0) { out[o] = h; out[o + 1024] = l; out[o + 2048] = h; }
    else           { out[o] = h; out[o + 1024] = h; out[o + 2048] = l; }
}

// ---------------------------------------------------------------------------
// V transpose + split: g_v [bh][t][64] fp32 -> V^T hi/lo [bh][d][t].
// ---------------------------------------------------------------------------
__global__ __launch_bounds__(256)
void v_split(const float* __restrict__ v,
             __nv_bfloat16* __restrict__ vht, __nv_bfloat16* __restrict__ vlt)
{
    __shared__ float tile[128][65];
    const int tid = threadIdx.x;
    const int t0  = blockIdx.x * 128;
    const int h   = blockIdx.y;
    const int b   = blockIdx.z;
    const int bh  = b * HH + h;

#pragma unroll
    for (int i = 0; i < 8; i++) {
        const int s   = tid + i * 256;
        const int row = s >> 4;
        const int c4  = (s & 15) * 4;
        float4 vv = *(const float4*)(v + ((size_t)bh * TT + t0 + row) * DK + c4);
        tile[row][c4 + 0] = vv.x; tile[row][c4 + 1] = vv.y;
        tile[row][c4 + 2] = vv.z; tile[row][c4 + 3] = vv.w;
    }
    __syncthreads();

    const int wid  = tid >> 5;
    const int lane = tid & 31;
#pragma unroll
    for (int r = 0; r < 8; r++) {
        const int d = wid * 8 + r;
        uint32_t* oh = (uint32_t*)(vht + ((size_t)bh * DK + d) * TT + t0);
        uint32_t* ol = (uint32_t*)(vlt + ((size_t)bh * DK + d) * TT + t0);
#pragma unroll
        for (int it = 0; it < 2; it++) {
            const int tt = (lane + it * 32) * 2;
            const float v0 = tile[tt][d], v1 = tile[tt + 1][d];
            const float h0 = __bfloat162float(__float2bfloat16(v0));
            const float h1 = __bfloat162float(__float2bfloat16(v1));
            oh[lane + it * 32] = pack2(h0, h1);
            ol[lane + it * 32] = pack2(v0 - h0, v1 - h1);
        }
    }
}

// ---------------------------------------------------------------------------
// Flash attention on tensor cores (compensated bf16).
// Block: 128 queries x one (b,h). 256 threads = 8 warps; warp w owns query
// rows [w*16, w*16+16). Key tiles of 64. Epilogue writes the proj-GEMM
// A-operand layout (hi | lo | hi) directly.
// ---------------------------------------------------------------------------
#define SQHI 0
#define SQLO 16384
#define SKHI 32768
#define SKLO 40960
#define SVHI 49152
#define SVLO 57344
#define SPHI 65536
#define SPLO 81920
#define SPAD 98304
#define ATT2_SMEM (98304 + 256)

__global__ __launch_bounds__(256)
void attn_mma(const __nv_bfloat16* __restrict__ qh,
              const __nv_bfloat16* __restrict__ ql,
              const __nv_bfloat16* __restrict__ kh,
              const __nv_bfloat16* __restrict__ kl,
              const __nv_bfloat16* __restrict__ vht,
              const __nv_bfloat16* __restrict__ vlt,
              const int* __restrict__ mask,
              __nv_bfloat16* __restrict__ yp)
{
    extern __shared__ char smc[];
    const uint32_t sb = smem_u32(smc);
    int* padm = (int*)(smc + SPAD);

    const int tid  = threadIdx.x;
    const int wid  = tid >> 5;
    const int lane = tid & 31;
    const int bx   = gridDim.x - 1 - blockIdx.x;   // heavy blocks first
    const int b    = blockIdx.z;
    const int hh   = blockIdx.y;
    const int bh   = b * HH + hh;
    const int qb   = bx * 128;

    // ---- load Q (hi & lo) ----
    {
        const __nv_bfloat16* qhp = qh + ((size_t)bh * TT + qb) * DK;
        const __nv_bfloat16* qlp = ql + ((size_t)bh * TT + qb) * DK;
#pragma unroll
        for (int i = 0; i < 4; i++) {
            const int s   = tid + i * 256;
            const int row = s >> 3;
            const int ci  = s & 7;
            const uint32_t sw = sw128((uint32_t)(row * 128 + ci * 16));
            cp16(sb + SQHI + sw, qhp + (size_t)row * DK + ci * 8);
            cp16(sb + SQLO + sw, qlp + (size_t)row * DK + ci * 8);
        }
        cp_commit();
    }

    float acc[8][4];
#pragma unroll
    for (int nt = 0; nt < 8; nt++)
#pragma unroll
        for (int q = 0; q < 4; q++) acc[nt][q] = 0.f;
    float m0 = -INFINITY, m1 = -INFINITY, l0 = 0.f, l1 = 0.f;

    const int r0g = qb + wid * 16 + (lane >> 2);
    const int r1g = r0g + 8;

    const int ntiles = 2 * bx + 2;
    for (int kt = 0; kt < ntiles; kt++) {
        const int j0 = kt * 64;
        __syncthreads();

        {
            const __nv_bfloat16* khp = kh + ((size_t)bh * TT + j0) * DK;
            const __nv_bfloat16* klp = kl + ((size_t)bh * TT + j0) * DK;
            const __nv_bfloat16* vhp = vht + (size_t)bh * DK * TT + j0;
            const __nv_bfloat16* vlp = vlt + (size_t)bh * DK * TT + j0;
#pragma unroll
            for (int i = 0; i < 2; i++) {
                const int s   = tid + i * 256;
                const int row = s >> 3;
                const int ci  = s & 7;
                const uint32_t sw = sw128((uint32_t)(row * 128 + ci * 16));
                cp16(sb + SKHI + sw, khp + (size_t)row * DK + ci * 8);
                cp16(sb + SKLO + sw, klp + (size_t)row * DK + ci * 8);
                cp16(sb + SVHI + sw, vhp + (size_t)row * TT + ci * 8);
                cp16(sb + SVLO + sw, vlp + (size_t)row * TT + ci * 8);
            }
            if (tid < 64) padm[tid] = mask[b * TT + j0 + tid];
            cp_commit();
            cp_wait<0>();
            __syncthreads();
        }

        // ---- S = Qhi*Khi + Qlo*Khi + Qhi*Klo ----
        float s4[8][4];
#pragma unroll
        for (int nt = 0; nt < 8; nt++)
#pragma unroll
            for (int q = 0; q < 4; q++) s4[nt][q] = 0.f;

#pragma unroll
        for (int seg = 0; seg < 3; seg++) {
            const uint32_t Ab = sb + (seg == 1 ? SQLO : SQHI);
            const uint32_t Bb = sb + (seg == 2 ? SKLO : SKHI);
#pragma unroll
            for (int ks = 0; ks < 4; ks++) {
                uint32_t af[4];
                {
                    const int row = wid * 16 + (lane & 15);
                    const uint32_t bo =
                        (uint32_t)(row * 128 + ks * 32 + ((lane >> 4) & 1) * 16);
                    ldsm_x4(af, Ab + sw128(bo));
                }
#pragma unroll
                for (int nt2 = 0; nt2 < 4; nt2++) {
                    const int row = nt2 * 16 + ((lane >> 4) << 3) + (lane & 7);
                    const uint32_t bo =
                        (uint32_t)(row * 128 + ks * 32 + ((lane >> 3) & 1) * 16);
                    uint32_t t[4];
                    ldsm_x4(t, Bb + sw128(bo));
                    mma_bf16(s4[nt2 * 2 + 0], af, t);
                    mma_bf16(s4[nt2 * 2 + 1], af, t + 2);
                }
            }
        }

        // ---- mask + scale ----
#pragma unroll
        for (int nt = 0; nt < 8; nt++) {
            const int c0 = nt * 8 + (lane & 3) * 2;
            const bool p0 = padm[c0] != 0, p1 = padm[c0 + 1] != 0;
            const int jg0 = j0 + c0, jg1 = jg0 + 1;
            s4[nt][0] = (p0 && jg0 <= r0g) ? s4[nt][0] * 0.125f : -INFINITY;
            s4[nt][1] = (p1 && jg1 <= r0g) ? s4[nt][1] * 0.125f : -INFINITY;
            s4[nt][2] = (p0 && jg0 <= r1g) ? s4[nt][2] * 0.125f : -INFINITY;
            s4[nt][3] = (p1 && jg1 <= r1g) ? s4[nt][3] * 0.125f : -INFINITY;
        }

        // ---- online softmax ----
        float mx0 = -INFINITY, mx1 = -INFINITY;
#pragma unroll
        for (int nt = 0; nt < 8; nt++) {
            mx0 = fmaxf(mx0, fmaxf(s4[nt][0], s4[nt][1]));
            mx1 = fmaxf(mx1, fmaxf(s4[nt][2], s4[nt][3]));
        }
        mx0 = fmaxf(mx0, __shfl_xor_sync(0xffffffffu, mx0, 1));
        mx0 = fmaxf(mx0, __shfl_xor_sync(0xffffffffu, mx0, 2));
        mx1 = fmaxf(mx1, __shfl_xor_sync(0xffffffffu, mx1, 1));
        mx1 = fmaxf(mx1, __shfl_xor_sync(0xffffffffu, mx1, 2));

        float a0 = 1.f, a1 = 1.f;
        if (mx0 > -INFINITY) {
            const float mn = fmaxf(m0, mx0);
            a0 = __expf(m0 - mn);
            m0 = mn;
        }
        if (mx1 > -INFINITY) {
            const float mn = fmaxf(m1, mx1);
            a1 = __expf(m1 - mn);
            m1 = mn;
        }
        const float mm0 = (m0 == -INFINITY) ? 0.f : m0;
        const float mm1 = (m1 == -INFINITY) ? 0.f : m1;

        // ---- p = exp(s-m) -> hi/lo smem P tiles ----
        const int pr0 = wid * 16 + (lane >> 2);
        const uint32_t pcolb = (uint32_t)((lane & 3) * 4);
        float sum0 = 0.f, sum1 = 0.f;
#pragma unroll
        for (int nt = 0; nt < 8; nt++) {
            const float p00 = __expf(s4[nt][0] - mm0);
            const float p01 = __expf(s4[nt][1] - mm0);
            const float p10 = __expf(s4[nt][2] - mm1);
            const float p11 = __expf(s4[nt][3] - mm1);
            sum0 += p00 + p01;
            sum1 += p10 + p11;
            const float h00 = __bfloat162float(__float2bfloat16(p00));
            const float h01 = __bfloat162float(__float2bfloat16(p01));
            const float h10 = __bfloat162float(__float2bfloat16(p10));
            const float h11 = __bfloat162float(__float2bfloat16(p11));
            const uint32_t bo0 = (uint32_t)(pr0 * 128 + nt * 16) + pcolb;
            const uint32_t bo1 = bo0 + 8 * 128;
            *(uint32_t*)(smc + SPHI + sw128(bo0)) = pack2(h00, h01);
            *(uint32_t*)(smc + SPHI + sw128(bo1)) = pack2(h10, h11);
            *(uint32_t*)(smc + SPLO + sw128(bo0)) = pack2(p00 - h00, p01 - h01);
            *(uint32_t*)(smc + SPLO + sw128(bo1)) = pack2(p10 - h10, p11 - h11);
        }
        sum0 += __shfl_xor_sync(0xffffffffu, sum0, 1);
        sum0 += __shfl_xor_sync(0xffffffffu, sum0, 2);
        sum1 += __shfl_xor_sync(0xffffffffu, sum1, 1);
        sum1 += __shfl_xor_sync(0xffffffffu, sum1, 2);
        l0 = l0 * a0 + sum0;
        l1 = l1 * a1 + sum1;

#pragma unroll
        for (int nt = 0; nt < 8; nt++) {
            acc[nt][0] *= a0; acc[nt][1] *= a0;
            acc[nt][2] *= a1; acc[nt][3] *= a1;
        }
        __syncwarp();

        // ---- O += Phi*Vhi + Plo*Vhi + Phi*Vlo ----
#pragma unroll
        for (int seg = 0; seg < 3; seg++) {
            const uint32_t Ab = sb + (seg == 1 ? SPLO : SPHI);
            const uint32_t Bb = sb + (seg == 2 ? SVLO : SVHI);
#pragma unroll
            for (int ks = 0; ks < 4; ks++) {
                uint32_t af[4];
                {
                    const int row = wid * 16 + (lane & 15);
                    const uint32_t bo =
                        (uint32_t)(row * 128 + ks * 32 + ((lane >> 4) & 1) * 16);
                    ldsm_x4(af, Ab + sw128(bo));
                }
#pragma unroll
                for (int nt2 = 0; nt2 < 4; nt2++) {
                    const int row = nt2 * 16 + ((lane >> 4) << 3) + (lane & 7);
                    const uint32_t bo =
                        (uint32_t)(row * 128 + ks * 32 + ((lane >> 3) & 1) * 16);
                    uint32_t t[4];
                    ldsm_x4(t, Bb + sw128(bo));
                    mma_bf16(acc[nt2 * 2 + 0], af, t);
                    mma_bf16(acc[nt2 * 2 + 1], af, t + 2);
                }
            }
        }
    }

    // ---- epilogue: write proj A-operand layout (hi | lo | hi) directly ----
    const float inv0 = (l0 > 0.f) ? (1.f / l0) : 0.f;
    const float inv1 = (l1 > 0.f) ? (1.f / l1) : 0.f;
#pragma unroll
    for (int nt = 0; nt < 8; nt++) {
        const int col = hh * DK + nt * 8 + (lane & 3) * 2;
        {
            const float vx = acc[nt][0] * inv0, vy = acc[nt][1] * inv0;
            const float hx = __bfloat162float(__float2bfloat16(vx));
            const float hy = __bfloat162float(__float2bfloat16(vy));
            const size_t o = ((size_t)b * TT + r0g) * KSPLIT + col;
            const uint32_t hp = pack2(hx, hy);
            *(uint32_t*)(yp + o)        = hp;
            *(uint32_t*)(yp + o + 1024) = pack2(vx - hx, vy - hy);
            *(uint32_t*)(yp + o + 2048) = hp;
        }
        {
            const float vx = acc[nt][2] * inv1, vy = acc[nt][3] * inv1;
            const float hx = __bfloat162float(__float2bfloat16(vx));
            const float hy = __bfloat162float(__float2bfloat16(vy));
            const size_t o = ((size_t)b * TT + r1g) * KSPLIT + col;
            const uint32_t hp = pack2(hx, hy);
            *(uint32_t*)(yp + o)        = hp;
            *(uint32_t*)(yp + o + 1024) = pack2(vx - hx, vy - hy);
            *(uint32_t*)(yp + o + 2048) = hp;
        }
    }
}

// ---------------------------------------------------------------------------
extern "C" void kernel_launch(void* const* d_in, const int* in_sizes, int n_in,
                              void* d_out, int out_size)
{
    const float* x     = (const float*)d_in[0];
    const float* Wqkv  = (const float*)d_in[1];
    const float* bqkv  = (const float*)d_in[2];
    const float* Wproj = (const float*)d_in[3];
    const float* bproj = (const float*)d_in[4];
    const int*   mask  = (const int*)d_in[5];
    float* out = (float*)d_out;

    float *vp;
    __nv_bfloat16 *xpp, *wqp, *ypp, *wpp;
    __nv_bfloat16 *qhp, *qlp, *khp, *klp, *vhp, *vlp;
    cudaGetSymbolAddress((void**)&vp,   g_v);
    cudaGetSymbolAddress((void**)&xpp,  g_xp);
    cudaGetSymbolAddress((void**)&wqp,  g_wqkvp);
    cudaGetSymbolAddress((void**)&ypp,  g_yp);
    cudaGetSymbolAddress((void**)&wpp,  g_wprojp);
    cudaGetSymbolAddress((void**)&qhp,  g_qh);
    cudaGetSymbolAddress((void**)&qlp,  g_ql);
    cudaGetSymbolAddress((void**)&khp,  g_kh);
    cudaGetSymbolAddress((void**)&klp,  g_kl);
    cudaGetSymbolAddress((void**)&vhp,  g_vht);
    cudaGetSymbolAddress((void**)&vlp,  g_vlt);

    cudaFuncSetAttribute(gemm_bf16_mma<0>,
                         cudaFuncAttributeMaxDynamicSharedMemorySize, GEMM_SMEM);
    cudaFuncSetAttribute(gemm_bf16_mma<1>,
                         cudaFuncAttributeMaxDynamicSharedMemorySize, GEMM_SMEM);
    cudaFuncSetAttribute(attn_mma,
                         cudaFuncAttributeMaxDynamicSharedMemorySize, ATT2_SMEM);

    // input splits
    split_hilo<<<(MROWS * DD) / 256, 256>>>(x, xpp, MROWS * DD, 0);
    split_hilo<<<(3 * DD * DD) / 256, 256>>>(Wqkv, wqp, 3 * DD * DD, 1);
    split_hilo<<<(DD * DD) / 256, 256>>>(Wproj, wpp, DD * DD, 1);

    // qkv GEMM with fused q/k split + compact V
    gemm_bf16_mma<1><<<dim3(3 * DD / 128, MROWS / 128), 256, GEMM_SMEM>>>(
        xpp, wqp, bqkv, nullptr, MROWS, 3 * DD, KSPLIT);

    // V transpose + split
    v_split<<<dim3(TT / 128, HH, BB), 256>>>(vp, vhp, vlp);

    // attention -> g_yp (proj A-operand layout, fused)
    attn_mma<<<dim3(TT / 128, HH, BB), 256, ATT2_SMEM>>>(
        qhp, qlp, khp, klp, vhp, vlp, mask, ypp);

    // out = y @ Wproj^T + bproj
    gemm_bf16_mma<0><<<dim3(DD / 128, MROWS / 128), 256, GEMM_SMEM>>>(
        ypp, wpp, bproj, out, MROWS, DD, KSPLIT);
}

// round 11
// speedup vs baseline: 1.2131x; 1.0983x over previous
#include <cuda_runtime.h>
#include <cuda_bf16.h>
#include <cstdint>
#include <stdint.h>
#include <math.h>

// Problem constants (fixed by the reference)
#define BB 4
#define TT 2048
#define DD 1024
#define HH 16
#define DK 64
#define MROWS (BB * TT)          // 8192
#define KSPLIT (3 * DD)          // 3072 = split-K' for compensated bf16 GEMM

// Scratch (allocation-free rule: __device__ globals)
__device__ float         g_v[(size_t)BB * HH * TT * DK];    // V fp32 [bh][t][d]
__device__ __nv_bfloat16 g_xp[(size_t)MROWS * KSPLIT];      // x  split  (hi|lo|hi)
__device__ __nv_bfloat16 g_wqkvp[(size_t)(3 * DD) * KSPLIT];// Wqkv split (hi|hi|lo)
__device__ __nv_bfloat16 g_yp[(size_t)MROWS * KSPLIT];      // y  split  (hi|lo|hi)
__device__ __nv_bfloat16 g_wprojp[(size_t)DD * KSPLIT];     // Wproj split (hi|hi|lo)
// attention operand tensors, per (b,h):
__device__ __nv_bfloat16 g_qh[(size_t)BB * HH * TT * DK];   // Q hi  [bh][t][d]
__device__ __nv_bfloat16 g_ql[(size_t)BB * HH * TT * DK];   // Q lo
__device__ __nv_bfloat16 g_kh[(size_t)BB * HH * TT * DK];   // K hi
__device__ __nv_bfloat16 g_kl[(size_t)BB * HH * TT * DK];   // K lo
__device__ __nv_bfloat16 g_vht[(size_t)BB * HH * DK * TT];  // V^T hi [bh][d][t]
__device__ __nv_bfloat16 g_vlt[(size_t)BB * HH * DK * TT];  // V^T lo

// ---------------------------------------------------------------------------
// helpers (all baseline PTX — compiles on compute_103)
// ---------------------------------------------------------------------------
__device__ __forceinline__ uint32_t smem_u32(const void* p) {
    uint32_t a;
    asm("{ .reg .u64 t; cvta.to.shared.u64 t, %1; cvt.u32.u64 %0, t; }"
        : "=r"(a) : "l"(p));
    return a;
}
__device__ __forceinline__ void cp16(uint32_t saddr, const void* gaddr) {
    asm volatile("cp.async.cg.shared.global [%0], [%1], 16;"
                 :: "r"(saddr), "l"(gaddr) : "memory");
}
__device__ __forceinline__ void cp_commit() {
    asm volatile("cp.async.commit_group;" ::: "memory");
}
template <int N>
__device__ __forceinline__ void cp_wait() {
    asm volatile("cp.async.wait_group %0;" :: "n"(N) : "memory");
}
__device__ __forceinline__ void ldsm_x4(uint32_t* r, uint32_t addr) {
    asm volatile("ldmatrix.sync.aligned.m8n8.x4.shared.b16 {%0,%1,%2,%3}, [%4];"
                 : "=r"(r[0]), "=r"(r[1]), "=r"(r[2]), "=r"(r[3]) : "r"(addr));
}
__device__ __forceinline__ void mma_bf16(float* c, const uint32_t* a,
                                         const uint32_t* b) {
    asm volatile(
        "mma.sync.aligned.m16n8k16.row.col.f32.bf16.bf16.f32 "
        "{%0,%1,%2,%3}, {%4,%5,%6,%7}, {%8,%9}, {%0,%1,%2,%3};"
        : "+f"(c[0]), "+f"(c[1]), "+f"(c[2]), "+f"(c[3])
        : "r"(a[0]), "r"(a[1]), "r"(a[2]), "r"(a[3]), "r"(b[0]), "r"(b[1]));
}
__device__ __forceinline__ uint32_t sw128(uint32_t bo) {
    return bo ^ ((bo >> 3) & 0x70);
}
__device__ __forceinline__ uint32_t pack2(float a, float b) {
    __nv_bfloat162 t = __floats2bfloat162_rn(a, b);
    return *(uint32_t*)&t;
}

#define GEMM_SMEM 65536   // 2 x (16KB A + 16KB B)

// ---------------------------------------------------------------------------
// Tensor-core GEMM via mma.sync: C = A @ B^T + bias.  (unchanged — verified)
// ---------------------------------------------------------------------------
template <int MODE>
__global__ __launch_bounds__(256, 2)
void gemm_bf16_mma(const __nv_bfloat16* __restrict__ A,
                   const __nv_bfloat16* __restrict__ B,
                   const float* __restrict__ bias, float* __restrict__ C,
                   int M, int N, int K)
{
    extern __shared__ char smc[];
    const uint32_t sb = smem_u32(smc);
    const int tid  = threadIdx.x;
    const int wid  = tid >> 5;
    const int lane = tid & 31;
    const int nb   = blockIdx.x * 128;
    const int mb   = blockIdx.y * 128;
    const int mw   = (wid >> 2) * 64;
    const int nw   = (wid & 3) * 32;

    const uint32_t sA = sb;
    const uint32_t sB = sb + 32768;

    float acc[4][4][4];
#pragma unroll
    for (int mt = 0; mt < 4; mt++)
#pragma unroll
        for (int nt = 0; nt < 4; nt++)
#pragma unroll
            for (int q = 0; q < 4; q++) acc[mt][nt][q] = 0.f;

    const int lrow = tid >> 3;
    const int lci  = tid & 7;
    const uint32_t lsw = sw128((uint32_t)(lrow * 128 + lci * 16));

    const int nch = K >> 6;
    {
        const __nv_bfloat16* Ap = A + (size_t)mb * K;
        const __nv_bfloat16* Bp = B + (size_t)nb * K;
#pragma unroll
        for (int i = 0; i < 4; i++) {
            const uint32_t so = lsw + i * 4096;
            cp16(sA + so, Ap + (size_t)(lrow + i * 32) * K + lci * 8);
            cp16(sB + so, Bp + (size_t)(lrow + i * 32) * K + lci * 8);
        }
        cp_commit();
    }

    for (int c = 0; c < nch; c++) {
        const int s = c & 1;
        if (c + 1 < nch) {
            const int k0 = (c + 1) << 6;
            const __nv_bfloat16* Ap = A + (size_t)mb * K + k0;
            const __nv_bfloat16* Bp = B + (size_t)nb * K + k0;
            const uint32_t sbuf = (s ^ 1) * 16384;
#pragma unroll
            for (int i = 0; i < 4; i++) {
                const uint32_t so = sbuf + lsw + i * 4096;
                cp16(sA + so, Ap + (size_t)(lrow + i * 32) * K + lci * 8);
                cp16(sB + so, Bp + (size_t)(lrow + i * 32) * K + lci * 8);
            }
            cp_commit();
            cp_wait<1>();
        } else {
            cp_wait<0>();
        }
        __syncthreads();

        const uint32_t baseA = sA + s * 16384;
        const uint32_t baseB = sB + s * 16384;
#pragma unroll
        for (int ks = 0; ks < 4; ks++) {
            uint32_t af[4][4];
#pragma unroll
            for (int mt = 0; mt < 4; mt++) {
                const int row = mw + mt * 16 + (lane & 15);
                const uint32_t bo =
                    (uint32_t)(row * 128 + ks * 32 + ((lane >> 4) & 1) * 16);
                ldsm_x4(af[mt], baseA + sw128(bo));
            }
            uint32_t bf[4][2];
#pragma unroll
            for (int nt2 = 0; nt2 < 2; nt2++) {
                const int row = nw + nt2 * 16 + ((lane >> 4) << 3) + (lane & 7);
                const uint32_t bo =
                    (uint32_t)(row * 128 + ks * 32 + ((lane >> 3) & 1) * 16);
                uint32_t t[4];
                ldsm_x4(t, baseB + sw128(bo));
                bf[nt2 * 2 + 0][0] = t[0]; bf[nt2 * 2 + 0][1] = t[1];
                bf[nt2 * 2 + 1][0] = t[2]; bf[nt2 * 2 + 1][1] = t[3];
            }
#pragma unroll
            for (int mt = 0; mt < 4; mt++)
#pragma unroll
                for (int nt = 0; nt < 4; nt++)
                    mma_bf16(acc[mt][nt], af[mt], bf[nt]);
        }
        __syncthreads();
    }

    const int r0 = mb + mw + (lane >> 2);
    const int c0 = nb + nw + (lane & 3) * 2;

    if (MODE == 0) {
#pragma unroll
        for (int mt = 0; mt < 4; mt++) {
#pragma unroll
            for (int nt = 0; nt < 4; nt++) {
                const int col = c0 + nt * 8;
                const float bx = bias[col], by = bias[col + 1];
                float2 v0 = make_float2(acc[mt][nt][0] + bx, acc[mt][nt][1] + by);
                float2 v1 = make_float2(acc[mt][nt][2] + bx, acc[mt][nt][3] + by);
                *(float2*)(C + (size_t)(r0 + mt * 16) * N + col)     = v0;
                *(float2*)(C + (size_t)(r0 + mt * 16 + 8) * N + col) = v1;
            }
        }
    } else {
        // qkv epilogue: scatter into attention operand layouts
#pragma unroll
        for (int nt = 0; nt < 4; nt++) {
            const int col = c0 + nt * 8;
            const int src = col >> 10;          // 0=q, 1=k, 2=v (warp-uniform)
            const int cc  = col & 1023;
            const int h   = cc >> 6;
            const int d   = cc & 63;
            const float bx = bias[col], by = bias[col + 1];
#pragma unroll
            for (int mt = 0; mt < 4; mt++) {
#pragma unroll
                for (int half = 0; half < 2; half++) {
                    const int r = r0 + mt * 16 + half * 8;
                    const float vx = acc[mt][nt][half * 2 + 0] + bx;
                    const float vy = acc[mt][nt][half * 2 + 1] + by;
                    const int bsel = r >> 11;
                    const int t    = r & 2047;
                    const size_t o =
                        ((size_t)(bsel * HH + h) * TT + t) * DK + d;
                    if (src == 2) {
                        *(float2*)(g_v + o) = make_float2(vx, vy);
                    } else {
                        const float hx = __bfloat162float(__float2bfloat16(vx));
                        const float hy = __bfloat162float(__float2bfloat16(vy));
                        if (src == 0) {
                            *(uint32_t*)(g_qh + o) = pack2(hx, hy);
                            *(uint32_t*)(g_ql + o) = pack2(vx - hx, vy - hy);
                        } else {
                            *(uint32_t*)(g_kh + o) = pack2(hx, hy);
                            *(uint32_t*)(g_kl + o) = pack2(vx - hx, vy - hy);
                        }
                    }
                }
            }
        }
    }
}

// ---------------------------------------------------------------------------
// Split fp32 -> compensated bf16 triple along K (x and the two weights).
// ---------------------------------------------------------------------------
__global__ __launch_bounds__(256)
void split_hilo(const float* __restrict__ in, __nv_bfloat16* __restrict__ out,
                int total, int type)
{
    int idx = blockIdx.x * 256 + threadIdx.x;
    if (idx >= total) return;
    const int r = idx >> 10;
    const int k = idx & 1023;
    const float x = in[idx];
    const __nv_bfloat16 h = __float2bfloat16(x);
    const __nv_bfloat16 l = __float2bfloat16(x - __bfloat162float(h));
    const size_t o = (size_t)r * KSPLIT + k;
    if (type == 0) { out[o] = h; out[o + 1024] = l; out[o + 2048] = h; }
    else           { out[o] = h; out[o + 1024] = h; out[o + 2048] = l; }
}

// ---------------------------------------------------------------------------
// V transpose + split: g_v [bh][t][64] fp32 -> V^T hi/lo [bh][d][t].
// ---------------------------------------------------------------------------
__global__ __launch_bounds__(256)
void v_split(const float* __restrict__ v,
             __nv_bfloat16* __restrict__ vht, __nv_bfloat16* __restrict__ vlt)
{
    __shared__ float tile[128][65];
    const int tid = threadIdx.x;
    const int t0  = blockIdx.x * 128;
    const int h   = blockIdx.y;
    const int b   = blockIdx.z;
    const int bh  = b * HH + h;

#pragma unroll
    for (int i = 0; i < 8; i++) {
        const int s   = tid + i * 256;
        const int row = s >> 4;
        const int c4  = (s & 15) * 4;
        float4 vv = *(const float4*)(v + ((size_t)bh * TT + t0 + row) * DK + c4);
        tile[row][c4 + 0] = vv.x; tile[row][c4 + 1] = vv.y;
        tile[row][c4 + 2] = vv.z; tile[row][c4 + 3] = vv.w;
    }
    __syncthreads();

    const int wid  = tid >> 5;
    const int lane = tid & 31;
#pragma unroll
    for (int r = 0; r < 8; r++) {
        const int d = wid * 8 + r;
        uint32_t* oh = (uint32_t*)(vht + ((size_t)bh * DK + d) * TT + t0);
        uint32_t* ol = (uint32_t*)(vlt + ((size_t)bh * DK + d) * TT + t0);
#pragma unroll
        for (int it = 0; it < 2; it++) {
            const int tt = (lane + it * 32) * 2;
            const float v0 = tile[tt][d], v1 = tile[tt + 1][d];
            const float h0 = __bfloat162float(__float2bfloat16(v0));
            const float h1 = __bfloat162float(__float2bfloat16(v1));
            oh[lane + it * 32] = pack2(h0, h1);
            ol[lane + it * 32] = pack2(v0 - h0, v1 - h1);
        }
    }
}

// ---------------------------------------------------------------------------
// Flash attention on tensor cores (compensated bf16), software-pipelined.
// Block: 128 queries x one (b,h). 256 threads = 8 warps; warp w owns query
// rows [w*16, w*16+16). Key tiles of 64. K and V travel in SEPARATE cp.async
// groups: K(kt+1) is issued right after S consumes Kbuf (overlaps with
// softmax+PV); V(kt+1) after PV consumes Vbuf. Fragment reuse: each B-frag
// (Khi/Klo/Vhi/Vlo) is ldsm'd once and feeds all compensation MMAs.
// ---------------------------------------------------------------------------
#define SQHI 0
#define SQLO 16384
#define SKHI 32768
#define SKLO 40960
#define SVHI 49152
#define SVLO 57344
#define SPHI 65536
#define SPLO 81920
#define SPAD 98304
#define ATT2_SMEM (98304 + 256)

// issue one 64-row hi/lo tile pair (8KB each) as ONE commit group
__device__ __forceinline__ void att_issue_tile(
    uint32_t dst_hi, uint32_t dst_lo,
    const __nv_bfloat16* __restrict__ hp, const __nv_bfloat16* __restrict__ lp,
    size_t rstride, int tid)
{
#pragma unroll
    for (int i = 0; i < 2; i++) {
        const int s   = tid + i * 256;
        const int row = s >> 3;
        const int ci  = s & 7;
        const uint32_t sw = sw128((uint32_t)(row * 128 + ci * 16));
        cp16(dst_hi + sw, hp + (size_t)row * rstride + ci * 8);
        cp16(dst_lo + sw, lp + (size_t)row * rstride + ci * 8);
    }
    cp_commit();
}

__global__ __launch_bounds__(256)
void attn_mma(const __nv_bfloat16* __restrict__ qh,
              const __nv_bfloat16* __restrict__ ql,
              const __nv_bfloat16* __restrict__ kh,
              const __nv_bfloat16* __restrict__ kl,
              const __nv_bfloat16* __restrict__ vht,
              const __nv_bfloat16* __restrict__ vlt,
              const int* __restrict__ mask,
              __nv_bfloat16* __restrict__ yp)
{
    extern __shared__ char smc[];
    const uint32_t sb = smem_u32(smc);
    int* padm = (int*)(smc + SPAD);

    const int tid  = threadIdx.x;
    const int wid  = tid >> 5;
    const int lane = tid & 31;
    const int bx   = gridDim.x - 1 - blockIdx.x;   // heavy blocks first
    const int b    = blockIdx.z;
    const int hh   = blockIdx.y;
    const int bh   = b * HH + hh;
    const int qb   = bx * 128;

    const __nv_bfloat16* khB = kh + (size_t)bh * TT * DK;
    const __nv_bfloat16* klB = kl + (size_t)bh * TT * DK;
    const __nv_bfloat16* vhB = vht + (size_t)bh * DK * TT;
    const __nv_bfloat16* vlB = vlt + (size_t)bh * DK * TT;

    // ---- group 1: Q (hi & lo) ----
    {
        const __nv_bfloat16* qhp = qh + ((size_t)bh * TT + qb) * DK;
        const __nv_bfloat16* qlp = ql + ((size_t)bh * TT + qb) * DK;
#pragma unroll
        for (int i = 0; i < 4; i++) {
            const int s   = tid + i * 256;
            const int row = s >> 3;
            const int ci  = s & 7;
            const uint32_t sw = sw128((uint32_t)(row * 128 + ci * 16));
            cp16(sb + SQHI + sw, qhp + (size_t)row * DK + ci * 8);
            cp16(sb + SQLO + sw, qlp + (size_t)row * DK + ci * 8);
        }
        cp_commit();
    }
    // ---- group 2: K(0), group 3: V(0) ----
    att_issue_tile(sb + SKHI, sb + SKLO, khB, klB, DK, tid);
    att_issue_tile(sb + SVHI, sb + SVLO, vhB, vlB, TT, tid);

    float acc[8][4];
#pragma unroll
    for (int nt = 0; nt < 8; nt++)
#pragma unroll
        for (int q = 0; q < 4; q++) acc[nt][q] = 0.f;
    float m0 = -INFINITY, m1 = -INFINITY, l0 = 0.f, l1 = 0.f;

    const int r0g = qb + wid * 16 + (lane >> 2);
    const int r1g = r0g + 8;

    const int ntiles = 2 * bx + 2;
    for (int kt = 0; kt < ntiles; kt++) {
        const int j0 = kt * 64;

        // K(kt) arrived (and Q on first iter); V(kt) may still be in flight
        cp_wait<1>();
        __syncthreads();
        if (tid < 64) padm[tid] = mask[b * TT + j0 + tid];

        // ---- S = Qhi*Khi + Qlo*Khi + Qhi*Klo (fragment-reuse form) ----
        float s4[8][4];
#pragma unroll
        for (int nt = 0; nt < 8; nt++)
#pragma unroll
            for (int q = 0; q < 4; q++) s4[nt][q] = 0.f;

#pragma unroll
        for (int ks = 0; ks < 4; ks++) {
            uint32_t aqh[4], aql[4];
            {
                const int row = wid * 16 + (lane & 15);
                const uint32_t bo =
                    (uint32_t)(row * 128 + ks * 32 + ((lane >> 4) & 1) * 16);
                ldsm_x4(aqh, sb + SQHI + sw128(bo));
                ldsm_x4(aql, sb + SQLO + sw128(bo));
            }
#pragma unroll
            for (int nt2 = 0; nt2 < 4; nt2++) {
                const int row = nt2 * 16 + ((lane >> 4) << 3) + (lane & 7);
                const uint32_t bo =
                    (uint32_t)(row * 128 + ks * 32 + ((lane >> 3) & 1) * 16);
                uint32_t tk[4];
                ldsm_x4(tk, sb + SKHI + sw128(bo));
                mma_bf16(s4[nt2 * 2 + 0], aqh, tk);
                mma_bf16(s4[nt2 * 2 + 1], aqh, tk + 2);
                mma_bf16(s4[nt2 * 2 + 0], aql, tk);
                mma_bf16(s4[nt2 * 2 + 1], aql, tk + 2);
                uint32_t tl[4];
                ldsm_x4(tl, sb + SKLO + sw128(bo));
                mma_bf16(s4[nt2 * 2 + 0], aqh, tl);
                mma_bf16(s4[nt2 * 2 + 1], aqh, tl + 2);
            }
        }

        __syncthreads();            // Kbuf fully consumed + padm visible
        {                           // prefetch K(kt+1) — overlaps softmax+PV
            const int jn = (kt + 1 < ntiles) ? j0 + 64 : 0;
            att_issue_tile(sb + SKHI, sb + SKLO,
                           khB + (size_t)jn * DK, klB + (size_t)jn * DK, DK, tid);
        }

        // ---- mask + scale ----
#pragma unroll
        for (int nt = 0; nt < 8; nt++) {
            const int c0 = nt * 8 + (lane & 3) * 2;
            const bool p0 = padm[c0] != 0, p1 = padm[c0 + 1] != 0;
            const int jg0 = j0 + c0, jg1 = jg0 + 1;
            s4[nt][0] = (p0 && jg0 <= r0g) ? s4[nt][0] * 0.125f : -INFINITY;
            s4[nt][1] = (p1 && jg1 <= r0g) ? s4[nt][1] * 0.125f : -INFINITY;
            s4[nt][2] = (p0 && jg0 <= r1g) ? s4[nt][2] * 0.125f : -INFINITY;
            s4[nt][3] = (p1 && jg1 <= r1g) ? s4[nt][3] * 0.125f : -INFINITY;
        }

        // ---- online softmax ----
        float mx0 = -INFINITY, mx1 = -INFINITY;
#pragma unroll
        for (int nt = 0; nt < 8; nt++) {
            mx0 = fmaxf(mx0, fmaxf(s4[nt][0], s4[nt][1]));
            mx1 = fmaxf(mx1, fmaxf(s4[nt][2], s4[nt][3]));
        }
        mx0 = fmaxf(mx0, __shfl_xor_sync(0xffffffffu, mx0, 1));
        mx0 = fmaxf(mx0, __shfl_xor_sync(0xffffffffu, mx0, 2));
        mx1 = fmaxf(mx1, __shfl_xor_sync(0xffffffffu, mx1, 1));
        mx1 = fmaxf(mx1, __shfl_xor_sync(0xffffffffu, mx1, 2));

        float a0 = 1.f, a1 = 1.f;
        if (mx0 > -INFINITY) {
            const float mn = fmaxf(m0, mx0);
            a0 = __expf(m0 - mn);
            m0 = mn;
        }
        if (mx1 > -INFINITY) {
            const float mn = fmaxf(m1, mx1);
            a1 = __expf(m1 - mn);
            m1 = mn;
        }
        const float mm0 = (m0 == -INFINITY) ? 0.f : m0;
        const float mm1 = (m1 == -INFINITY) ? 0.f : m1;

        // ---- p = exp(s-m) -> hi/lo smem P tiles ----
        const int pr0 = wid * 16 + (lane >> 2);
        const uint32_t pcolb = (uint32_t)((lane & 3) * 4);
        float sum0 = 0.f, sum1 = 0.f;
#pragma unroll
        for (int nt = 0; nt < 8; nt++) {
            const float p00 = __expf(s4[nt][0] - mm0);
            const float p01 = __expf(s4[nt][1] - mm0);
            const float p10 = __expf(s4[nt][2] - mm1);
            const float p11 = __expf(s4[nt][3] - mm1);
            sum0 += p00 + p01;
            sum1 += p10 + p11;
            const float h00 = __bfloat162float(__float2bfloat16(p00));
            const float h01 = __bfloat162float(__float2bfloat16(p01));
            const float h10 = __bfloat162float(__float2bfloat16(p10));
            const float h11 = __bfloat162float(__float2bfloat16(p11));
            const uint32_t bo0 = (uint32_t)(pr0 * 128 + nt * 16) + pcolb;
            const uint32_t bo1 = bo0 + 8 * 128;
            *(uint32_t*)(smc + SPHI + sw128(bo0)) = pack2(h00, h01);
            *(uint32_t*)(smc + SPHI + sw128(bo1)) = pack2(h10, h11);
            *(uint32_t*)(smc + SPLO + sw128(bo0)) = pack2(p00 - h00, p01 - h01);
            *(uint32_t*)(smc + SPLO + sw128(bo1)) = pack2(p10 - h10, p11 - h11);
        }
        sum0 += __shfl_xor_sync(0xffffffffu, sum0, 1);
        sum0 += __shfl_xor_sync(0xffffffffu, sum0, 2);
        sum1 += __shfl_xor_sync(0xffffffffu, sum1, 1);
        sum1 += __shfl_xor_sync(0xffffffffu, sum1, 2);
        l0 = l0 * a0 + sum0;
        l1 = l1 * a1 + sum1;

#pragma unroll
        for (int nt = 0; nt < 8; nt++) {
            acc[nt][0] *= a0; acc[nt][1] *= a0;
            acc[nt][2] *= a1; acc[nt][3] *= a1;
        }

        // V(kt) arrived (outstanding: K(kt+1)); barrier also publishes P tiles
        cp_wait<1>();
        __syncthreads();

        // ---- O += Phi*Vhi + Plo*Vhi + Phi*Vlo (fragment-reuse form) ----
#pragma unroll
        for (int ks = 0; ks < 4; ks++) {
            uint32_t aph[4], apl[4];
            {
                const int row = wid * 16 + (lane & 15);
                const uint32_t bo =
                    (uint32_t)(row * 128 + ks * 32 + ((lane >> 4) & 1) * 16);
                ldsm_x4(aph, sb + SPHI + sw128(bo));
                ldsm_x4(apl, sb + SPLO + sw128(bo));
            }
#pragma unroll
            for (int nt2 = 0; nt2 < 4; nt2++) {
                const int row = nt2 * 16 + ((lane >> 4) << 3) + (lane & 7);
                const uint32_t bo =
                    (uint32_t)(row * 128 + ks * 32 + ((lane >> 3) & 1) * 16);
                uint32_t tv[4];
                ldsm_x4(tv, sb + SVHI + sw128(bo));
                mma_bf16(acc[nt2 * 2 + 0], aph, tv);
                mma_bf16(acc[nt2 * 2 + 1], aph, tv + 2);
                mma_bf16(acc[nt2 * 2 + 0], apl, tv);
                mma_bf16(acc[nt2 * 2 + 1], apl, tv + 2);
                uint32_t tw[4];
                ldsm_x4(tw, sb + SVLO + sw128(bo));
                mma_bf16(acc[nt2 * 2 + 0], aph, tw);
                mma_bf16(acc[nt2 * 2 + 1], aph, tw + 2);
            }
        }

        __syncthreads();            // Vbuf fully consumed (and P tiles free)
        {                           // prefetch V(kt+1)
            const int jn = (kt + 1 < ntiles) ? j0 + 64 : 0;
            att_issue_tile(sb + SVHI, sb + SVLO,
                           vhB + jn, vlB + jn, TT, tid);
        }
    }

    // ---- epilogue: write proj A-operand layout (hi | lo | hi) directly ----
    const float inv0 = (l0 > 0.f) ? (1.f / l0) : 0.f;
    const float inv1 = (l1 > 0.f) ? (1.f / l1) : 0.f;
#pragma unroll
    for (int nt = 0; nt < 8; nt++) {
        const int col = hh * DK + nt * 8 + (lane & 3) * 2;
        {
            const float vx = acc[nt][0] * inv0, vy = acc[nt][1] * inv0;
            const float hx = __bfloat162float(__float2bfloat16(vx));
            const float hy = __bfloat162float(__float2bfloat16(vy));
            const size_t o = ((size_t)b * TT + r0g) * KSPLIT + col;
            const uint32_t hp = pack2(hx, hy);
            *(uint32_t*)(yp + o)        = hp;
            *(uint32_t*)(yp + o + 1024) = pack2(vx - hx, vy - hy);
            *(uint32_t*)(yp + o + 2048) = hp;
        }
        {
            const float vx = acc[nt][2] * inv1, vy = acc[nt][3] * inv1;
            const float hx = __bfloat162float(__float2bfloat16(vx));
            const float hy = __bfloat162float(__float2bfloat16(vy));
            const size_t o = ((size_t)b * TT + r1g) * KSPLIT + col;
            const uint32_t hp = pack2(hx, hy);
            *(uint32_t*)(yp + o)        = hp;
            *(uint32_t*)(yp + o + 1024) = pack2(vx - hx, vy - hy);
            *(uint32_t*)(yp + o + 2048) = hp;
        }
    }
}

// ---------------------------------------------------------------------------
extern "C" void kernel_launch(void* const* d_in, const int* in_sizes, int n_in,
                              void* d_out, int out_size)
{
    const float* x     = (const float*)d_in[0];
    const float* Wqkv  = (const float*)d_in[1];
    const float* bqkv  = (const float*)d_in[2];
    const float* Wproj = (const float*)d_in[3];
    const float* bproj = (const float*)d_in[4];
    const int*   mask  = (const int*)d_in[5];
    float* out = (float*)d_out;

    float *vp;
    __nv_bfloat16 *xpp, *wqp, *ypp, *wpp;
    __nv_bfloat16 *qhp, *qlp, *khp, *klp, *vhp, *vlp;
    cudaGetSymbolAddress((void**)&vp,   g_v);
    cudaGetSymbolAddress((void**)&xpp,  g_xp);
    cudaGetSymbolAddress((void**)&wqp,  g_wqkvp);
    cudaGetSymbolAddress((void**)&ypp,  g_yp);
    cudaGetSymbolAddress((void**)&wpp,  g_wprojp);
    cudaGetSymbolAddress((void**)&qhp,  g_qh);
    cudaGetSymbolAddress((void**)&qlp,  g_ql);
    cudaGetSymbolAddress((void**)&khp,  g_kh);
    cudaGetSymbolAddress((void**)&klp,  g_kl);
    cudaGetSymbolAddress((void**)&vhp,  g_vht);
    cudaGetSymbolAddress((void**)&vlp,  g_vlt);

    cudaFuncSetAttribute(gemm_bf16_mma<0>,
                         cudaFuncAttributeMaxDynamicSharedMemorySize, GEMM_SMEM);
    cudaFuncSetAttribute(gemm_bf16_mma<1>,
                         cudaFuncAttributeMaxDynamicSharedMemorySize, GEMM_SMEM);
    cudaFuncSetAttribute(attn_mma,
                         cudaFuncAttributeMaxDynamicSharedMemorySize, ATT2_SMEM);

    // input splits
    split_hilo<<<(MROWS * DD) / 256, 256>>>(x, xpp, MROWS * DD, 0);
    split_hilo<<<(3 * DD * DD) / 256, 256>>>(Wqkv, wqp, 3 * DD * DD, 1);
    split_hilo<<<(DD * DD) / 256, 256>>>(Wproj, wpp, DD * DD, 1);

    // qkv GEMM with fused q/k split + compact V
    gemm_bf16_mma<1><<<dim3(3 * DD / 128, MROWS / 128), 256, GEMM_SMEM>>>(
        xpp, wqp, bqkv, nullptr, MROWS, 3 * DD, KSPLIT);

    // V transpose + split
    v_split<<<dim3(TT / 128, HH, BB), 256>>>(vp, vhp, vlp);

    // attention -> g_yp (proj A-operand layout, fused)
    attn_mma<<<dim3(TT / 128, HH, BB), 256, ATT2_SMEM>>>(
        qhp, qlp, khp, klp, vhp, vlp, mask, ypp);

    // out = y @ Wproj^T + bproj
    gemm_bf16_mma<0><<<dim3(DD / 128, MROWS / 128), 256, GEMM_SMEM>>>(
        ypp, wpp, bproj, out, MROWS, DD, KSPLIT);
}

// round 12
// speedup vs baseline: 1.2403x; 1.0225x over previous
#include <cuda_runtime.h>
#include <cuda_bf16.h>
#include <cstdint>
#include <stdint.h>
#include <math.h>

// Problem constants (fixed by the reference)
#define BB 4
#define TT 2048
#define DD 1024
#define HH 16
#define DK 64
#define MROWS (BB * TT)          // 8192
#define KST 2048                 // stored K (hi|lo); virtual K' = 3072 via remap
#define NCHG 48                  // virtual K' / 64

// Scratch (allocation-free rule: __device__ globals)
__device__ float         g_v[(size_t)BB * HH * TT * DK];    // V fp32 [bh][t][d]
__device__ __nv_bfloat16 g_xp[(size_t)MROWS * KST];         // x  (hi|lo)
__device__ __nv_bfloat16 g_wqkvp[(size_t)(3 * DD) * KST];   // Wqkv (hi|lo)
__device__ __nv_bfloat16 g_yp[(size_t)MROWS * KST];         // y  (hi|lo)
__device__ __nv_bfloat16 g_wprojp[(size_t)DD * KST];        // Wproj (hi|lo)
// attention operand tensors, per (b,h):
__device__ __nv_bfloat16 g_qh[(size_t)BB * HH * TT * DK];   // Q hi  [bh][t][d]
__device__ __nv_bfloat16 g_ql[(size_t)BB * HH * TT * DK];   // Q lo
__device__ __nv_bfloat16 g_kh[(size_t)BB * HH * TT * DK];   // K hi
__device__ __nv_bfloat16 g_kl[(size_t)BB * HH * TT * DK];   // K lo
__device__ __nv_bfloat16 g_vht[(size_t)BB * HH * DK * TT];  // V^T hi [bh][d][t]
__device__ __nv_bfloat16 g_vlt[(size_t)BB * HH * DK * TT];  // V^T lo

// ---------------------------------------------------------------------------
// helpers (all baseline PTX — compiles on compute_103)
// ---------------------------------------------------------------------------
__device__ __forceinline__ uint32_t smem_u32(const void* p) {
    uint32_t a;
    asm("{ .reg .u64 t; cvta.to.shared.u64 t, %1; cvt.u32.u64 %0, t; }"
        : "=r"(a) : "l"(p));
    return a;
}
__device__ __forceinline__ void cp16(uint32_t saddr, const void* gaddr) {
    asm volatile("cp.async.cg.shared.global [%0], [%1], 16;"
                 :: "r"(saddr), "l"(gaddr) : "memory");
}
__device__ __forceinline__ void cp_commit() {
    asm volatile("cp.async.commit_group;" ::: "memory");
}
template <int N>
__device__ __forceinline__ void cp_wait() {
    asm volatile("cp.async.wait_group %0;" :: "n"(N) : "memory");
}
__device__ __forceinline__ void ldsm_x4(uint32_t* r, uint32_t addr) {
    asm volatile("ldmatrix.sync.aligned.m8n8.x4.shared.b16 {%0,%1,%2,%3}, [%4];"
                 : "=r"(r[0]), "=r"(r[1]), "=r"(r[2]), "=r"(r[3]) : "r"(addr));
}
__device__ __forceinline__ void mma_bf16(float* c, const uint32_t* a,
                                         const uint32_t* b) {
    asm volatile(
        "mma.sync.aligned.m16n8k16.row.col.f32.bf16.bf16.f32 "
        "{%0,%1,%2,%3}, {%4,%5,%6,%7}, {%8,%9}, {%0,%1,%2,%3};"
        : "+f"(c[0]), "+f"(c[1]), "+f"(c[2]), "+f"(c[3])
        : "r"(a[0]), "r"(a[1]), "r"(a[2]), "r"(a[3]), "r"(b[0]), "r"(b[1]));
}
__device__ __forceinline__ uint32_t sw128(uint32_t bo) {
    return bo ^ ((bo >> 3) & 0x70);
}
__device__ __forceinline__ uint32_t pack2(float a, float b) {
    __nv_bfloat162 t = __floats2bfloat162_rn(a, b);
    return *(uint32_t*)&t;
}
// virtual-chunk -> stored-chunk remap (A pattern hi,lo,hi ; B pattern hi,hi,lo)
__device__ __forceinline__ int kmapA(int c) { return c < 32 ? c : c - 32; }
__device__ __forceinline__ int kmapB(int c) { return c < 16 ? c : c - 16; }

#define GEMM_SMEM 98304   // 3 x (16KB A + 16KB B)

// ---------------------------------------------------------------------------
// Tensor-core GEMM via mma.sync: C = A(hi|lo) @ B(hi|lo)^T + bias, with the
// compensated-K' schedule applied through kmapA/kmapB (virtual K' = 3072).
// MODE 0: plain fp32 C[M,N].   MODE 1 (qkv): scatter epilogue.
// 128x128 CTA tile, 256 threads, warp 64x32, K-chunks of 64, 3-stage pipeline.
// ---------------------------------------------------------------------------
template <int MODE>
__global__ __launch_bounds__(256, 2)
void gemm_bf16_mma(const __nv_bfloat16* __restrict__ A,
                   const __nv_bfloat16* __restrict__ B,
                   const float* __restrict__ bias, float* __restrict__ C,
                   int M, int N)
{
    extern __shared__ char smc[];
    const uint32_t sb = smem_u32(smc);
    const int tid  = threadIdx.x;
    const int wid  = tid >> 5;
    const int lane = tid & 31;
    const int nb   = blockIdx.x * 128;
    const int mb   = blockIdx.y * 128;
    const int mw   = (wid >> 2) * 64;
    const int nw   = (wid & 3) * 32;

    const uint32_t sA = sb;             // 3 x 16KB
    const uint32_t sB = sb + 49152;     // 3 x 16KB

    float acc[4][4][4];
#pragma unroll
    for (int mt = 0; mt < 4; mt++)
#pragma unroll
        for (int nt = 0; nt < 4; nt++)
#pragma unroll
            for (int q = 0; q < 4; q++) acc[mt][nt][q] = 0.f;

    const int lrow = tid >> 3;
    const int lci  = tid & 7;
    const uint32_t lsw = sw128((uint32_t)(lrow * 128 + lci * 16));

    // prologue: issue chunks 0 and 1
#pragma unroll
    for (int c = 0; c < 2; c++) {
        const __nv_bfloat16* Ap = A + (size_t)mb * KST + (kmapA(c) << 6);
        const __nv_bfloat16* Bp = B + (size_t)nb * KST + (kmapB(c) << 6);
        const uint32_t sbuf = c * 16384;
#pragma unroll
        for (int i = 0; i < 4; i++) {
            const uint32_t so = sbuf + lsw + i * 4096;
            cp16(sA + so, Ap + (size_t)(lrow + i * 32) * KST + lci * 8);
            cp16(sB + so, Bp + (size_t)(lrow + i * 32) * KST + lci * 8);
        }
        cp_commit();
    }

    int s = 0;      // buffer of chunk c
    int sn = 2;     // buffer of chunk c+2
    for (int c = 0; c < NCHG; c++) {
        if (c + 2 < NCHG) {
            const __nv_bfloat16* Ap = A + (size_t)mb * KST + (kmapA(c + 2) << 6);
            const __nv_bfloat16* Bp = B + (size_t)nb * KST + (kmapB(c + 2) << 6);
            const uint32_t sbuf = sn * 16384;
#pragma unroll
            for (int i = 0; i < 4; i++) {
                const uint32_t so = sbuf + lsw + i * 4096;
                cp16(sA + so, Ap + (size_t)(lrow + i * 32) * KST + lci * 8);
                cp16(sB + so, Bp + (size_t)(lrow + i * 32) * KST + lci * 8);
            }
            cp_commit();
            cp_wait<2>();
        } else if (c + 1 < NCHG) {
            cp_wait<1>();
        } else {
            cp_wait<0>();
        }
        __syncthreads();

        const uint32_t baseA = sA + s * 16384;
        const uint32_t baseB = sB + s * 16384;
#pragma unroll
        for (int ks = 0; ks < 4; ks++) {
            uint32_t af[4][4];
#pragma unroll
            for (int mt = 0; mt < 4; mt++) {
                const int row = mw + mt * 16 + (lane & 15);
                const uint32_t bo =
                    (uint32_t)(row * 128 + ks * 32 + ((lane >> 4) & 1) * 16);
                ldsm_x4(af[mt], baseA + sw128(bo));
            }
            uint32_t bf[4][2];
#pragma unroll
            for (int nt2 = 0; nt2 < 2; nt2++) {
                const int row = nw + nt2 * 16 + ((lane >> 4) << 3) + (lane & 7);
                const uint32_t bo =
                    (uint32_t)(row * 128 + ks * 32 + ((lane >> 3) & 1) * 16);
                uint32_t t[4];
                ldsm_x4(t, baseB + sw128(bo));
                bf[nt2 * 2 + 0][0] = t[0]; bf[nt2 * 2 + 0][1] = t[1];
                bf[nt2 * 2 + 1][0] = t[2]; bf[nt2 * 2 + 1][1] = t[3];
            }
#pragma unroll
            for (int mt = 0; mt < 4; mt++)
#pragma unroll
                for (int nt = 0; nt < 4; nt++)
                    mma_bf16(acc[mt][nt], af[mt], bf[nt]);
        }
        __syncthreads();
        s  = (s  == 2) ? 0 : s + 1;
        sn = (sn == 2) ? 0 : sn + 1;
    }

    const int r0 = mb + mw + (lane >> 2);
    const int c0 = nb + nw + (lane & 3) * 2;

    if (MODE == 0) {
#pragma unroll
        for (int mt = 0; mt < 4; mt++) {
#pragma unroll
            for (int nt = 0; nt < 4; nt++) {
                const int col = c0 + nt * 8;
                const float bx = bias[col], by = bias[col + 1];
                float2 v0 = make_float2(acc[mt][nt][0] + bx, acc[mt][nt][1] + by);
                float2 v1 = make_float2(acc[mt][nt][2] + bx, acc[mt][nt][3] + by);
                *(float2*)(C + (size_t)(r0 + mt * 16) * N + col)     = v0;
                *(float2*)(C + (size_t)(r0 + mt * 16 + 8) * N + col) = v1;
            }
        }
    } else {
        // qkv epilogue: scatter into attention operand layouts
#pragma unroll
        for (int nt = 0; nt < 4; nt++) {
            const int col = c0 + nt * 8;
            const int src = col >> 10;          // 0=q, 1=k, 2=v (warp-uniform)
            const int cc  = col & 1023;
            const int h   = cc >> 6;
            const int d   = cc & 63;
            const float bx = bias[col], by = bias[col + 1];
#pragma unroll
            for (int mt = 0; mt < 4; mt++) {
#pragma unroll
                for (int half = 0; half < 2; half++) {
                    const int r = r0 + mt * 16 + half * 8;
                    const float vx = acc[mt][nt][half * 2 + 0] + bx;
                    const float vy = acc[mt][nt][half * 2 + 1] + by;
                    const int bsel = r >> 11;
                    const int t    = r & 2047;
                    const size_t o =
                        ((size_t)(bsel * HH + h) * TT + t) * DK + d;
                    if (src == 2) {
                        *(float2*)(g_v + o) = make_float2(vx, vy);
                    } else {
                        const float hx = __bfloat162float(__float2bfloat16(vx));
                        const float hy = __bfloat162float(__float2bfloat16(vy));
                        if (src == 0) {
                            *(uint32_t*)(g_qh + o) = pack2(hx, hy);
                            *(uint32_t*)(g_ql + o) = pack2(vx - hx, vy - hy);
                        } else {
                            *(uint32_t*)(g_kh + o) = pack2(hx, hy);
                            *(uint32_t*)(g_kl + o) = pack2(vx - hx, vy - hy);
                        }
                    }
                }
            }
        }
    }
}

// ---------------------------------------------------------------------------
// Split fp32 [R,1024] -> (hi | lo) bf16 [R,2048]
// ---------------------------------------------------------------------------
__global__ __launch_bounds__(256)
void split_hilo(const float* __restrict__ in, __nv_bfloat16* __restrict__ out,
                int total)
{
    int idx = blockIdx.x * 256 + threadIdx.x;
    if (idx >= total) return;
    const int r = idx >> 10;
    const int k = idx & 1023;
    const float x = in[idx];
    const __nv_bfloat16 h = __float2bfloat16(x);
    const __nv_bfloat16 l = __float2bfloat16(x - __bfloat162float(h));
    const size_t o = (size_t)r * KST + k;
    out[o] = h; out[o + 1024] = l;
}

// ---------------------------------------------------------------------------
// V transpose + split: g_v [bh][t][64] fp32 -> V^T hi/lo [bh][d][t].
// ---------------------------------------------------------------------------
__global__ __launch_bounds__(256)
void v_split(const float* __restrict__ v,
             __nv_bfloat16* __restrict__ vht, __nv_bfloat16* __restrict__ vlt)
{
    __shared__ float tile[128][65];
    const int tid = threadIdx.x;
    const int t0  = blockIdx.x * 128;
    const int h   = blockIdx.y;
    const int b   = blockIdx.z;
    const int bh  = b * HH + h;

#pragma unroll
    for (int i = 0; i < 8; i++) {
        const int s   = tid + i * 256;
        const int row = s >> 4;
        const int c4  = (s & 15) * 4;
        float4 vv = *(const float4*)(v + ((size_t)bh * TT + t0 + row) * DK + c4);
        tile[row][c4 + 0] = vv.x; tile[row][c4 + 1] = vv.y;
        tile[row][c4 + 2] = vv.z; tile[row][c4 + 3] = vv.w;
    }
    __syncthreads();

    const int wid  = tid >> 5;
    const int lane = tid & 31;
#pragma unroll
    for (int r = 0; r < 8; r++) {
        const int d = wid * 8 + r;
        uint32_t* oh = (uint32_t*)(vht + ((size_t)bh * DK + d) * TT + t0);
        uint32_t* ol = (uint32_t*)(vlt + ((size_t)bh * DK + d) * TT + t0);
#pragma unroll
        for (int it = 0; it < 2; it++) {
            const int tt = (lane + it * 32) * 2;
            const float v0 = tile[tt][d], v1 = tile[tt + 1][d];
            const float h0 = __bfloat162float(__float2bfloat16(v0));
            const float h1 = __bfloat162float(__float2bfloat16(v1));
            oh[lane + it * 32] = pack2(h0, h1);
            ol[lane + it * 32] = pack2(v0 - h0, v1 - h1);
        }
    }
}

// ---------------------------------------------------------------------------
// Flash attention on tensor cores (compensated bf16), software-pipelined,
// 3 barriers per key tile. Mask read directly from gmem (L1-cached).
// ---------------------------------------------------------------------------
#define SQHI 0
#define SQLO 16384
#define SKHI 32768
#define SKLO 40960
#define SVHI 49152
#define SVLO 57344
#define SPHI 65536
#define SPLO 81920
#define ATT2_SMEM 98304

// issue one 64-row hi/lo tile pair (8KB each) as ONE commit group
__device__ __forceinline__ void att_issue_tile(
    uint32_t dst_hi, uint32_t dst_lo,
    const __nv_bfloat16* __restrict__ hp, const __nv_bfloat16* __restrict__ lp,
    size_t rstride, int tid)
{
#pragma unroll
    for (int i = 0; i < 2; i++) {
        const int s   = tid + i * 256;
        const int row = s >> 3;
        const int ci  = s & 7;
        const uint32_t sw = sw128((uint32_t)(row * 128 + ci * 16));
        cp16(dst_hi + sw, hp + (size_t)row * rstride + ci * 8);
        cp16(dst_lo + sw, lp + (size_t)row * rstride + ci * 8);
    }
    cp_commit();
}

__global__ __launch_bounds__(256)
void attn_mma(const __nv_bfloat16* __restrict__ qh,
              const __nv_bfloat16* __restrict__ ql,
              const __nv_bfloat16* __restrict__ kh,
              const __nv_bfloat16* __restrict__ kl,
              const __nv_bfloat16* __restrict__ vht,
              const __nv_bfloat16* __restrict__ vlt,
              const int* __restrict__ mask,
              __nv_bfloat16* __restrict__ yp)
{
    extern __shared__ char smc[];
    const uint32_t sb = smem_u32(smc);

    const int tid  = threadIdx.x;
    const int wid  = tid >> 5;
    const int lane = tid & 31;
    const int bx   = gridDim.x - 1 - blockIdx.x;   // heavy blocks first
    const int b    = blockIdx.z;
    const int hh   = blockIdx.y;
    const int bh   = b * HH + hh;
    const int qb   = bx * 128;

    const __nv_bfloat16* khB = kh + (size_t)bh * TT * DK;
    const __nv_bfloat16* klB = kl + (size_t)bh * TT * DK;
    const __nv_bfloat16* vhB = vht + (size_t)bh * DK * TT;
    const __nv_bfloat16* vlB = vlt + (size_t)bh * DK * TT;
    const int* maskB = mask + b * TT;

    // ---- group 1: Q (hi & lo) ----
    {
        const __nv_bfloat16* qhp = qh + ((size_t)bh * TT + qb) * DK;
        const __nv_bfloat16* qlp = ql + ((size_t)bh * TT + qb) * DK;
#pragma unroll
        for (int i = 0; i < 4; i++) {
            const int s   = tid + i * 256;
            const int row = s >> 3;
            const int ci  = s & 7;
            const uint32_t sw = sw128((uint32_t)(row * 128 + ci * 16));
            cp16(sb + SQHI + sw, qhp + (size_t)row * DK + ci * 8);
            cp16(sb + SQLO + sw, qlp + (size_t)row * DK + ci * 8);
        }
        cp_commit();
    }
    // ---- group 2: K(0), group 3: V(0) ----
    att_issue_tile(sb + SKHI, sb + SKLO, khB, klB, DK, tid);
    att_issue_tile(sb + SVHI, sb + SVLO, vhB, vlB, TT, tid);

    float acc[8][4];
#pragma unroll
    for (int nt = 0; nt < 8; nt++)
#pragma unroll
        for (int q = 0; q < 4; q++) acc[nt][q] = 0.f;
    float m0 = -INFINITY, m1 = -INFINITY, l0 = 0.f, l1 = 0.f;

    const int r0g = qb + wid * 16 + (lane >> 2);
    const int r1g = r0g + 8;

    const int ntiles = 2 * bx + 2;
    for (int kt = 0; kt < ntiles; kt++) {
        const int j0 = kt * 64;

        // K(kt) arrived (V(kt) may still be in flight)
        cp_wait<1>();
        __syncthreads();                     // sync A

        // ---- S = Qhi*Khi + Qlo*Khi + Qhi*Klo (fragment-reuse form) ----
        float s4[8][4];
#pragma unroll
        for (int nt = 0; nt < 8; nt++)
#pragma unroll
            for (int q = 0; q < 4; q++) s4[nt][q] = 0.f;

#pragma unroll
        for (int ks = 0; ks < 4; ks++) {
            uint32_t aqh[4], aql[4];
            {
                const int row = wid * 16 + (lane & 15);
                const uint32_t bo =
                    (uint32_t)(row * 128 + ks * 32 + ((lane >> 4) & 1) * 16);
                ldsm_x4(aqh, sb + SQHI + sw128(bo));
                ldsm_x4(aql, sb + SQLO + sw128(bo));
            }
#pragma unroll
            for (int nt2 = 0; nt2 < 4; nt2++) {
                const int row = nt2 * 16 + ((lane >> 4) << 3) + (lane & 7);
                const uint32_t bo =
                    (uint32_t)(row * 128 + ks * 32 + ((lane >> 3) & 1) * 16);
                uint32_t tk[4];
                ldsm_x4(tk, sb + SKHI + sw128(bo));
                mma_bf16(s4[nt2 * 2 + 0], aqh, tk);
                mma_bf16(s4[nt2 * 2 + 1], aqh, tk + 2);
                mma_bf16(s4[nt2 * 2 + 0], aql, tk);
                mma_bf16(s4[nt2 * 2 + 1], aql, tk + 2);
                uint32_t tl[4];
                ldsm_x4(tl, sb + SKLO + sw128(bo));
                mma_bf16(s4[nt2 * 2 + 0], aqh, tl);
                mma_bf16(s4[nt2 * 2 + 1], aqh, tl + 2);
            }
        }

        // ---- mask + scale (mask straight from gmem; all-ones fast in L1) ----
#pragma unroll
        for (int nt = 0; nt < 8; nt++) {
            const int c0 = nt * 8 + (lane & 3) * 2;
            const bool p0 = maskB[j0 + c0] != 0;
            const bool p1 = maskB[j0 + c0 + 1] != 0;
            const int jg0 = j0 + c0, jg1 = jg0 + 1;
            s4[nt][0] = (p0 && jg0 <= r0g) ? s4[nt][0] * 0.125f : -INFINITY;
            s4[nt][1] = (p1 && jg1 <= r0g) ? s4[nt][1] * 0.125f : -INFINITY;
            s4[nt][2] = (p0 && jg0 <= r1g) ? s4[nt][2] * 0.125f : -INFINITY;
            s4[nt][3] = (p1 && jg1 <= r1g) ? s4[nt][3] * 0.125f : -INFINITY;
        }

        // ---- online softmax ----
        float mx0 = -INFINITY, mx1 = -INFINITY;
#pragma unroll
        for (int nt = 0; nt < 8; nt++) {
            mx0 = fmaxf(mx0, fmaxf(s4[nt][0], s4[nt][1]));
            mx1 = fmaxf(mx1, fmaxf(s4[nt][2], s4[nt][3]));
        }
        mx0 = fmaxf(mx0, __shfl_xor_sync(0xffffffffu, mx0, 1));
        mx0 = fmaxf(mx0, __shfl_xor_sync(0xffffffffu, mx0, 2));
        mx1 = fmaxf(mx1, __shfl_xor_sync(0xffffffffu, mx1, 1));
        mx1 = fmaxf(mx1, __shfl_xor_sync(0xffffffffu, mx1, 2));

        float a0 = 1.f, a1 = 1.f;
        if (mx0 > -INFINITY) {
            const float mn = fmaxf(m0, mx0);
            a0 = __expf(m0 - mn);
            m0 = mn;
        }
        if (mx1 > -INFINITY) {
            const float mn = fmaxf(m1, mx1);
            a1 = __expf(m1 - mn);
            m1 = mn;
        }
        const float mm0 = (m0 == -INFINITY) ? 0.f : m0;
        const float mm1 = (m1 == -INFINITY) ? 0.f : m1;

        // ---- p = exp(s-m) -> hi/lo smem P tiles ----
        const int pr0 = wid * 16 + (lane >> 2);
        const uint32_t pcolb = (uint32_t)((lane & 3) * 4);
        float sum0 = 0.f, sum1 = 0.f;
#pragma unroll
        for (int nt = 0; nt < 8; nt++) {
            const float p00 = __expf(s4[nt][0] - mm0);
            const float p01 = __expf(s4[nt][1] - mm0);
            const float p10 = __expf(s4[nt][2] - mm1);
            const float p11 = __expf(s4[nt][3] - mm1);
            sum0 += p00 + p01;
            sum1 += p10 + p11;
            const float h00 = __bfloat162float(__float2bfloat16(p00));
            const float h01 = __bfloat162float(__float2bfloat16(p01));
            const float h10 = __bfloat162float(__float2bfloat16(p10));
            const float h11 = __bfloat162float(__float2bfloat16(p11));
            const uint32_t bo0 = (uint32_t)(pr0 * 128 + nt * 16) + pcolb;
            const uint32_t bo1 = bo0 + 8 * 128;
            *(uint32_t*)(smc + SPHI + sw128(bo0)) = pack2(h00, h01);
            *(uint32_t*)(smc + SPHI + sw128(bo1)) = pack2(h10, h11);
            *(uint32_t*)(smc + SPLO + sw128(bo0)) = pack2(p00 - h00, p01 - h01);
            *(uint32_t*)(smc + SPLO + sw128(bo1)) = pack2(p10 - h10, p11 - h11);
        }
        sum0 += __shfl_xor_sync(0xffffffffu, sum0, 1);
        sum0 += __shfl_xor_sync(0xffffffffu, sum0, 2);
        sum1 += __shfl_xor_sync(0xffffffffu, sum1, 1);
        sum1 += __shfl_xor_sync(0xffffffffu, sum1, 2);
        l0 = l0 * a0 + sum0;
        l1 = l1 * a1 + sum1;

#pragma unroll
        for (int nt = 0; nt < 8; nt++) {
            acc[nt][0] *= a0; acc[nt][1] *= a0;
            acc[nt][2] *= a1; acc[nt][3] *= a1;
        }

        // V(kt) ready + P published + K consumed by all warps
        cp_wait<0>();
        __syncthreads();                     // sync C
        {                                    // prefetch K(kt+1) — covers PV
            const int jn = (kt + 1 < ntiles) ? j0 + 64 : 0;
            att_issue_tile(sb + SKHI, sb + SKLO,
                           khB + (size_t)jn * DK, klB + (size_t)jn * DK, DK, tid);
        }

        // ---- O += Phi*Vhi + Plo*Vhi + Phi*Vlo (fragment-reuse form) ----
#pragma unroll
        for (int ks = 0; ks < 4; ks++) {
            uint32_t aph[4], apl[4];
            {
                const int row = wid * 16 + (lane & 15);
                const uint32_t bo =
                    (uint32_t)(row * 128 + ks * 32 + ((lane >> 4) & 1) * 16);
                ldsm_x4(aph, sb + SPHI + sw128(bo));
                ldsm_x4(apl, sb + SPLO + sw128(bo));
            }
#pragma unroll
            for (int nt2 = 0; nt2 < 4; nt2++) {
                const int row = nt2 * 16 + ((lane >> 4) << 3) + (lane & 7);
                const uint32_t bo =
                    (uint32_t)(row * 128 + ks * 32 + ((lane >> 3) & 1) * 16);
                uint32_t tv[4];
                ldsm_x4(tv, sb + SVHI + sw128(bo));
                mma_bf16(acc[nt2 * 2 + 0], aph, tv);
                mma_bf16(acc[nt2 * 2 + 1], aph, tv + 2);
                mma_bf16(acc[nt2 * 2 + 0], apl, tv);
                mma_bf16(acc[nt2 * 2 + 1], apl, tv + 2);
                uint32_t tw[4];
                ldsm_x4(tw, sb + SVLO + sw128(bo));
                mma_bf16(acc[nt2 * 2 + 0], aph, tw);
                mma_bf16(acc[nt2 * 2 + 1], aph, tw + 2);
            }
        }

        __syncthreads();                     // sync D: V + P consumed
        {                                    // prefetch V(kt+1)
            const int jn = (kt + 1 < ntiles) ? j0 + 64 : 0;
            att_issue_tile(sb + SVHI, sb + SVLO,
                           vhB + jn, vlB + jn, TT, tid);
        }
    }

    // ---- epilogue: write proj A-operand (hi | lo) layout directly ----
    const float inv0 = (l0 > 0.f) ? (1.f / l0) : 0.f;
    const float inv1 = (l1 > 0.f) ? (1.f / l1) : 0.f;
#pragma unroll
    for (int nt = 0; nt < 8; nt++) {
        const int col = hh * DK + nt * 8 + (lane & 3) * 2;
        {
            const float vx = acc[nt][0] * inv0, vy = acc[nt][1] * inv0;
            const float hx = __bfloat162float(__float2bfloat16(vx));
            const float hy = __bfloat162float(__float2bfloat16(vy));
            const size_t o = ((size_t)b * TT + r0g) * KST + col;
            *(uint32_t*)(yp + o)        = pack2(hx, hy);
            *(uint32_t*)(yp + o + 1024) = pack2(vx - hx, vy - hy);
        }
        {
            const float vx = acc[nt][2] * inv1, vy = acc[nt][3] * inv1;
            const float hx = __bfloat162float(__float2bfloat16(vx));
            const float hy = __bfloat162float(__float2bfloat16(vy));
            const size_t o = ((size_t)b * TT + r1g) * KST + col;
            *(uint32_t*)(yp + o)        = pack2(hx, hy);
            *(uint32_t*)(yp + o + 1024) = pack2(vx - hx, vy - hy);
        }
    }
}

// ---------------------------------------------------------------------------
extern "C" void kernel_launch(void* const* d_in, const int* in_sizes, int n_in,
                              void* d_out, int out_size)
{
    const float* x     = (const float*)d_in[0];
    const float* Wqkv  = (const float*)d_in[1];
    const float* bqkv  = (const float*)d_in[2];
    const float* Wproj = (const float*)d_in[3];
    const float* bproj = (const float*)d_in[4];
    const int*   mask  = (const int*)d_in[5];
    float* out = (float*)d_out;

    float *vp;
    __nv_bfloat16 *xpp, *wqp, *ypp, *wpp;
    __nv_bfloat16 *qhp, *qlp, *khp, *klp, *vhp, *vlp;
    cudaGetSymbolAddress((void**)&vp,   g_v);
    cudaGetSymbolAddress((void**)&xpp,  g_xp);
    cudaGetSymbolAddress((void**)&wqp,  g_wqkvp);
    cudaGetSymbolAddress((void**)&ypp,  g_yp);
    cudaGetSymbolAddress((void**)&wpp,  g_wprojp);
    cudaGetSymbolAddress((void**)&qhp,  g_qh);
    cudaGetSymbolAddress((void**)&qlp,  g_ql);
    cudaGetSymbolAddress((void**)&khp,  g_kh);
    cudaGetSymbolAddress((void**)&klp,  g_kl);
    cudaGetSymbolAddress((void**)&vhp,  g_vht);
    cudaGetSymbolAddress((void**)&vlp,  g_vlt);

    cudaFuncSetAttribute(gemm_bf16_mma<0>,
                         cudaFuncAttributeMaxDynamicSharedMemorySize, GEMM_SMEM);
    cudaFuncSetAttribute(gemm_bf16_mma<1>,
                         cudaFuncAttributeMaxDynamicSharedMemorySize, GEMM_SMEM);
    cudaFuncSetAttribute(attn_mma,
                         cudaFuncAttributeMaxDynamicSharedMemorySize, ATT2_SMEM);

    // input splits (hi|lo)
    split_hilo<<<(MROWS * DD) / 256, 256>>>(x, xpp, MROWS * DD);
    split_hilo<<<(3 * DD * DD) / 256, 256>>>(Wqkv, wqp, 3 * DD * DD);
    split_hilo<<<(DD * DD) / 256, 256>>>(Wproj, wpp, DD * DD);

    // qkv GEMM with fused q/k split + compact V
    gemm_bf16_mma<1><<<dim3(3 * DD / 128, MROWS / 128), 256, GEMM_SMEM>>>(
        xpp, wqp, bqkv, nullptr, MROWS, 3 * DD);

    // V transpose + split
    v_split<<<dim3(TT / 128, HH, BB), 256>>>(vp, vhp, vlp);

    // attention -> g_yp (proj A-operand layout, fused)
    attn_mma<<<dim3(TT / 128, HH, BB), 256, ATT2_SMEM>>>(
        qhp, qlp, khp, klp, vhp, vlp, mask, ypp);

    // out = y @ Wproj^T + bproj
    gemm_bf16_mma<0><<<dim3(DD / 128, MROWS / 128), 256, GEMM_SMEM>>>(
        ypp, wpp, bproj, out, MROWS, DD);
}

// round 15
// speedup vs baseline: 1.2672x; 1.0217x over previous
#include <cuda_runtime.h>
#include <cuda_bf16.h>
#include <cstdint>
#include <stdint.h>
#include <math.h>

// Problem constants (fixed by the reference)
#define BB 4
#define TT 2048
#define DD 1024
#define HH 16
#define DK 64
#define MROWS (BB * TT)          // 8192
#define KST 2048                 // stored K (hi|lo); virtual K' = 3072 via remap
#define NCHG 48                  // virtual K' / 64

// Scratch (allocation-free rule: __device__ globals)
__device__ float         g_v[(size_t)BB * HH * TT * DK];    // V fp32 [bh][t][d]
__device__ __nv_bfloat16 g_xp[(size_t)MROWS * KST];         // x  (hi|lo)
__device__ __nv_bfloat16 g_wqkvp[(size_t)(3 * DD) * KST];   // Wqkv (hi|lo)
__device__ __nv_bfloat16 g_yp[(size_t)MROWS * KST];         // y  (hi|lo)
__device__ __nv_bfloat16 g_wprojp[(size_t)DD * KST];        // Wproj (hi|lo)
// attention operand tensors, per (b,h):
__device__ __nv_bfloat16 g_qh[(size_t)BB * HH * TT * DK];   // Q hi  [bh][t][d]
__device__ __nv_bfloat16 g_ql[(size_t)BB * HH * TT * DK];   // Q lo
__device__ __nv_bfloat16 g_kh[(size_t)BB * HH * TT * DK];   // K hi
__device__ __nv_bfloat16 g_kl[(size_t)BB * HH * TT * DK];   // K lo
__device__ __nv_bfloat16 g_vht[(size_t)BB * HH * DK * TT];  // V^T hi [bh][d][t]
__device__ __nv_bfloat16 g_vlt[(size_t)BB * HH * DK * TT];  // V^T lo

// ---------------------------------------------------------------------------
// helpers (all baseline PTX — compiles on compute_103)
// ---------------------------------------------------------------------------
__device__ __forceinline__ uint32_t smem_u32(const void* p) {
    uint32_t a;
    asm("{ .reg .u64 t; cvta.to.shared.u64 t, %1; cvt.u32.u64 %0, t; }"
        : "=r"(a) : "l"(p));
    return a;
}
__device__ __forceinline__ void cp16(uint32_t saddr, const void* gaddr) {
    asm volatile("cp.async.cg.shared.global [%0], [%1], 16;"
                 :: "r"(saddr), "l"(gaddr) : "memory");
}
__device__ __forceinline__ void cp_commit() {
    asm volatile("cp.async.commit_group;" ::: "memory");
}
template <int N>
__device__ __forceinline__ void cp_wait() {
    asm volatile("cp.async.wait_group %0;" :: "n"(N) : "memory");
}
__device__ __forceinline__ void ldsm_x4(uint32_t* r, uint32_t addr) {
    asm volatile("ldmatrix.sync.aligned.m8n8.x4.shared.b16 {%0,%1,%2,%3}, [%4];"
                 : "=r"(r[0]), "=r"(r[1]), "=r"(r[2]), "=r"(r[3]) : "r"(addr));
}
__device__ __forceinline__ void mma_bf16(float* c, const uint32_t* a,
                                         const uint32_t* b) {
    asm volatile(
        "mma.sync.aligned.m16n8k16.row.col.f32.bf16.bf16.f32 "
        "{%0,%1,%2,%3}, {%4,%5,%6,%7}, {%8,%9}, {%0,%1,%2,%3};"
        : "+f"(c[0]), "+f"(c[1]), "+f"(c[2]), "+f"(c[3])
        : "r"(a[0]), "r"(a[1]), "r"(a[2]), "r"(a[3]), "r"(b[0]), "r"(b[1]));
}
__device__ __forceinline__ uint32_t sw128(uint32_t bo) {
    return bo ^ ((bo >> 3) & 0x70);
}
__device__ __forceinline__ uint32_t pack2(float a, float b) {
    __nv_bfloat162 t = __floats2bfloat162_rn(a, b);
    return *(uint32_t*)&t;
}
// virtual-chunk -> stored-chunk remap (A pattern hi,lo,hi ; B pattern hi,hi,lo)
__device__ __forceinline__ int kmapA(int c) { return c < 32 ? c : c - 32; }
__device__ __forceinline__ int kmapB(int c) { return c < 16 ? c : c - 16; }

#define GEMM_SMEM 98304   // 3 x (16KB A + 16KB B)

// ---------------------------------------------------------------------------
// Tensor-core GEMM via mma.sync: C = A(hi|lo) @ B(hi|lo)^T + bias, with the
// compensated-K' schedule applied through kmapA/kmapB (virtual K' = 3072).
// MODE 0: plain fp32 C[M,N].   MODE 1 (qkv): scatter epilogue.
// 128x128 CTA tile, 256 threads, warp 64x32, K-chunks of 64, 3-stage
// pipeline. R12-verified sync structure: cp_wait -> sync -> compute -> sync.
// ---------------------------------------------------------------------------
template <int MODE>
__global__ __launch_bounds__(256, 2)
void gemm_bf16_mma(const __nv_bfloat16* __restrict__ A,
                   const __nv_bfloat16* __restrict__ B,
                   const float* __restrict__ bias, float* __restrict__ C,
                   int M, int N)
{
    extern __shared__ char smc[];
    const uint32_t sb = smem_u32(smc);
    const int tid  = threadIdx.x;
    const int wid  = tid >> 5;
    const int lane = tid & 31;
    const int nb   = blockIdx.x * 128;
    const int mb   = blockIdx.y * 128;
    const int mw   = (wid >> 2) * 64;
    const int nw   = (wid & 3) * 32;

    const uint32_t sA = sb;             // 3 x 16KB
    const uint32_t sB = sb + 49152;     // 3 x 16KB

    float acc[4][4][4];
#pragma unroll
    for (int mt = 0; mt < 4; mt++)
#pragma unroll
        for (int nt = 0; nt < 4; nt++)
#pragma unroll
            for (int q = 0; q < 4; q++) acc[mt][nt][q] = 0.f;

    const int lrow = tid >> 3;
    const int lci  = tid & 7;
    const uint32_t lsw = sw128((uint32_t)(lrow * 128 + lci * 16));

    // prologue: issue chunks 0 and 1
#pragma unroll
    for (int c = 0; c < 2; c++) {
        const __nv_bfloat16* Ap = A + (size_t)mb * KST + (kmapA(c) << 6);
        const __nv_bfloat16* Bp = B + (size_t)nb * KST + (kmapB(c) << 6);
        const uint32_t sbuf = c * 16384;
#pragma unroll
        for (int i = 0; i < 4; i++) {
            const uint32_t so = sbuf + lsw + i * 4096;
            cp16(sA + so, Ap + (size_t)(lrow + i * 32) * KST + lci * 8);
            cp16(sB + so, Bp + (size_t)(lrow + i * 32) * KST + lci * 8);
        }
        cp_commit();
    }

    int s = 0;      // buffer of chunk c
    int sn = 2;     // buffer of chunk c+2
    for (int c = 0; c < NCHG; c++) {
        if (c + 2 < NCHG) {
            const __nv_bfloat16* Ap = A + (size_t)mb * KST + (kmapA(c + 2) << 6);
            const __nv_bfloat16* Bp = B + (size_t)nb * KST + (kmapB(c + 2) << 6);
            const uint32_t sbuf = sn * 16384;
#pragma unroll
            for (int i = 0; i < 4; i++) {
                const uint32_t so = sbuf + lsw + i * 4096;
                cp16(sA + so, Ap + (size_t)(lrow + i * 32) * KST + lci * 8);
                cp16(sB + so, Bp + (size_t)(lrow + i * 32) * KST + lci * 8);
            }
            cp_commit();
            cp_wait<2>();
        } else if (c + 1 < NCHG) {
            cp_wait<1>();
        } else {
            cp_wait<0>();
        }
        __syncthreads();            // all threads' chunk-c data visible

        const uint32_t baseA = sA + s * 16384;
        const uint32_t baseB = sB + s * 16384;
#pragma unroll
        for (int ks = 0; ks < 4; ks++) {
            uint32_t af[4][4];
#pragma unroll
            for (int mt = 0; mt < 4; mt++) {
                const int row = mw + mt * 16 + (lane & 15);
                const uint32_t bo =
                    (uint32_t)(row * 128 + ks * 32 + ((lane >> 4) & 1) * 16);
                ldsm_x4(af[mt], baseA + sw128(bo));
            }
            uint32_t bf[4][2];
#pragma unroll
            for (int nt2 = 0; nt2 < 2; nt2++) {
                const int row = nw + nt2 * 16 + ((lane >> 4) << 3) + (lane & 7);
                const uint32_t bo =
                    (uint32_t)(row * 128 + ks * 32 + ((lane >> 3) & 1) * 16);
                uint32_t t[4];
                ldsm_x4(t, baseB + sw128(bo));
                bf[nt2 * 2 + 0][0] = t[0]; bf[nt2 * 2 + 0][1] = t[1];
                bf[nt2 * 2 + 1][0] = t[2]; bf[nt2 * 2 + 1][1] = t[3];
            }
#pragma unroll
            for (int mt = 0; mt < 4; mt++)
#pragma unroll
                for (int nt = 0; nt < 4; nt++)
                    mma_bf16(acc[mt][nt], af[mt], bf[nt]);
        }
        __syncthreads();            // chunk-c buffer free for reuse
        s  = (s  == 2) ? 0 : s + 1;
        sn = (sn == 2) ? 0 : sn + 1;
    }

    const int r0 = mb + mw + (lane >> 2);
    const int c0 = nb + nw + (lane & 3) * 2;

    if (MODE == 0) {
#pragma unroll
        for (int mt = 0; mt < 4; mt++) {
#pragma unroll
            for (int nt = 0; nt < 4; nt++) {
                const int col = c0 + nt * 8;
                const float bx = bias[col], by = bias[col + 1];
                float2 v0 = make_float2(acc[mt][nt][0] + bx, acc[mt][nt][1] + by);
                float2 v1 = make_float2(acc[mt][nt][2] + bx, acc[mt][nt][3] + by);
                *(float2*)(C + (size_t)(r0 + mt * 16) * N + col)     = v0;
                *(float2*)(C + (size_t)(r0 + mt * 16 + 8) * N + col) = v1;
            }
        }
    } else {
        // qkv epilogue: scatter into attention operand layouts
#pragma unroll
        for (int nt = 0; nt < 4; nt++) {
            const int col = c0 + nt * 8;
            const int src = col >> 10;          // 0=q, 1=k, 2=v (warp-uniform)
            const int cc  = col & 1023;
            const int h   = cc >> 6;
            const int d   = cc & 63;
            const float bx = bias[col], by = bias[col + 1];
#pragma unroll
            for (int mt = 0; mt < 4; mt++) {
#pragma unroll
                for (int half = 0; half < 2; half++) {
                    const int r = r0 + mt * 16 + half * 8;
                    const float vx = acc[mt][nt][half * 2 + 0] + bx;
                    const float vy = acc[mt][nt][half * 2 + 1] + by;
                    const int bsel = r >> 11;
                    const int t    = r & 2047;
                    const size_t o =
                        ((size_t)(bsel * HH + h) * TT + t) * DK + d;
                    if (src == 2) {
                        *(float2*)(g_v + o) = make_float2(vx, vy);
                    } else {
                        const float hx = __bfloat162float(__float2bfloat16(vx));
                        const float hy = __bfloat162float(__float2bfloat16(vy));
                        if (src == 0) {
                            *(uint32_t*)(g_qh + o) = pack2(hx, hy);
                            *(uint32_t*)(g_ql + o) = pack2(vx - hx, vy - hy);
                        } else {
                            *(uint32_t*)(g_kh + o) = pack2(hx, hy);
                            *(uint32_t*)(g_kl + o) = pack2(vx - hx, vy - hy);
                        }
                    }
                }
            }
        }
    }
}

// ---------------------------------------------------------------------------
// Split fp32 [R,1024] -> (hi | lo) bf16 [R,2048]
// ---------------------------------------------------------------------------
__global__ __launch_bounds__(256)
void split_hilo(const float* __restrict__ in, __nv_bfloat16* __restrict__ out,
                int total)
{
    int idx = blockIdx.x * 256 + threadIdx.x;
    if (idx >= total) return;
    const int r = idx >> 10;
    const int k = idx & 1023;
    const float x = in[idx];
    const __nv_bfloat16 h = __float2bfloat16(x);
    const __nv_bfloat16 l = __float2bfloat16(x - __bfloat162float(h));
    const size_t o = (size_t)r * KST + k;
    out[o] = h; out[o + 1024] = l;
}

// ---------------------------------------------------------------------------
// V transpose + split: g_v [bh][t][64] fp32 -> V^T hi/lo [bh][d][t].
// ---------------------------------------------------------------------------
__global__ __launch_bounds__(256)
void v_split(const float* __restrict__ v,
             __nv_bfloat16* __restrict__ vht, __nv_bfloat16* __restrict__ vlt)
{
    __shared__ float tile[128][65];
    const int tid = threadIdx.x;
    const int t0  = blockIdx.x * 128;
    const int h   = blockIdx.y;
    const int b   = blockIdx.z;
    const int bh  = b * HH + h;

#pragma unroll
    for (int i = 0; i < 8; i++) {
        const int s   = tid + i * 256;
        const int row = s >> 4;
        const int c4  = (s & 15) * 4;
        float4 vv = *(const float4*)(v + ((size_t)bh * TT + t0 + row) * DK + c4);
        tile[row][c4 + 0] = vv.x; tile[row][c4 + 1] = vv.y;
        tile[row][c4 + 2] = vv.z; tile[row][c4 + 3] = vv.w;
    }
    __syncthreads();

    const int wid  = tid >> 5;
    const int lane = tid & 31;
#pragma unroll
    for (int r = 0; r < 8; r++) {
        const int d = wid * 8 + r;
        uint32_t* oh = (uint32_t*)(vht + ((size_t)bh * DK + d) * TT + t0);
        uint32_t* ol = (uint32_t*)(vlt + ((size_t)bh * DK + d) * TT + t0);
#pragma unroll
        for (int it = 0; it < 2; it++) {
            const int tt = (lane + it * 32) * 2;
            const float v0 = tile[tt][d], v1 = tile[tt + 1][d];
            const float h0 = __bfloat162float(__float2bfloat16(v0));
            const float h1 = __bfloat162float(__float2bfloat16(v1));
            oh[lane + it * 32] = pack2(h0, h1);
            ol[lane + it * 32] = pack2(v0 - h0, v1 - h1);
        }
    }
}

// ---------------------------------------------------------------------------
// Flash attention on tensor cores (compensated bf16), software-pipelined.
// P STAYS IN REGISTERS: the S C-fragments of two adjacent n8 groups ARE the
// A-fragment of the k16 PV mma (a0=(r,k lo pair) a1=(r+8,k lo) a2=(r,k hi)
// a3=(r+8,k hi)), so exp/hi/lo conversion feeds mma directly.
// smem: Q 32KB + K 16KB + V 16KB = 64KB.
// ---------------------------------------------------------------------------
#define SQHI 0
#define SQLO 16384
#define SKHI 32768
#define SKLO 40960
#define SVHI 49152
#define SVLO 57344
#define ATT2_SMEM 65536

// issue one 64-row hi/lo tile pair (8KB each) as ONE commit group
__device__ __forceinline__ void att_issue_tile(
    uint32_t dst_hi, uint32_t dst_lo,
    const __nv_bfloat16* __restrict__ hp, const __nv_bfloat16* __restrict__ lp,
    size_t rstride, int tid)
{
#pragma unroll
    for (int i = 0; i < 2; i++) {
        const int s   = tid + i * 256;
        const int row = s >> 3;
        const int ci  = s & 7;
        const uint32_t sw = sw128((uint32_t)(row * 128 + ci * 16));
        cp16(dst_hi + sw, hp + (size_t)row * rstride + ci * 8);
        cp16(dst_lo + sw, lp + (size_t)row * rstride + ci * 8);
    }
    cp_commit();
}

__global__ __launch_bounds__(256, 2)
void attn_mma(const __nv_bfloat16* __restrict__ qh,
              const __nv_bfloat16* __restrict__ ql,
              const __nv_bfloat16* __restrict__ kh,
              const __nv_bfloat16* __restrict__ kl,
              const __nv_bfloat16* __restrict__ vht,
              const __nv_bfloat16* __restrict__ vlt,
              const int* __restrict__ mask,
              __nv_bfloat16* __restrict__ yp)
{
    extern __shared__ char smc[];
    const uint32_t sb = smem_u32(smc);

    const int tid  = threadIdx.x;
    const int wid  = tid >> 5;
    const int lane = tid & 31;
    const int bx   = gridDim.x - 1 - blockIdx.x;   // heavy blocks first
    const int b    = blockIdx.z;
    const int hh   = blockIdx.y;
    const int bh   = b * HH + hh;
    const int qb   = bx * 128;

    const __nv_bfloat16* khB = kh + (size_t)bh * TT * DK;
    const __nv_bfloat16* klB = kl + (size_t)bh * TT * DK;
    const __nv_bfloat16* vhB = vht + (size_t)bh * DK * TT;
    const __nv_bfloat16* vlB = vlt + (size_t)bh * DK * TT;
    const int* maskB = mask + b * TT;

    // ---- group 1: Q (hi & lo) ----
    {
        const __nv_bfloat16* qhp = qh + ((size_t)bh * TT + qb) * DK;
        const __nv_bfloat16* qlp = ql + ((size_t)bh * TT + qb) * DK;
#pragma unroll
        for (int i = 0; i < 4; i++) {
            const int s   = tid + i * 256;
            const int row = s >> 3;
            const int ci  = s & 7;
            const uint32_t sw = sw128((uint32_t)(row * 128 + ci * 16));
            cp16(sb + SQHI + sw, qhp + (size_t)row * DK + ci * 8);
            cp16(sb + SQLO + sw, qlp + (size_t)row * DK + ci * 8);
        }
        cp_commit();
    }
    // ---- group 2: K(0), group 3: V(0) ----
    att_issue_tile(sb + SKHI, sb + SKLO, khB, klB, DK, tid);
    att_issue_tile(sb + SVHI, sb + SVLO, vhB, vlB, TT, tid);

    float acc[8][4];
#pragma unroll
    for (int nt = 0; nt < 8; nt++)
#pragma unroll
        for (int q = 0; q < 4; q++) acc[nt][q] = 0.f;
    float m0 = -INFINITY, m1 = -INFINITY, l0 = 0.f, l1 = 0.f;

    const int r0g = qb + wid * 16 + (lane >> 2);
    const int r1g = r0g + 8;

    const int ntiles = 2 * bx + 2;
    for (int kt = 0; kt < ntiles; kt++) {
        const int j0 = kt * 64;

        // K(kt) (and Q on first iter) arrived; V(kt) may be in flight
        cp_wait<1>();
        __syncthreads();                     // sync A

        // ---- S = Qhi*Khi + Qlo*Khi + Qhi*Klo (fragment-reuse form) ----
        float s4[8][4];
#pragma unroll
        for (int nt = 0; nt < 8; nt++)
#pragma unroll
            for (int q = 0; q < 4; q++) s4[nt][q] = 0.f;

#pragma unroll
        for (int ks = 0; ks < 4; ks++) {
            uint32_t aqh[4], aql[4];
            {
                const int row = wid * 16 + (lane & 15);
                const uint32_t bo =
                    (uint32_t)(row * 128 + ks * 32 + ((lane >> 4) & 1) * 16);
                ldsm_x4(aqh, sb + SQHI + sw128(bo));
                ldsm_x4(aql, sb + SQLO + sw128(bo));
            }
#pragma unroll
            for (int nt2 = 0; nt2 < 4; nt2++) {
                const int row = nt2 * 16 + ((lane >> 4) << 3) + (lane & 7);
                const uint32_t bo =
                    (uint32_t)(row * 128 + ks * 32 + ((lane >> 3) & 1) * 16);
                uint32_t tk[4];
                ldsm_x4(tk, sb + SKHI + sw128(bo));
                mma_bf16(s4[nt2 * 2 + 0], aqh, tk);
                mma_bf16(s4[nt2 * 2 + 1], aqh, tk + 2);
                mma_bf16(s4[nt2 * 2 + 0], aql, tk);
                mma_bf16(s4[nt2 * 2 + 1], aql, tk + 2);
                uint32_t tl[4];
                ldsm_x4(tl, sb + SKLO + sw128(bo));
                mma_bf16(s4[nt2 * 2 + 0], aqh, tl);
                mma_bf16(s4[nt2 * 2 + 1], aqh, tl + 2);
            }
        }

        // ---- mask + scale (mask straight from gmem; all-ones fast in L1) ----
#pragma unroll
        for (int nt = 0; nt < 8; nt++) {
            const int c0 = nt * 8 + (lane & 3) * 2;
            const bool p0 = maskB[j0 + c0] != 0;
            const bool p1 = maskB[j0 + c0 + 1] != 0;
            const int jg0 = j0 + c0, jg1 = jg0 + 1;
            s4[nt][0] = (p0 && jg0 <= r0g) ? s4[nt][0] * 0.125f : -INFINITY;
            s4[nt][1] = (p1 && jg1 <= r0g) ? s4[nt][1] * 0.125f : -INFINITY;
            s4[nt][2] = (p0 && jg0 <= r1g) ? s4[nt][2] * 0.125f : -INFINITY;
            s4[nt][3] = (p1 && jg1 <= r1g) ? s4[nt][3] * 0.125f : -INFINITY;
        }

        // ---- online softmax ----
        float mx0 = -INFINITY, mx1 = -INFINITY;
#pragma unroll
        for (int nt = 0; nt < 8; nt++) {
            mx0 = fmaxf(mx0, fmaxf(s4[nt][0], s4[nt][1]));
            mx1 = fmaxf(mx1, fmaxf(s4[nt][2], s4[nt][3]));
        }
        mx0 = fmaxf(mx0, __shfl_xor_sync(0xffffffffu, mx0, 1));
        mx0 = fmaxf(mx0, __shfl_xor_sync(0xffffffffu, mx0, 2));
        mx1 = fmaxf(mx1, __shfl_xor_sync(0xffffffffu, mx1, 1));
        mx1 = fmaxf(mx1, __shfl_xor_sync(0xffffffffu, mx1, 2));

        float a0 = 1.f, a1 = 1.f;
        if (mx0 > -INFINITY) {
            const float mn = fmaxf(m0, mx0);
            a0 = __expf(m0 - mn);
            m0 = mn;
        }
        if (mx1 > -INFINITY) {
            const float mn = fmaxf(m1, mx1);
            a1 = __expf(m1 - mn);
            m1 = mn;
        }
        const float mm0 = (m0 == -INFINITY) ? 0.f : m0;
        const float mm1 = (m1 == -INFINITY) ? 0.f : m1;

        // ---- p = exp(s-m) in registers; sums ----
        float sum0 = 0.f, sum1 = 0.f;
#pragma unroll
        for (int nt = 0; nt < 8; nt++) {
            s4[nt][0] = __expf(s4[nt][0] - mm0);
            s4[nt][1] = __expf(s4[nt][1] - mm0);
            s4[nt][2] = __expf(s4[nt][2] - mm1);
            s4[nt][3] = __expf(s4[nt][3] - mm1);
            sum0 += s4[nt][0] + s4[nt][1];
            sum1 += s4[nt][2] + s4[nt][3];
        }
        sum0 += __shfl_xor_sync(0xffffffffu, sum0, 1);
        sum0 += __shfl_xor_sync(0xffffffffu, sum0, 2);
        sum1 += __shfl_xor_sync(0xffffffffu, sum1, 1);
        sum1 += __shfl_xor_sync(0xffffffffu, sum1, 2);
        l0 = l0 * a0 + sum0;
        l1 = l1 * a1 + sum1;

#pragma unroll
        for (int nt = 0; nt < 8; nt++) {
            acc[nt][0] *= a0; acc[nt][1] *= a0;
            acc[nt][2] *= a1; acc[nt][3] *= a1;
        }

        // V(kt) arrived; all warps done reading K -> safe to overwrite K
        cp_wait<0>();
        __syncthreads();                     // sync B
        {                                    // prefetch K(kt+1) — covers PV
            const int jn = (kt + 1 < ntiles) ? j0 + 64 : 0;
            att_issue_tile(sb + SKHI, sb + SKLO,
                           khB + (size_t)jn * DK, klB + (size_t)jn * DK, DK, tid);
        }

        // ---- O += Phi*Vhi + Plo*Vhi + Phi*Vlo, P built in registers ----
#pragma unroll
        for (int ks = 0; ks < 4; ks++) {
            const float h00 = __bfloat162float(__float2bfloat16(s4[2*ks][0]));
            const float h01 = __bfloat162float(__float2bfloat16(s4[2*ks][1]));
            const float h02 = __bfloat162float(__float2bfloat16(s4[2*ks][2]));
            const float h03 = __bfloat162float(__float2bfloat16(s4[2*ks][3]));
            const float h10 = __bfloat162float(__float2bfloat16(s4[2*ks+1][0]));
            const float h11 = __bfloat162float(__float2bfloat16(s4[2*ks+1][1]));
            const float h12 = __bfloat162float(__float2bfloat16(s4[2*ks+1][2]));
            const float h13 = __bfloat162float(__float2bfloat16(s4[2*ks+1][3]));
            uint32_t aph[4], apl[4];
            aph[0] = pack2(h00, h01);
            aph[1] = pack2(h02, h03);
            aph[2] = pack2(h10, h11);
            aph[3] = pack2(h12, h13);
            apl[0] = pack2(s4[2*ks][0] - h00, s4[2*ks][1] - h01);
            apl[1] = pack2(s4[2*ks][2] - h02, s4[2*ks][3] - h03);
            apl[2] = pack2(s4[2*ks+1][0] - h10, s4[2*ks+1][1] - h11);
            apl[3] = pack2(s4[2*ks+1][2] - h12, s4[2*ks+1][3] - h13);
#pragma unroll
            for (int nt2 = 0; nt2 < 4; nt2++) {
                const int row = nt2 * 16 + ((lane >> 4) << 3) + (lane & 7);
                const uint32_t bo =
                    (uint32_t)(row * 128 + ks * 32 + ((lane >> 3) & 1) * 16);
                uint32_t tv[4];
                ldsm_x4(tv, sb + SVHI + sw128(bo));
                mma_bf16(acc[nt2 * 2 + 0], aph, tv);
                mma_bf16(acc[nt2 * 2 + 1], aph, tv + 2);
                mma_bf16(acc[nt2 * 2 + 0], apl, tv);
                mma_bf16(acc[nt2 * 2 + 1], apl, tv + 2);
                uint32_t tw[4];
                ldsm_x4(tw, sb + SVLO + sw128(bo));
                mma_bf16(acc[nt2 * 2 + 0], aph, tw);
                mma_bf16(acc[nt2 * 2 + 1], aph, tw + 2);
            }
        }

        __syncthreads();                     // sync C: V consumed
        {                                    // prefetch V(kt+1)
            const int jn = (kt + 1 < ntiles) ? j0 + 64 : 0;
            att_issue_tile(sb + SVHI, sb + SVLO,
                           vhB + jn, vlB + jn, TT, tid);
        }
    }

    // ---- epilogue: write proj A-operand (hi | lo) layout directly ----
    const float inv0 = (l0 > 0.f) ? (1.f / l0) : 0.f;
    const float inv1 = (l1 > 0.f) ? (1.f / l1) : 0.f;
#pragma unroll
    for (int nt = 0; nt < 8; nt++) {
        const int col = hh * DK + nt * 8 + (lane & 3) * 2;
        {
            const float vx = acc[nt][0] * inv0, vy = acc[nt][1] * inv0;
            const float hx = __bfloat162float(__float2bfloat16(vx));
            const float hy = __bfloat162float(__float2bfloat16(vy));
            const size_t o = ((size_t)b * TT + r0g) * KST + col;
            *(uint32_t*)(yp + o)        = pack2(hx, hy);
            *(uint32_t*)(yp + o + 1024) = pack2(vx - hx, vy - hy);
        }
        {
            const float vx = acc[nt][2] * inv1, vy = acc[nt][3] * inv1;
            const float hx = __bfloat162float(__float2bfloat16(vx));
            const float hy = __bfloat162float(__float2bfloat16(vy));
            const size_t o = ((size_t)b * TT + r1g) * KST + col;
            *(uint32_t*)(yp + o)        = pack2(hx, hy);
            *(uint32_t*)(yp + o + 1024) = pack2(vx - hx, vy - hy);
        }
    }
}

// ---------------------------------------------------------------------------
extern "C" void kernel_launch(void* const* d_in, const int* in_sizes, int n_in,
                              void* d_out, int out_size)
{
    const float* x     = (const float*)d_in[0];
    const float* Wqkv  = (const float*)d_in[1];
    const float* bqkv  = (const float*)d_in[2];
    const float* Wproj = (const float*)d_in[3];
    const float* bproj = (const float*)d_in[4];
    const int*   mask  = (const int*)d_in[5];
    float* out = (float*)d_out;

    float *vp;
    __nv_bfloat16 *xpp, *wqp, *ypp, *wpp;
    __nv_bfloat16 *qhp, *qlp, *khp, *klp, *vhp, *vlp;
    cudaGetSymbolAddress((void**)&vp,   g_v);
    cudaGetSymbolAddress((void**)&xpp,  g_xp);
    cudaGetSymbolAddress((void**)&wqp,  g_wqkvp);
    cudaGetSymbolAddress((void**)&ypp,  g_yp);
    cudaGetSymbolAddress((void**)&wpp,  g_wprojp);
    cudaGetSymbolAddress((void**)&qhp,  g_qh);
    cudaGetSymbolAddress((void**)&qlp,  g_ql);
    cudaGetSymbolAddress((void**)&khp,  g_kh);
    cudaGetSymbolAddress((void**)&klp,  g_kl);
    cudaGetSymbolAddress((void**)&vhp,  g_vht);
    cudaGetSymbolAddress((void**)&vlp,  g_vlt);

    cudaFuncSetAttribute(gemm_bf16_mma<0>,
                         cudaFuncAttributeMaxDynamicSharedMemorySize, GEMM_SMEM);
    cudaFuncSetAttribute(gemm_bf16_mma<1>,
                         cudaFuncAttributeMaxDynamicSharedMemorySize, GEMM_SMEM);
    cudaFuncSetAttribute(attn_mma,
                         cudaFuncAttributeMaxDynamicSharedMemorySize, ATT2_SMEM);

    // input splits (hi|lo)
    split_hilo<<<(MROWS * DD) / 256, 256>>>(x, xpp, MROWS * DD);
    split_hilo<<<(3 * DD * DD) / 256, 256>>>(Wqkv, wqp, 3 * DD * DD);
    split_hilo<<<(DD * DD) / 256, 256>>>(Wproj, wpp, DD * DD);

    // qkv GEMM with fused q/k split + compact V
    gemm_bf16_mma<1><<<dim3(3 * DD / 128, MROWS / 128), 256, GEMM_SMEM>>>(
        xpp, wqp, bqkv, nullptr, MROWS, 3 * DD);

    // V transpose + split
    v_split<<<dim3(TT / 128, HH, BB), 256>>>(vp, vhp, vlp);

    // attention -> g_yp (proj A-operand layout, fused)
    attn_mma<<<dim3(TT / 128, HH, BB), 256, ATT2_SMEM>>>(
        qhp, qlp, khp, klp, vhp, vlp, mask, ypp);

    // out = y @ Wproj^T + bproj
    gemm_bf16_mma<0><<<dim3(DD / 128, MROWS / 128), 256, GEMM_SMEM>>>(
        ypp, wpp, bproj, out, MROWS, DD);
}

// round 16
// speedup vs baseline: 1.2844x; 1.0135x over previous
#include <cuda_runtime.h>
#include <cuda_bf16.h>
#include <cstdint>
#include <stdint.h>
#include <math.h>

// Problem constants (fixed by the reference)
#define BB 4
#define TT 2048
#define DD 1024
#define HH 16
#define DK 64
#define MROWS (BB * TT)          // 8192
#define KST 2048                 // stored K (hi|lo); virtual K' = 3072 via remap
#define NCHG 48                  // virtual K' / 64

// Scratch (allocation-free rule: __device__ globals)
__device__ float         g_v[(size_t)BB * HH * TT * DK];    // V fp32 [bh][t][d]
__device__ __nv_bfloat16 g_xp[(size_t)MROWS * KST];         // x  (hi|lo)
__device__ __nv_bfloat16 g_wqkvp[(size_t)(3 * DD) * KST];   // Wqkv (hi|lo)
__device__ __nv_bfloat16 g_yp[(size_t)MROWS * KST];         // y  (hi|lo)
__device__ __nv_bfloat16 g_wprojp[(size_t)DD * KST];        // Wproj (hi|lo)
// attention operand tensors, per (b,h):
__device__ __nv_bfloat16 g_qh[(size_t)BB * HH * TT * DK];   // Q hi  [bh][t][d]
__device__ __nv_bfloat16 g_ql[(size_t)BB * HH * TT * DK];   // Q lo
__device__ __nv_bfloat16 g_kh[(size_t)BB * HH * TT * DK];   // K hi
__device__ __nv_bfloat16 g_kl[(size_t)BB * HH * TT * DK];   // K lo
__device__ __nv_bfloat16 g_vht[(size_t)BB * HH * DK * TT];  // V^T hi [bh][d][t]
__device__ __nv_bfloat16 g_vlt[(size_t)BB * HH * DK * TT];  // V^T lo

// ---------------------------------------------------------------------------
// helpers (all baseline PTX — compiles on compute_103)
// ---------------------------------------------------------------------------
__device__ __forceinline__ uint32_t smem_u32(const void* p) {
    uint32_t a;
    asm("{ .reg .u64 t; cvta.to.shared.u64 t, %1; cvt.u32.u64 %0, t; }"
        : "=r"(a) : "l"(p));
    return a;
}
__device__ __forceinline__ void cp16(uint32_t saddr, const void* gaddr) {
    asm volatile("cp.async.cg.shared.global [%0], [%1], 16;"
                 :: "r"(saddr), "l"(gaddr) : "memory");
}
__device__ __forceinline__ void cp_commit() {
    asm volatile("cp.async.commit_group;" ::: "memory");
}
template <int N>
__device__ __forceinline__ void cp_wait() {
    asm volatile("cp.async.wait_group %0;" :: "n"(N) : "memory");
}
__device__ __forceinline__ void ldsm_x4(uint32_t* r, uint32_t addr) {
    asm volatile("ldmatrix.sync.aligned.m8n8.x4.shared.b16 {%0,%1,%2,%3}, [%4];"
                 : "=r"(r[0]), "=r"(r[1]), "=r"(r[2]), "=r"(r[3]) : "r"(addr));
}
__device__ __forceinline__ void mma_bf16(float* c, const uint32_t* a,
                                         const uint32_t* b) {
    asm volatile(
        "mma.sync.aligned.m16n8k16.row.col.f32.bf16.bf16.f32 "
        "{%0,%1,%2,%3}, {%4,%5,%6,%7}, {%8,%9}, {%0,%1,%2,%3};"
        : "+f"(c[0]), "+f"(c[1]), "+f"(c[2]), "+f"(c[3])
        : "r"(a[0]), "r"(a[1]), "r"(a[2]), "r"(a[3]), "r"(b[0]), "r"(b[1]));
}
__device__ __forceinline__ uint32_t sw128(uint32_t bo) {
    return bo ^ ((bo >> 3) & 0x70);
}
__device__ __forceinline__ uint32_t pack2(float a, float b) {
    __nv_bfloat162 t = __floats2bfloat162_rn(a, b);
    return *(uint32_t*)&t;
}
// truncation split: hi = top 16 bits of fp32 (x - hi exact in fp32)
__device__ __forceinline__ float trunc_hi(float a) {
    return __uint_as_float(__float_as_uint(a) & 0xffff0000u);
}
// pack the two truncated-hi bf16s of (a,b) in one PRMT
__device__ __forceinline__ uint32_t hi2_trunc(float a, float b) {
    return __byte_perm(__float_as_uint(a), __float_as_uint(b), 0x7632);
}
// virtual-chunk -> stored-chunk remap (A pattern hi,lo,hi ; B pattern hi,hi,lo)
__device__ __forceinline__ int kmapA(int c) { return c < 32 ? c : c - 32; }
__device__ __forceinline__ int kmapB(int c) { return c < 16 ? c : c - 16; }

#define GEMM_SMEM 98304   // 3 x (16KB A + 16KB B)

// ---------------------------------------------------------------------------
// Tensor-core GEMM via mma.sync: C = A(hi|lo) @ B(hi|lo)^T + bias, with the
// compensated-K' schedule applied through kmapA/kmapB (virtual K' = 3072).
// MODE 0: plain fp32 C[M,N].   MODE 1 (qkv): scatter epilogue.
// 3-stage pipeline, ONE barrier per chunk, CUTLASS ordering:
//   cp_wait(c) -> __syncthreads -> issue(c+2 into buf of c-1) -> compute(c)
// Safety: wait precedes the barrier in EVERY thread (so the barrier publishes
// chunk c to all); the issue follows the barrier that proves all threads
// finished compute(c-1) last iteration, so its buffer is free.
// ---------------------------------------------------------------------------
template <int MODE>
__global__ __launch_bounds__(256, 2)
void gemm_bf16_mma(const __nv_bfloat16* __restrict__ A,
                   const __nv_bfloat16* __restrict__ B,
                   const float* __restrict__ bias, float* __restrict__ C,
                   int M, int N)
{
    extern __shared__ char smc[];
    const uint32_t sb = smem_u32(smc);
    const int tid  = threadIdx.x;
    const int wid  = tid >> 5;
    const int lane = tid & 31;
    const int nb   = blockIdx.x * 128;
    const int mb   = blockIdx.y * 128;
    const int mw   = (wid >> 2) * 64;
    const int nw   = (wid & 3) * 32;

    const uint32_t sA = sb;             // 3 x 16KB
    const uint32_t sB = sb + 49152;     // 3 x 16KB

    float acc[4][4][4];
#pragma unroll
    for (int mt = 0; mt < 4; mt++)
#pragma unroll
        for (int nt = 0; nt < 4; nt++)
#pragma unroll
            for (int q = 0; q < 4; q++) acc[mt][nt][q] = 0.f;

    const int lrow = tid >> 3;
    const int lci  = tid & 7;
    const uint32_t lsw = sw128((uint32_t)(lrow * 128 + lci * 16));

    // prologue: issue chunks 0 and 1
#pragma unroll
    for (int c = 0; c < 2; c++) {
        const __nv_bfloat16* Ap = A + (size_t)mb * KST + (kmapA(c) << 6);
        const __nv_bfloat16* Bp = B + (size_t)nb * KST + (kmapB(c) << 6);
        const uint32_t sbuf = c * 16384;
#pragma unroll
        for (int i = 0; i < 4; i++) {
            const uint32_t so = sbuf + lsw + i * 4096;
            cp16(sA + so, Ap + (size_t)(lrow + i * 32) * KST + lci * 8);
            cp16(sB + so, Bp + (size_t)(lrow + i * 32) * KST + lci * 8);
        }
        cp_commit();
    }

    int s = 0;      // buffer of chunk c
    int sn = 2;     // buffer of chunk c+2 (== buffer of chunk c-1)
    for (int c = 0; c < NCHG; c++) {
        // pending groups at this point: {c, c+1} (or {c} on the last iter)
        if (c + 1 < NCHG) cp_wait<1>(); else cp_wait<0>();
        __syncthreads();            // chunk c visible to ALL; buf sn free

        if (c + 2 < NCHG) {
            const __nv_bfloat16* Ap = A + (size_t)mb * KST + (kmapA(c + 2) << 6);
            const __nv_bfloat16* Bp = B + (size_t)nb * KST + (kmapB(c + 2) << 6);
            const uint32_t sbuf = sn * 16384;
#pragma unroll
            for (int i = 0; i < 4; i++) {
                const uint32_t so = sbuf + lsw + i * 4096;
                cp16(sA + so, Ap + (size_t)(lrow + i * 32) * KST + lci * 8);
                cp16(sB + so, Bp + (size_t)(lrow + i * 32) * KST + lci * 8);
            }
            cp_commit();
        }

        const uint32_t baseA = sA + s * 16384;
        const uint32_t baseB = sB + s * 16384;
#pragma unroll
        for (int ks = 0; ks < 4; ks++) {
            uint32_t af[4][4];
#pragma unroll
            for (int mt = 0; mt < 4; mt++) {
                const int row = mw + mt * 16 + (lane & 15);
                const uint32_t bo =
                    (uint32_t)(row * 128 + ks * 32 + ((lane >> 4) & 1) * 16);
                ldsm_x4(af[mt], baseA + sw128(bo));
            }
            uint32_t bf[4][2];
#pragma unroll
            for (int nt2 = 0; nt2 < 2; nt2++) {
                const int row = nw + nt2 * 16 + ((lane >> 4) << 3) + (lane & 7);
                const uint32_t bo =
                    (uint32_t)(row * 128 + ks * 32 + ((lane >> 3) & 1) * 16);
                uint32_t t[4];
                ldsm_x4(t, baseB + sw128(bo));
                bf[nt2 * 2 + 0][0] = t[0]; bf[nt2 * 2 + 0][1] = t[1];
                bf[nt2 * 2 + 1][0] = t[2]; bf[nt2 * 2 + 1][1] = t[3];
            }
#pragma unroll
            for (int mt = 0; mt < 4; mt++)
#pragma unroll
                for (int nt = 0; nt < 4; nt++)
                    mma_bf16(acc[mt][nt], af[mt], bf[nt]);
        }
        s  = (s  == 2) ? 0 : s + 1;
        sn = (sn == 2) ? 0 : sn + 1;
    }

    const int r0 = mb + mw + (lane >> 2);
    const int c0 = nb + nw + (lane & 3) * 2;

    if (MODE == 0) {
#pragma unroll
        for (int mt = 0; mt < 4; mt++) {
#pragma unroll
            for (int nt = 0; nt < 4; nt++) {
                const int col = c0 + nt * 8;
                const float bx = bias[col], by = bias[col + 1];
                float2 v0 = make_float2(acc[mt][nt][0] + bx, acc[mt][nt][1] + by);
                float2 v1 = make_float2(acc[mt][nt][2] + bx, acc[mt][nt][3] + by);
                *(float2*)(C + (size_t)(r0 + mt * 16) * N + col)     = v0;
                *(float2*)(C + (size_t)(r0 + mt * 16 + 8) * N + col) = v1;
            }
        }
    } else {
        // qkv epilogue: scatter into attention operand layouts (trunc split)
#pragma unroll
        for (int nt = 0; nt < 4; nt++) {
            const int col = c0 + nt * 8;
            const int src = col >> 10;          // 0=q, 1=k, 2=v (warp-uniform)
            const int cc  = col & 1023;
            const int h   = cc >> 6;
            const int d   = cc & 63;
            const float bx = bias[col], by = bias[col + 1];
#pragma unroll
            for (int mt = 0; mt < 4; mt++) {
#pragma unroll
                for (int half = 0; half < 2; half++) {
                    const int r = r0 + mt * 16 + half * 8;
                    const float vx = acc[mt][nt][half * 2 + 0] + bx;
                    const float vy = acc[mt][nt][half * 2 + 1] + by;
                    const int bsel = r >> 11;
                    const int t    = r & 2047;
                    const size_t o =
                        ((size_t)(bsel * HH + h) * TT + t) * DK + d;
                    if (src == 2) {
                        *(float2*)(g_v + o) = make_float2(vx, vy);
                    } else {
                        const uint32_t hp = hi2_trunc(vx, vy);
                        const uint32_t lp = pack2(vx - trunc_hi(vx),
                                                  vy - trunc_hi(vy));
                        if (src == 0) {
                            *(uint32_t*)(g_qh + o) = hp;
                            *(uint32_t*)(g_ql + o) = lp;
                        } else {
                            *(uint32_t*)(g_kh + o) = hp;
                            *(uint32_t*)(g_kl + o) = lp;
                        }
                    }
                }
            }
        }
    }
}

// ---------------------------------------------------------------------------
// Split fp32 [R,1024] -> (hi | lo) bf16 [R,2048]  (truncation split)
// ---------------------------------------------------------------------------
__global__ __launch_bounds__(256)
void split_hilo(const float* __restrict__ in, __nv_bfloat16* __restrict__ out,
                int total)
{
    int idx = blockIdx.x * 256 + threadIdx.x;
    if (idx >= total) return;
    const int r = idx >> 10;
    const int k = idx & 1023;
    const float x = in[idx];
    const size_t o = (size_t)r * KST + k;
    ((uint16_t*)out)[o] = (uint16_t)(__float_as_uint(x) >> 16);   // hi (trunc)
    out[o + 1024] = __float2bfloat16(x - trunc_hi(x));            // lo
}

// ---------------------------------------------------------------------------
// V transpose + split: g_v [bh][t][64] fp32 -> V^T hi/lo [bh][d][t].
// ---------------------------------------------------------------------------
__global__ __launch_bounds__(256)
void v_split(const float* __restrict__ v,
             __nv_bfloat16* __restrict__ vht, __nv_bfloat16* __restrict__ vlt)
{
    __shared__ float tile[128][65];
    const int tid = threadIdx.x;
    const int t0  = blockIdx.x * 128;
    const int h   = blockIdx.y;
    const int b   = blockIdx.z;
    const int bh  = b * HH + h;

#pragma unroll
    for (int i = 0; i < 8; i++) {
        const int s   = tid + i * 256;
        const int row = s >> 4;
        const int c4  = (s & 15) * 4;
        float4 vv = *(const float4*)(v + ((size_t)bh * TT + t0 + row) * DK + c4);
        tile[row][c4 + 0] = vv.x; tile[row][c4 + 1] = vv.y;
        tile[row][c4 + 2] = vv.z; tile[row][c4 + 3] = vv.w;
    }
    __syncthreads();

    const int wid  = tid >> 5;
    const int lane = tid & 31;
#pragma unroll
    for (int r = 0; r < 8; r++) {
        const int d = wid * 8 + r;
        uint32_t* oh = (uint32_t*)(vht + ((size_t)bh * DK + d) * TT + t0);
        uint32_t* ol = (uint32_t*)(vlt + ((size_t)bh * DK + d) * TT + t0);
#pragma unroll
        for (int it = 0; it < 2; it++) {
            const int tt = (lane + it * 32) * 2;
            const float v0 = tile[tt][d], v1 = tile[tt + 1][d];
            oh[lane + it * 32] = hi2_trunc(v0, v1);
            ol[lane + it * 32] = pack2(v0 - trunc_hi(v0), v1 - trunc_hi(v1));
        }
    }
}

// ---------------------------------------------------------------------------
// Flash attention on tensor cores (compensated bf16), software-pipelined,
// register-resident P (verified R15). Truncation hi/lo for the P split.
// smem: Q 32KB + K 16KB + V 16KB = 64KB.
// ---------------------------------------------------------------------------
#define SQHI 0
#define SQLO 16384
#define SKHI 32768
#define SKLO 40960
#define SVHI 49152
#define SVLO 57344
#define ATT2_SMEM 65536

// issue one 64-row hi/lo tile pair (8KB each) as ONE commit group
__device__ __forceinline__ void att_issue_tile(
    uint32_t dst_hi, uint32_t dst_lo,
    const __nv_bfloat16* __restrict__ hp, const __nv_bfloat16* __restrict__ lp,
    size_t rstride, int tid)
{
#pragma unroll
    for (int i = 0; i < 2; i++) {
        const int s   = tid + i * 256;
        const int row = s >> 3;
        const int ci  = s & 7;
        const uint32_t sw = sw128((uint32_t)(row * 128 + ci * 16));
        cp16(dst_hi + sw, hp + (size_t)row * rstride + ci * 8);
        cp16(dst_lo + sw, lp + (size_t)row * rstride + ci * 8);
    }
    cp_commit();
}

__global__ __launch_bounds__(256, 2)
void attn_mma(const __nv_bfloat16* __restrict__ qh,
              const __nv_bfloat16* __restrict__ ql,
              const __nv_bfloat16* __restrict__ kh,
              const __nv_bfloat16* __restrict__ kl,
              const __nv_bfloat16* __restrict__ vht,
              const __nv_bfloat16* __restrict__ vlt,
              const int* __restrict__ mask,
              __nv_bfloat16* __restrict__ yp)
{
    extern __shared__ char smc[];
    const uint32_t sb = smem_u32(smc);

    const int tid  = threadIdx.x;
    const int wid  = tid >> 5;
    const int lane = tid & 31;
    const int bx   = gridDim.x - 1 - blockIdx.x;   // heavy blocks first
    const int b    = blockIdx.z;
    const int hh   = blockIdx.y;
    const int bh   = b * HH + hh;
    const int qb   = bx * 128;

    const __nv_bfloat16* khB = kh + (size_t)bh * TT * DK;
    const __nv_bfloat16* klB = kl + (size_t)bh * TT * DK;
    const __nv_bfloat16* vhB = vht + (size_t)bh * DK * TT;
    const __nv_bfloat16* vlB = vlt + (size_t)bh * DK * TT;
    const int* maskB = mask + b * TT;

    // ---- group 1: Q (hi & lo) ----
    {
        const __nv_bfloat16* qhp = qh + ((size_t)bh * TT + qb) * DK;
        const __nv_bfloat16* qlp = ql + ((size_t)bh * TT + qb) * DK;
#pragma unroll
        for (int i = 0; i < 4; i++) {
            const int s   = tid + i * 256;
            const int row = s >> 3;
            const int ci  = s & 7;
            const uint32_t sw = sw128((uint32_t)(row * 128 + ci * 16));
            cp16(sb + SQHI + sw, qhp + (size_t)row * DK + ci * 8);
            cp16(sb + SQLO + sw, qlp + (size_t)row * DK + ci * 8);
        }
        cp_commit();
    }
    // ---- group 2: K(0), group 3: V(0) ----
    att_issue_tile(sb + SKHI, sb + SKLO, khB, klB, DK, tid);
    att_issue_tile(sb + SVHI, sb + SVLO, vhB, vlB, TT, tid);

    float acc[8][4];
#pragma unroll
    for (int nt = 0; nt < 8; nt++)
#pragma unroll
        for (int q = 0; q < 4; q++) acc[nt][q] = 0.f;
    float m0 = -INFINITY, m1 = -INFINITY, l0 = 0.f, l1 = 0.f;

    const int r0g = qb + wid * 16 + (lane >> 2);
    const int r1g = r0g + 8;

    const int ntiles = 2 * bx + 2;
    for (int kt = 0; kt < ntiles; kt++) {
        const int j0 = kt * 64;

        // K(kt) (and Q on first iter) arrived; V(kt) may be in flight
        cp_wait<1>();
        __syncthreads();                     // sync A

        // ---- S = Qhi*Khi + Qlo*Khi + Qhi*Klo (fragment-reuse form) ----
        float s4[8][4];
#pragma unroll
        for (int nt = 0; nt < 8; nt++)
#pragma unroll
            for (int q = 0; q < 4; q++) s4[nt][q] = 0.f;

#pragma unroll
        for (int ks = 0; ks < 4; ks++) {
            uint32_t aqh[4], aql[4];
            {
                const int row = wid * 16 + (lane & 15);
                const uint32_t bo =
                    (uint32_t)(row * 128 + ks * 32 + ((lane >> 4) & 1) * 16);
                ldsm_x4(aqh, sb + SQHI + sw128(bo));
                ldsm_x4(aql, sb + SQLO + sw128(bo));
            }
#pragma unroll
            for (int nt2 = 0; nt2 < 4; nt2++) {
                const int row = nt2 * 16 + ((lane >> 4) << 3) + (lane & 7);
                const uint32_t bo =
                    (uint32_t)(row * 128 + ks * 32 + ((lane >> 3) & 1) * 16);
                uint32_t tk[4];
                ldsm_x4(tk, sb + SKHI + sw128(bo));
                mma_bf16(s4[nt2 * 2 + 0], aqh, tk);
                mma_bf16(s4[nt2 * 2 + 1], aqh, tk + 2);
                mma_bf16(s4[nt2 * 2 + 0], aql, tk);
                mma_bf16(s4[nt2 * 2 + 1], aql, tk + 2);
                uint32_t tl[4];
                ldsm_x4(tl, sb + SKLO + sw128(bo));
                mma_bf16(s4[nt2 * 2 + 0], aqh, tl);
                mma_bf16(s4[nt2 * 2 + 1], aqh, tl + 2);
            }
        }

        // ---- mask + scale (mask straight from gmem; all-ones fast in L1) ----
#pragma unroll
        for (int nt = 0; nt < 8; nt++) {
            const int c0 = nt * 8 + (lane & 3) * 2;
            const bool p0 = maskB[j0 + c0] != 0;
            const bool p1 = maskB[j0 + c0 + 1] != 0;
            const int jg0 = j0 + c0, jg1 = jg0 + 1;
            s4[nt][0] = (p0 && jg0 <= r0g) ? s4[nt][0] * 0.125f : -INFINITY;
            s4[nt][1] = (p1 && jg1 <= r0g) ? s4[nt][1] * 0.125f : -INFINITY;
            s4[nt][2] = (p0 && jg0 <= r1g) ? s4[nt][2] * 0.125f : -INFINITY;
            s4[nt][3] = (p1 && jg1 <= r1g) ? s4[nt][3] * 0.125f : -INFINITY;
        }

        // ---- online softmax ----
        float mx0 = -INFINITY, mx1 = -INFINITY;
#pragma unroll
        for (int nt = 0; nt < 8; nt++) {
            mx0 = fmaxf(mx0, fmaxf(s4[nt][0], s4[nt][1]));
            mx1 = fmaxf(mx1, fmaxf(s4[nt][2], s4[nt][3]));
        }
        mx0 = fmaxf(mx0, __shfl_xor_sync(0xffffffffu, mx0, 1));
        mx0 = fmaxf(mx0, __shfl_xor_sync(0xffffffffu, mx0, 2));
        mx1 = fmaxf(mx1, __shfl_xor_sync(0xffffffffu, mx1, 1));
        mx1 = fmaxf(mx1, __shfl_xor_sync(0xffffffffu, mx1, 2));

        float a0 = 1.f, a1 = 1.f;
        if (mx0 > -INFINITY) {
            const float mn = fmaxf(m0, mx0);
            a0 = __expf(m0 - mn);
            m0 = mn;
        }
        if (mx1 > -INFINITY) {
            const float mn = fmaxf(m1, mx1);
            a1 = __expf(m1 - mn);
            m1 = mn;
        }
        const float mm0 = (m0 == -INFINITY) ? 0.f : m0;
        const float mm1 = (m1 == -INFINITY) ? 0.f : m1;

        // ---- p = exp(s-m) in registers; sums ----
        float sum0 = 0.f, sum1 = 0.f;
#pragma unroll
        for (int nt = 0; nt < 8; nt++) {
            s4[nt][0] = __expf(s4[nt][0] - mm0);
            s4[nt][1] = __expf(s4[nt][1] - mm0);
            s4[nt][2] = __expf(s4[nt][2] - mm1);
            s4[nt][3] = __expf(s4[nt][3] - mm1);
            sum0 += s4[nt][0] + s4[nt][1];
            sum1 += s4[nt][2] + s4[nt][3];
        }
        sum0 += __shfl_xor_sync(0xffffffffu, sum0, 1);
        sum0 += __shfl_xor_sync(0xffffffffu, sum0, 2);
        sum1 += __shfl_xor_sync(0xffffffffu, sum1, 1);
        sum1 += __shfl_xor_sync(0xffffffffu, sum1, 2);
        l0 = l0 * a0 + sum0;
        l1 = l1 * a1 + sum1;

#pragma unroll
        for (int nt = 0; nt < 8; nt++) {
            acc[nt][0] *= a0; acc[nt][1] *= a0;
            acc[nt][2] *= a1; acc[nt][3] *= a1;
        }

        // V(kt) arrived; all warps done reading K -> safe to overwrite K
        cp_wait<0>();
        __syncthreads();                     // sync B
        {                                    // prefetch K(kt+1) — covers PV
            const int jn = (kt + 1 < ntiles) ? j0 + 64 : 0;
            att_issue_tile(sb + SKHI, sb + SKLO,
                           khB + (size_t)jn * DK, klB + (size_t)jn * DK, DK, tid);
        }

        // ---- O += Phi*Vhi + Plo*Vhi + Phi*Vlo, P built in registers ----
#pragma unroll
        for (int ks = 0; ks < 4; ks++) {
            uint32_t aph[4], apl[4];
            aph[0] = hi2_trunc(s4[2*ks][0],   s4[2*ks][1]);
            aph[1] = hi2_trunc(s4[2*ks][2],   s4[2*ks][3]);
            aph[2] = hi2_trunc(s4[2*ks+1][0], s4[2*ks+1][1]);
            aph[3] = hi2_trunc(s4[2*ks+1][2], s4[2*ks+1][3]);
            apl[0] = pack2(s4[2*ks][0] - trunc_hi(s4[2*ks][0]),
                           s4[2*ks][1] - trunc_hi(s4[2*ks][1]));
            apl[1] = pack2(s4[2*ks][2] - trunc_hi(s4[2*ks][2]),
                           s4[2*ks][3] - trunc_hi(s4[2*ks][3]));
            apl[2] = pack2(s4[2*ks+1][0] - trunc_hi(s4[2*ks+1][0]),
                           s4[2*ks+1][1] - trunc_hi(s4[2*ks+1][1]));
            apl[3] = pack2(s4[2*ks+1][2] - trunc_hi(s4[2*ks+1][2]),
                           s4[2*ks+1][3] - trunc_hi(s4[2*ks+1][3]));
#pragma unroll
            for (int nt2 = 0; nt2 < 4; nt2++) {
                const int row = nt2 * 16 + ((lane >> 4) << 3) + (lane & 7);
                const uint32_t bo =
                    (uint32_t)(row * 128 + ks * 32 + ((lane >> 3) & 1) * 16);
                uint32_t tv[4];
                ldsm_x4(tv, sb + SVHI + sw128(bo));
                mma_bf16(acc[nt2 * 2 + 0], aph, tv);
                mma_bf16(acc[nt2 * 2 + 1], aph, tv + 2);
                mma_bf16(acc[nt2 * 2 + 0], apl, tv);
                mma_bf16(acc[nt2 * 2 + 1], apl, tv + 2);
                uint32_t tw[4];
                ldsm_x4(tw, sb + SVLO + sw128(bo));
                mma_bf16(acc[nt2 * 2 + 0], aph, tw);
                mma_bf16(acc[nt2 * 2 + 1], aph, tw + 2);
            }
        }

        __syncthreads();                     // sync C: V consumed
        {                                    // prefetch V(kt+1)
            const int jn = (kt + 1 < ntiles) ? j0 + 64 : 0;
            att_issue_tile(sb + SVHI, sb + SVLO,
                           vhB + jn, vlB + jn, TT, tid);
        }
    }

    // ---- epilogue: write proj A-operand (hi | lo) layout directly ----
    const float inv0 = (l0 > 0.f) ? (1.f / l0) : 0.f;
    const float inv1 = (l1 > 0.f) ? (1.f / l1) : 0.f;
#pragma unroll
    for (int nt = 0; nt < 8; nt++) {
        const int col = hh * DK + nt * 8 + (lane & 3) * 2;
        {
            const float vx = acc[nt][0] * inv0, vy = acc[nt][1] * inv0;
            const size_t o = ((size_t)b * TT + r0g) * KST + col;
            *(uint32_t*)(yp + o)        = hi2_trunc(vx, vy);
            *(uint32_t*)(yp + o + 1024) = pack2(vx - trunc_hi(vx),
                                                vy - trunc_hi(vy));
        }
        {
            const float vx = acc[nt][2] * inv1, vy = acc[nt][3] * inv1;
            const size_t o = ((size_t)b * TT + r1g) * KST + col;
            *(uint32_t*)(yp + o)        = hi2_trunc(vx, vy);
            *(uint32_t*)(yp + o + 1024) = pack2(vx - trunc_hi(vx),
                                                vy - trunc_hi(vy));
        }
    }
}

// ---------------------------------------------------------------------------
extern "C" void kernel_launch(void* const* d_in, const int* in_sizes, int n_in,
                              void* d_out, int out_size)
{
    const float* x     = (const float*)d_in[0];
    const float* Wqkv  = (const float*)d_in[1];
    const float* bqkv  = (const float*)d_in[2];
    const float* Wproj = (const float*)d_in[3];
    const float* bproj = (const float*)d_in[4];
    const int*   mask  = (const int*)d_in[5];
    float* out = (float*)d_out;

    float *vp;
    __nv_bfloat16 *xpp, *wqp, *ypp, *wpp;
    __nv_bfloat16 *qhp, *qlp, *khp, *klp, *vhp, *vlp;
    cudaGetSymbolAddress((void**)&vp,   g_v);
    cudaGetSymbolAddress((void**)&xpp,  g_xp);
    cudaGetSymbolAddress((void**)&wqp,  g_wqkvp);
    cudaGetSymbolAddress((void**)&ypp,  g_yp);
    cudaGetSymbolAddress((void**)&wpp,  g_wprojp);
    cudaGetSymbolAddress((void**)&qhp,  g_qh);
    cudaGetSymbolAddress((void**)&qlp,  g_ql);
    cudaGetSymbolAddress((void**)&khp,  g_kh);
    cudaGetSymbolAddress((void**)&klp,  g_kl);
    cudaGetSymbolAddress((void**)&vhp,  g_vht);
    cudaGetSymbolAddress((void**)&vlp,  g_vlt);

    cudaFuncSetAttribute(gemm_bf16_mma<0>,
                         cudaFuncAttributeMaxDynamicSharedMemorySize, GEMM_SMEM);
    cudaFuncSetAttribute(gemm_bf16_mma<1>,
                         cudaFuncAttributeMaxDynamicSharedMemorySize, GEMM_SMEM);
    cudaFuncSetAttribute(attn_mma,
                         cudaFuncAttributeMaxDynamicSharedMemorySize, ATT2_SMEM);

    // input splits (hi|lo, truncation)
    split_hilo<<<(MROWS * DD) / 256, 256>>>(x, xpp, MROWS * DD);
    split_hilo<<<(3 * DD * DD) / 256, 256>>>(Wqkv, wqp, 3 * DD * DD);
    split_hilo<<<(DD * DD) / 256, 256>>>(Wproj, wpp, DD * DD);

    // qkv GEMM with fused q/k split + compact V
    gemm_bf16_mma<1><<<dim3(3 * DD / 128, MROWS / 128), 256, GEMM_SMEM>>>(
        xpp, wqp, bqkv, nullptr, MROWS, 3 * DD);

    // V transpose + split
    v_split<<<dim3(TT / 128, HH, BB), 256>>>(vp, vhp, vlp);

    // attention -> g_yp (proj A-operand layout, fused)
    attn_mma<<<dim3(TT / 128, HH, BB), 256, ATT2_SMEM>>>(
        qhp, qlp, khp, klp, vhp, vlp, mask, ypp);

    // out = y @ Wproj^T + bproj
    gemm_bf16_mma<0><<<dim3(DD / 128, MROWS / 128), 256, GEMM_SMEM>>>(
        ypp, wpp, bproj, out, MROWS, DD);
}

// round 17
// speedup vs baseline: 1.3158x; 1.0245x over previous
#include <cuda_runtime.h>
#include <cuda_bf16.h>
#include <cstdint>
#include <stdint.h>
#include <math.h>

// Problem constants (fixed by the reference)
#define BB 4
#define TT 2048
#define DD 1024
#define HH 16
#define DK 64
#define MROWS (BB * TT)          // 8192
#define KST 2048                 // stored K (hi|lo); virtual K' = 3072 via remap
#define NCHG 48                  // virtual K' / 64
// softmax scale folded with log2(e): p = 2^(s*SCL2E - m')
#define SCL2E 0.1803368801111244f   // 0.125 * log2(e)

// Scratch (allocation-free rule: __device__ globals)
__device__ float         g_v[(size_t)BB * HH * TT * DK];    // V fp32 [bh][t][d]
__device__ __nv_bfloat16 g_xp[(size_t)MROWS * KST];         // x  (hi|lo)
__device__ __nv_bfloat16 g_wqkvp[(size_t)(3 * DD) * KST];   // Wqkv (hi|lo)
__device__ __nv_bfloat16 g_yp[(size_t)MROWS * KST];         // y  (hi|lo)
__device__ __nv_bfloat16 g_wprojp[(size_t)DD * KST];        // Wproj (hi|lo)
// attention operand tensors, per (b,h):
__device__ __nv_bfloat16 g_qh[(size_t)BB * HH * TT * DK];   // Q hi  [bh][t][d]
__device__ __nv_bfloat16 g_ql[(size_t)BB * HH * TT * DK];   // Q lo
__device__ __nv_bfloat16 g_kh[(size_t)BB * HH * TT * DK];   // K hi
__device__ __nv_bfloat16 g_kl[(size_t)BB * HH * TT * DK];   // K lo
__device__ __nv_bfloat16 g_vht[(size_t)BB * HH * DK * TT];  // V^T hi [bh][d][t]
__device__ __nv_bfloat16 g_vlt[(size_t)BB * HH * DK * TT];  // V^T lo

// ---------------------------------------------------------------------------
// helpers (all baseline PTX — compiles on compute_103)
// ---------------------------------------------------------------------------
__device__ __forceinline__ uint32_t smem_u32(const void* p) {
    uint32_t a;
    asm("{ .reg .u64 t; cvta.to.shared.u64 t, %1; cvt.u32.u64 %0, t; }"
        : "=r"(a) : "l"(p));
    return a;
}
__device__ __forceinline__ void cp16(uint32_t saddr, const void* gaddr) {
    asm volatile("cp.async.cg.shared.global [%0], [%1], 16;"
                 :: "r"(saddr), "l"(gaddr) : "memory");
}
__device__ __forceinline__ void cp_commit() {
    asm volatile("cp.async.commit_group;" ::: "memory");
}
template <int N>
__device__ __forceinline__ void cp_wait() {
    asm volatile("cp.async.wait_group %0;" :: "n"(N) : "memory");
}
__device__ __forceinline__ void ldsm_x4(uint32_t* r, uint32_t addr) {
    asm volatile("ldmatrix.sync.aligned.m8n8.x4.shared.b16 {%0,%1,%2,%3}, [%4];"
                 : "=r"(r[0]), "=r"(r[1]), "=r"(r[2]), "=r"(r[3]) : "r"(addr));
}
__device__ __forceinline__ void mma_bf16(float* c, const uint32_t* a,
                                         const uint32_t* b) {
    asm volatile(
        "mma.sync.aligned.m16n8k16.row.col.f32.bf16.bf16.f32 "
        "{%0,%1,%2,%3}, {%4,%5,%6,%7}, {%8,%9}, {%0,%1,%2,%3};"
        : "+f"(c[0]), "+f"(c[1]), "+f"(c[2]), "+f"(c[3])
        : "r"(a[0]), "r"(a[1]), "r"(a[2]), "r"(a[3]), "r"(b[0]), "r"(b[1]));
}
__device__ __forceinline__ uint32_t sw128(uint32_t bo) {
    return bo ^ ((bo >> 3) & 0x70);
}
__device__ __forceinline__ uint32_t pack2(float a, float b) {
    __nv_bfloat162 t = __floats2bfloat162_rn(a, b);
    return *(uint32_t*)&t;
}
// truncation split: hi = top 16 bits of fp32 (x - hi exact in fp32)
__device__ __forceinline__ float trunc_hi(float a) {
    return __uint_as_float(__float_as_uint(a) & 0xffff0000u);
}
// pack the two truncated-hi bf16s of (a,b) in one PRMT
__device__ __forceinline__ uint32_t hi2_trunc(float a, float b) {
    return __byte_perm(__float_as_uint(a), __float_as_uint(b), 0x7632);
}
// raw exp2 (softmax domain is pre-scaled by 0.125*log2e)
__device__ __forceinline__ float ex2(float x) {
    float y;
    asm("ex2.approx.f32 %0, %1;" : "=f"(y) : "f"(x));
    return y;
}
// virtual-chunk -> stored-chunk remap (A pattern hi,lo,hi ; B pattern hi,hi,lo)
__device__ __forceinline__ int kmapA(int c) { return c < 32 ? c : c - 32; }
__device__ __forceinline__ int kmapB(int c) { return c < 16 ? c : c - 16; }

#define GEMM_SMEM 98304   // 3 x (16KB A + 16KB B)

// ---------------------------------------------------------------------------
// Tensor-core GEMM via mma.sync (verified R16): single barrier per chunk,
// compensated-K' via kmapA/kmapB. MODE 0: fp32 C. MODE 1: qkv scatter.
// ---------------------------------------------------------------------------
template <int MODE>
__global__ __launch_bounds__(256, 2)
void gemm_bf16_mma(const __nv_bfloat16* __restrict__ A,
                   const __nv_bfloat16* __restrict__ B,
                   const float* __restrict__ bias, float* __restrict__ C,
                   int M, int N)
{
    extern __shared__ char smc[];
    const uint32_t sb = smem_u32(smc);
    const int tid  = threadIdx.x;
    const int wid  = tid >> 5;
    const int lane = tid & 31;
    const int nb   = blockIdx.x * 128;
    const int mb   = blockIdx.y * 128;
    const int mw   = (wid >> 2) * 64;
    const int nw   = (wid & 3) * 32;

    const uint32_t sA = sb;             // 3 x 16KB
    const uint32_t sB = sb + 49152;     // 3 x 16KB

    float acc[4][4][4];
#pragma unroll
    for (int mt = 0; mt < 4; mt++)
#pragma unroll
        for (int nt = 0; nt < 4; nt++)
#pragma unroll
            for (int q = 0; q < 4; q++) acc[mt][nt][q] = 0.f;

    const int lrow = tid >> 3;
    const int lci  = tid & 7;
    const uint32_t lsw = sw128((uint32_t)(lrow * 128 + lci * 16));

    // prologue: issue chunks 0 and 1
#pragma unroll
    for (int c = 0; c < 2; c++) {
        const __nv_bfloat16* Ap = A + (size_t)mb * KST + (kmapA(c) << 6);
        const __nv_bfloat16* Bp = B + (size_t)nb * KST + (kmapB(c) << 6);
        const uint32_t sbuf = c * 16384;
#pragma unroll
        for (int i = 0; i < 4; i++) {
            const uint32_t so = sbuf + lsw + i * 4096;
            cp16(sA + so, Ap + (size_t)(lrow + i * 32) * KST + lci * 8);
            cp16(sB + so, Bp + (size_t)(lrow + i * 32) * KST + lci * 8);
        }
        cp_commit();
    }

    int s = 0;      // buffer of chunk c
    int sn = 2;     // buffer of chunk c+2 (== buffer of chunk c-1)
    for (int c = 0; c < NCHG; c++) {
        if (c + 1 < NCHG) cp_wait<1>(); else cp_wait<0>();
        __syncthreads();            // chunk c visible to ALL; buf sn free

        if (c + 2 < NCHG) {
            const __nv_bfloat16* Ap = A + (size_t)mb * KST + (kmapA(c + 2) << 6);
            const __nv_bfloat16* Bp = B + (size_t)nb * KST + (kmapB(c + 2) << 6);
            const uint32_t sbuf = sn * 16384;
#pragma unroll
            for (int i = 0; i < 4; i++) {
                const uint32_t so = sbuf + lsw + i * 4096;
                cp16(sA + so, Ap + (size_t)(lrow + i * 32) * KST + lci * 8);
                cp16(sB + so, Bp + (size_t)(lrow + i * 32) * KST + lci * 8);
            }
            cp_commit();
        }

        const uint32_t baseA = sA + s * 16384;
        const uint32_t baseB = sB + s * 16384;
#pragma unroll
        for (int ks = 0; ks < 4; ks++) {
            uint32_t af[4][4];
#pragma unroll
            for (int mt = 0; mt < 4; mt++) {
                const int row = mw + mt * 16 + (lane & 15);
                const uint32_t bo =
                    (uint32_t)(row * 128 + ks * 32 + ((lane >> 4) & 1) * 16);
                ldsm_x4(af[mt], baseA + sw128(bo));
            }
            uint32_t bf[4][2];
#pragma unroll
            for (int nt2 = 0; nt2 < 2; nt2++) {
                const int row = nw + nt2 * 16 + ((lane >> 4) << 3) + (lane & 7);
                const uint32_t bo =
                    (uint32_t)(row * 128 + ks * 32 + ((lane >> 3) & 1) * 16);
                uint32_t t[4];
                ldsm_x4(t, baseB + sw128(bo));
                bf[nt2 * 2 + 0][0] = t[0]; bf[nt2 * 2 + 0][1] = t[1];
                bf[nt2 * 2 + 1][0] = t[2]; bf[nt2 * 2 + 1][1] = t[3];
            }
#pragma unroll
            for (int mt = 0; mt < 4; mt++)
#pragma unroll
                for (int nt = 0; nt < 4; nt++)
                    mma_bf16(acc[mt][nt], af[mt], bf[nt]);
        }
        s  = (s  == 2) ? 0 : s + 1;
        sn = (sn == 2) ? 0 : sn + 1;
    }

    const int r0 = mb + mw + (lane >> 2);
    const int c0 = nb + nw + (lane & 3) * 2;

    if (MODE == 0) {
#pragma unroll
        for (int mt = 0; mt < 4; mt++) {
#pragma unroll
            for (int nt = 0; nt < 4; nt++) {
                const int col = c0 + nt * 8;
                const float bx = bias[col], by = bias[col + 1];
                float2 v0 = make_float2(acc[mt][nt][0] + bx, acc[mt][nt][1] + by);
                float2 v1 = make_float2(acc[mt][nt][2] + bx, acc[mt][nt][3] + by);
                *(float2*)(C + (size_t)(r0 + mt * 16) * N + col)     = v0;
                *(float2*)(C + (size_t)(r0 + mt * 16 + 8) * N + col) = v1;
            }
        }
    } else {
        // qkv epilogue: scatter into attention operand layouts (trunc split)
#pragma unroll
        for (int nt = 0; nt < 4; nt++) {
            const int col = c0 + nt * 8;
            const int src = col >> 10;          // 0=q, 1=k, 2=v (warp-uniform)
            const int cc  = col & 1023;
            const int h   = cc >> 6;
            const int d   = cc & 63;
            const float bx = bias[col], by = bias[col + 1];
#pragma unroll
            for (int mt = 0; mt < 4; mt++) {
#pragma unroll
                for (int half = 0; half < 2; half++) {
                    const int r = r0 + mt * 16 + half * 8;
                    const float vx = acc[mt][nt][half * 2 + 0] + bx;
                    const float vy = acc[mt][nt][half * 2 + 1] + by;
                    const int bsel = r >> 11;
                    const int t    = r & 2047;
                    const size_t o =
                        ((size_t)(bsel * HH + h) * TT + t) * DK + d;
                    if (src == 2) {
                        *(float2*)(g_v + o) = make_float2(vx, vy);
                    } else {
                        const uint32_t hp = hi2_trunc(vx, vy);
                        const uint32_t lp = pack2(vx - trunc_hi(vx),
                                                  vy - trunc_hi(vy));
                        if (src == 0) {
                            *(uint32_t*)(g_qh + o) = hp;
                            *(uint32_t*)(g_ql + o) = lp;
                        } else {
                            *(uint32_t*)(g_kh + o) = hp;
                            *(uint32_t*)(g_kl + o) = lp;
                        }
                    }
                }
            }
        }
    }
}

// ---------------------------------------------------------------------------
// Split fp32 [R,1024] -> (hi | lo) bf16 [R,2048], 4 elems/thread, 8B stores.
// ---------------------------------------------------------------------------
__global__ __launch_bounds__(256)
void split_hilo(const float* __restrict__ in, __nv_bfloat16* __restrict__ out,
                int total4)
{
    const int i4 = blockIdx.x * 256 + threadIdx.x;
    if (i4 >= total4) return;
    const int idx = i4 * 4;
    const int r = idx >> 10;
    const int k = idx & 1023;
    const float4 x = *(const float4*)(in + idx);
    const size_t o = (size_t)r * KST + k;
    uint2 hp, lp;
    hp.x = hi2_trunc(x.x, x.y);
    hp.y = hi2_trunc(x.z, x.w);
    lp.x = pack2(x.x - trunc_hi(x.x), x.y - trunc_hi(x.y));
    lp.y = pack2(x.z - trunc_hi(x.z), x.w - trunc_hi(x.w));
    *(uint2*)(out + o)        = hp;
    *(uint2*)(out + o + 1024) = lp;
}

// ---------------------------------------------------------------------------
// V transpose + split: g_v [bh][t][64] fp32 -> V^T hi/lo [bh][d][t].
// ---------------------------------------------------------------------------
__global__ __launch_bounds__(256)
void v_split(const float* __restrict__ v,
             __nv_bfloat16* __restrict__ vht, __nv_bfloat16* __restrict__ vlt)
{
    __shared__ float tile[128][65];
    const int tid = threadIdx.x;
    const int t0  = blockIdx.x * 128;
    const int h   = blockIdx.y;
    const int b   = blockIdx.z;
    const int bh  = b * HH + h;

#pragma unroll
    for (int i = 0; i < 8; i++) {
        const int s   = tid + i * 256;
        const int row = s >> 4;
        const int c4  = (s & 15) * 4;
        float4 vv = *(const float4*)(v + ((size_t)bh * TT + t0 + row) * DK + c4);
        tile[row][c4 + 0] = vv.x; tile[row][c4 + 1] = vv.y;
        tile[row][c4 + 2] = vv.z; tile[row][c4 + 3] = vv.w;
    }
    __syncthreads();

    const int wid  = tid >> 5;
    const int lane = tid & 31;
#pragma unroll
    for (int r = 0; r < 8; r++) {
        const int d = wid * 8 + r;
        uint32_t* oh = (uint32_t*)(vht + ((size_t)bh * DK + d) * TT + t0);
        uint32_t* ol = (uint32_t*)(vlt + ((size_t)bh * DK + d) * TT + t0);
#pragma unroll
        for (int it = 0; it < 2; it++) {
            const int tt = (lane + it * 32) * 2;
            const float v0 = tile[tt][d], v1 = tile[tt + 1][d];
            oh[lane + it * 32] = hi2_trunc(v0, v1);
            ol[lane + it * 32] = pack2(v0 - trunc_hi(v0), v1 - trunc_hi(v1));
        }
    }
}

// ---------------------------------------------------------------------------
// Flash attention on tensor cores (compensated bf16), software-pipelined,
// register-resident P, exp2-domain softmax (scale*log2e folded into mask).
// smem: Q 32KB + K 16KB + V 16KB = 64KB.
// ---------------------------------------------------------------------------
#define SQHI 0
#define SQLO 16384
#define SKHI 32768
#define SKLO 40960
#define SVHI 49152
#define SVLO 57344
#define ATT2_SMEM 65536

// issue one 64-row hi/lo tile pair (8KB each) as ONE commit group
__device__ __forceinline__ void att_issue_tile(
    uint32_t dst_hi, uint32_t dst_lo,
    const __nv_bfloat16* __restrict__ hp, const __nv_bfloat16* __restrict__ lp,
    size_t rstride, int tid)
{
#pragma unroll
    for (int i = 0; i < 2; i++) {
        const int s   = tid + i * 256;
        const int row = s >> 3;
        const int ci  = s & 7;
        const uint32_t sw = sw128((uint32_t)(row * 128 + ci * 16));
        cp16(dst_hi + sw, hp + (size_t)row * rstride + ci * 8);
        cp16(dst_lo + sw, lp + (size_t)row * rstride + ci * 8);
    }
    cp_commit();
}

__global__ __launch_bounds__(256, 2)
void attn_mma(const __nv_bfloat16* __restrict__ qh,
              const __nv_bfloat16* __restrict__ ql,
              const __nv_bfloat16* __restrict__ kh,
              const __nv_bfloat16* __restrict__ kl,
              const __nv_bfloat16* __restrict__ vht,
              const __nv_bfloat16* __restrict__ vlt,
              const int* __restrict__ mask,
              __nv_bfloat16* __restrict__ yp)
{
    extern __shared__ char smc[];
    const uint32_t sb = smem_u32(smc);

    const int tid  = threadIdx.x;
    const int wid  = tid >> 5;
    const int lane = tid & 31;
    const int bx   = gridDim.x - 1 - blockIdx.x;   // heavy blocks first
    const int b    = blockIdx.z;
    const int hh   = blockIdx.y;
    const int bh   = b * HH + hh;
    const int qb   = bx * 128;

    const __nv_bfloat16* khB = kh + (size_t)bh * TT * DK;
    const __nv_bfloat16* klB = kl + (size_t)bh * TT * DK;
    const __nv_bfloat16* vhB = vht + (size_t)bh * DK * TT;
    const __nv_bfloat16* vlB = vlt + (size_t)bh * DK * TT;
    const int* maskB = mask + b * TT;

    // ---- group 1: Q (hi & lo) ----
    {
        const __nv_bfloat16* qhp = qh + ((size_t)bh * TT + qb) * DK;
        const __nv_bfloat16* qlp = ql + ((size_t)bh * TT + qb) * DK;
#pragma unroll
        for (int i = 0; i < 4; i++) {
            const int s   = tid + i * 256;
            const int row = s >> 3;
            const int ci  = s & 7;
            const uint32_t sw = sw128((uint32_t)(row * 128 + ci * 16));
            cp16(sb + SQHI + sw, qhp + (size_t)row * DK + ci * 8);
            cp16(sb + SQLO + sw, qlp + (size_t)row * DK + ci * 8);
        }
        cp_commit();
    }
    // ---- group 2: K(0), group 3: V(0) ----
    att_issue_tile(sb + SKHI, sb + SKLO, khB, klB, DK, tid);
    att_issue_tile(sb + SVHI, sb + SVLO, vhB, vlB, TT, tid);

    float acc[8][4];
#pragma unroll
    for (int nt = 0; nt < 8; nt++)
#pragma unroll
        for (int q = 0; q < 4; q++) acc[nt][q] = 0.f;
    float m0 = -INFINITY, m1 = -INFINITY, l0 = 0.f, l1 = 0.f;

    const int r0g = qb + wid * 16 + (lane >> 2);
    const int r1g = r0g + 8;

    const int ntiles = 2 * bx + 2;
    for (int kt = 0; kt < ntiles; kt++) {
        const int j0 = kt * 64;

        // K(kt) (and Q on first iter) arrived; V(kt) may be in flight
        cp_wait<1>();
        __syncthreads();                     // sync A

        // ---- S = Qhi*Khi + Qlo*Khi + Qhi*Klo (fragment-reuse form) ----
        float s4[8][4];
#pragma unroll
        for (int nt = 0; nt < 8; nt++)
#pragma unroll
            for (int q = 0; q < 4; q++) s4[nt][q] = 0.f;

#pragma unroll
        for (int ks = 0; ks < 4; ks++) {
            uint32_t aqh[4], aql[4];
            {
                const int row = wid * 16 + (lane & 15);
                const uint32_t bo =
                    (uint32_t)(row * 128 + ks * 32 + ((lane >> 4) & 1) * 16);
                ldsm_x4(aqh, sb + SQHI + sw128(bo));
                ldsm_x4(aql, sb + SQLO + sw128(bo));
            }
#pragma unroll
            for (int nt2 = 0; nt2 < 4; nt2++) {
                const int row = nt2 * 16 + ((lane >> 4) << 3) + (lane & 7);
                const uint32_t bo =
                    (uint32_t)(row * 128 + ks * 32 + ((lane >> 3) & 1) * 16);
                uint32_t tk[4];
                ldsm_x4(tk, sb + SKHI + sw128(bo));
                mma_bf16(s4[nt2 * 2 + 0], aqh, tk);
                mma_bf16(s4[nt2 * 2 + 1], aqh, tk + 2);
                mma_bf16(s4[nt2 * 2 + 0], aql, tk);
                mma_bf16(s4[nt2 * 2 + 1], aql, tk + 2);
                uint32_t tl[4];
                ldsm_x4(tl, sb + SKLO + sw128(bo));
                mma_bf16(s4[nt2 * 2 + 0], aqh, tl);
                mma_bf16(s4[nt2 * 2 + 1], aqh, tl + 2);
            }
        }

        // ---- mask + fold (0.125*log2e) scale; exp2 domain from here on ----
#pragma unroll
        for (int nt = 0; nt < 8; nt++) {
            const int c0 = nt * 8 + (lane & 3) * 2;
            const bool p0 = maskB[j0 + c0] != 0;
            const bool p1 = maskB[j0 + c0 + 1] != 0;
            const int jg0 = j0 + c0, jg1 = jg0 + 1;
            s4[nt][0] = (p0 && jg0 <= r0g) ? s4[nt][0] * SCL2E : -INFINITY;
            s4[nt][1] = (p1 && jg1 <= r0g) ? s4[nt][1] * SCL2E : -INFINITY;
            s4[nt][2] = (p0 && jg0 <= r1g) ? s4[nt][2] * SCL2E : -INFINITY;
            s4[nt][3] = (p1 && jg1 <= r1g) ? s4[nt][3] * SCL2E : -INFINITY;
        }

        // ---- online softmax (exp2 domain) ----
        float mx0 = -INFINITY, mx1 = -INFINITY;
#pragma unroll
        for (int nt = 0; nt < 8; nt++) {
            mx0 = fmaxf(mx0, fmaxf(s4[nt][0], s4[nt][1]));
            mx1 = fmaxf(mx1, fmaxf(s4[nt][2], s4[nt][3]));
        }
        mx0 = fmaxf(mx0, __shfl_xor_sync(0xffffffffu, mx0, 1));
        mx0 = fmaxf(mx0, __shfl_xor_sync(0xffffffffu, mx0, 2));
        mx1 = fmaxf(mx1, __shfl_xor_sync(0xffffffffu, mx1, 1));
        mx1 = fmaxf(mx1, __shfl_xor_sync(0xffffffffu, mx1, 2));

        float a0 = 1.f, a1 = 1.f;
        if (mx0 > -INFINITY) {
            const float mn = fmaxf(m0, mx0);
            a0 = ex2(m0 - mn);               // 2^(-inf)=0 on first tile
            m0 = mn;
        }
        if (mx1 > -INFINITY) {
            const float mn = fmaxf(m1, mx1);
            a1 = ex2(m1 - mn);
            m1 = mn;
        }
        const float mm0 = (m0 == -INFINITY) ? 0.f : m0;
        const float mm1 = (m1 == -INFINITY) ? 0.f : m1;

        // ---- p = 2^(s-m) in registers; sums ----
        float sum0 = 0.f, sum1 = 0.f;
#pragma unroll
        for (int nt = 0; nt < 8; nt++) {
            s4[nt][0] = ex2(s4[nt][0] - mm0);
            s4[nt][1] = ex2(s4[nt][1] - mm0);
            s4[nt][2] = ex2(s4[nt][2] - mm1);
            s4[nt][3] = ex2(s4[nt][3] - mm1);
            sum0 += s4[nt][0] + s4[nt][1];
            sum1 += s4[nt][2] + s4[nt][3];
        }
        sum0 += __shfl_xor_sync(0xffffffffu, sum0, 1);
        sum0 += __shfl_xor_sync(0xffffffffu, sum0, 2);
        sum1 += __shfl_xor_sync(0xffffffffu, sum1, 1);
        sum1 += __shfl_xor_sync(0xffffffffu, sum1, 2);
        l0 = l0 * a0 + sum0;
        l1 = l1 * a1 + sum1;

#pragma unroll
        for (int nt = 0; nt < 8; nt++) {
            acc[nt][0] *= a0; acc[nt][1] *= a0;
            acc[nt][2] *= a1; acc[nt][3] *= a1;
        }

        // V(kt) arrived; all warps done reading K -> safe to overwrite K
        cp_wait<0>();
        __syncthreads();                     // sync B
        {                                    // prefetch K(kt+1) — covers PV
            const int jn = (kt + 1 < ntiles) ? j0 + 64 : 0;
            att_issue_tile(sb + SKHI, sb + SKLO,
                           khB + (size_t)jn * DK, klB + (size_t)jn * DK, DK, tid);
        }

        // ---- O += Phi*Vhi + Plo*Vhi + Phi*Vlo, P built in registers ----
#pragma unroll
        for (int ks = 0; ks < 4; ks++) {
            uint32_t aph[4], apl[4];
            aph[0] = hi2_trunc(s4[2*ks][0],   s4[2*ks][1]);
            aph[1] = hi2_trunc(s4[2*ks][2],   s4[2*ks][3]);
            aph[2] = hi2_trunc(s4[2*ks+1][0], s4[2*ks+1][1]);
            aph[3] = hi2_trunc(s4[2*ks+1][2], s4[2*ks+1][3]);
            apl[0] = pack2(s4[2*ks][0] - trunc_hi(s4[2*ks][0]),
                           s4[2*ks][1] - trunc_hi(s4[2*ks][1]));
            apl[1] = pack2(s4[2*ks][2] - trunc_hi(s4[2*ks][2]),
                           s4[2*ks][3] - trunc_hi(s4[2*ks][3]));
            apl[2] = pack2(s4[2*ks+1][0] - trunc_hi(s4[2*ks+1][0]),
                           s4[2*ks+1][1] - trunc_hi(s4[2*ks+1][1]));
            apl[3] = pack2(s4[2*ks+1][2] - trunc_hi(s4[2*ks+1][2]),
                           s4[2*ks+1][3] - trunc_hi(s4[2*ks+1][3]));
#pragma unroll
            for (int nt2 = 0; nt2 < 4; nt2++) {
                const int row = nt2 * 16 + ((lane >> 4) << 3) + (lane & 7);
                const uint32_t bo =
                    (uint32_t)(row * 128 + ks * 32 + ((lane >> 3) & 1) * 16);
                uint32_t tv[4];
                ldsm_x4(tv, sb + SVHI + sw128(bo));
                mma_bf16(acc[nt2 * 2 + 0], aph, tv);
                mma_bf16(acc[nt2 * 2 + 1], aph, tv + 2);
                mma_bf16(acc[nt2 * 2 + 0], apl, tv);
                mma_bf16(acc[nt2 * 2 + 1], apl, tv + 2);
                uint32_t tw[4];
                ldsm_x4(tw, sb + SVLO + sw128(bo));
                mma_bf16(acc[nt2 * 2 + 0], aph, tw);
                mma_bf16(acc[nt2 * 2 + 1], aph, tw + 2);
            }
        }

        __syncthreads();                     // sync C: V consumed
        {                                    // prefetch V(kt+1)
            const int jn = (kt + 1 < ntiles) ? j0 + 64 : 0;
            att_issue_tile(sb + SVHI, sb + SVLO,
                           vhB + jn, vlB + jn, TT, tid);
        }
    }

    // ---- epilogue: write proj A-operand (hi | lo) layout directly ----
    const float inv0 = (l0 > 0.f) ? (1.f / l0) : 0.f;
    const float inv1 = (l1 > 0.f) ? (1.f / l1) : 0.f;
#pragma unroll
    for (int nt = 0; nt < 8; nt++) {
        const int col = hh * DK + nt * 8 + (lane & 3) * 2;
        {
            const float vx = acc[nt][0] * inv0, vy = acc[nt][1] * inv0;
            const size_t o = ((size_t)b * TT + r0g) * KST + col;
            *(uint32_t*)(yp + o)        = hi2_trunc(vx, vy);
            *(uint32_t*)(yp + o + 1024) = pack2(vx - trunc_hi(vx),
                                                vy - trunc_hi(vy));
        }
        {
            const float vx = acc[nt][2] * inv1, vy = acc[nt][3] * inv1;
            const size_t o = ((size_t)b * TT + r1g) * KST + col;
            *(uint32_t*)(yp + o)        = hi2_trunc(vx, vy);
            *(uint32_t*)(yp + o + 1024) = pack2(vx - trunc_hi(vx),
                                                vy - trunc_hi(vy));
        }
    }
}

// ---------------------------------------------------------------------------
extern "C" void kernel_launch(void* const* d_in, const int* in_sizes, int n_in,
                              void* d_out, int out_size)
{
    const float* x     = (const float*)d_in[0];
    const float* Wqkv  = (const float*)d_in[1];
    const float* bqkv  = (const float*)d_in[2];
    const float* Wproj = (const float*)d_in[3];
    const float* bproj = (const float*)d_in[4];
    const int*   mask  = (const int*)d_in[5];
    float* out = (float*)d_out;

    float *vp;
    __nv_bfloat16 *xpp, *wqp, *ypp, *wpp;
    __nv_bfloat16 *qhp, *qlp, *khp, *klp, *vhp, *vlp;
    cudaGetSymbolAddress((void**)&vp,   g_v);
    cudaGetSymbolAddress((void**)&xpp,  g_xp);
    cudaGetSymbolAddress((void**)&wqp,  g_wqkvp);
    cudaGetSymbolAddress((void**)&ypp,  g_yp);
    cudaGetSymbolAddress((void**)&wpp,  g_wprojp);
    cudaGetSymbolAddress((void**)&qhp,  g_qh);
    cudaGetSymbolAddress((void**)&qlp,  g_ql);
    cudaGetSymbolAddress((void**)&khp,  g_kh);
    cudaGetSymbolAddress((void**)&klp,  g_kl);
    cudaGetSymbolAddress((void**)&vhp,  g_vht);
    cudaGetSymbolAddress((void**)&vlp,  g_vlt);

    cudaFuncSetAttribute(gemm_bf16_mma<0>,
                         cudaFuncAttributeMaxDynamicSharedMemorySize, GEMM_SMEM);
    cudaFuncSetAttribute(gemm_bf16_mma<1>,
                         cudaFuncAttributeMaxDynamicSharedMemorySize, GEMM_SMEM);
    cudaFuncSetAttribute(attn_mma,
                         cudaFuncAttributeMaxDynamicSharedMemorySize, ATT2_SMEM);

    // input splits (hi|lo, truncation, 4-wide vectorized)
    split_hilo<<<(MROWS * DD / 4) / 256, 256>>>(x, xpp, MROWS * DD / 4);
    split_hilo<<<(3 * DD * DD / 4) / 256, 256>>>(Wqkv, wqp, 3 * DD * DD / 4);
    split_hilo<<<(DD * DD / 4) / 256, 256>>>(Wproj, wpp, DD * DD / 4);

    // qkv GEMM with fused q/k split + compact V
    gemm_bf16_mma<1><<<dim3(3 * DD / 128, MROWS / 128), 256, GEMM_SMEM>>>(
        xpp, wqp, bqkv, nullptr, MROWS, 3 * DD);

    // V transpose + split
    v_split<<<dim3(TT / 128, HH, BB), 256>>>(vp, vhp, vlp);

    // attention -> g_yp (proj A-operand layout, fused)
    attn_mma<<<dim3(TT / 128, HH, BB), 256, ATT2_SMEM>>>(
        qhp, qlp, khp, klp, vhp, vlp, mask, ypp);

    // out = y @ Wproj^T + bproj
    gemm_bf16_mma<0><<<dim3(DD / 128, MROWS / 128), 256, GEMM_SMEM>>>(
        ypp, wpp, bproj, out, MROWS, DD);
}